// round 2
// baseline (speedup 1.0000x reference)
#include <cuda_runtime.h>
#include <math.h>

// Problem constants
#define B_   8
#define N_   4096
#define C_   512
#define NH_  8
#define HD_  64
#define M_   64            // reduced tokens per batch (8x8)
#define MROWS 512          // B_*M_
#define KTOT 32768         // R*R*C
#define SPLITK 16
#define KCHUNK (KTOT/SPLITK)   // 2048
#define EPS 1e-3f

// Scratch (device globals — no runtime allocation, referenced device-side only)
__device__ float g_Q[B_*N_*C_];            // 64 MiB
__device__ float g_part[SPLITK*MROWS*C_];  // 16 MiB conv split-K partials
__device__ float g_F[MROWS*C_];            // conv+LN output
__device__ float g_KV[MROWS*2*C_];         // K|V projections
__device__ float g_AO[B_*N_*C_];           // attention output (pre out-proj)

// Buffer selectors (avoid any host-side symbol-address queries)
#define SEL_EXT 0
#define SEL_Q   1
#define SEL_F   2
#define SEL_KV  3
#define SEL_AO  4

__device__ __forceinline__ const float* pick_src(int sel, const float* ext) {
    switch (sel) {
        case SEL_Q:  return g_Q;
        case SEL_F:  return g_F;
        case SEL_KV: return g_KV;
        case SEL_AO: return g_AO;
        default:     return ext;
    }
}
__device__ __forceinline__ float* pick_dst(int sel, float* ext) {
    switch (sel) {
        case SEL_Q:  return g_Q;
        case SEL_F:  return g_F;
        case SEL_KV: return g_KV;
        case SEL_AO: return g_AO;
        default:     return ext;
    }
}

// ---------------------------------------------------------------------------
// Generic fp32 GEMM: C[M,N] = A[M,K] @ B[K,N] (+bias). 128x128 tile, BK=8,
// 256 threads, 8x8 per-thread microtile, float4 smem paths.
// Requires: M%128==0, N%128==0, K%8==0.
// ---------------------------------------------------------------------------
__global__ __launch_bounds__(256) void gemm128(
    const float* __restrict__ Aext, int aSel,
    const float* __restrict__ B,
    const float* __restrict__ bias,
    float* __restrict__ Cext, int cSel,
    int M, int N, int K, int hasBias)
{
    const float* A = pick_src(aSel, Aext);
    float* C = pick_dst(cSel, Cext);

    __shared__ float As[8][132];
    __shared__ float Bs[8][128];

    int tid = threadIdx.x;
    int tx = tid & 15;
    int ty = tid >> 4;
    int rowBase = blockIdx.y * 128;
    int colBase = blockIdx.x * 128;

    int ar = tid >> 1;            // 0..127
    int ak = (tid & 1) * 4;       // 0 or 4
    int bk = tid >> 5;            // 0..7
    int bc = (tid & 31) * 4;      // 0..124

    const float* Aptr = A + (size_t)(rowBase + ar) * K + ak;
    const float* Bptr = B + (size_t)bk * N + colBase + bc;

    float acc[8][8];
#pragma unroll
    for (int i = 0; i < 8; i++)
#pragma unroll
        for (int j = 0; j < 8; j++) acc[i][j] = 0.f;

    for (int k0 = 0; k0 < K; k0 += 8) {
        float4 av = *(const float4*)(Aptr + k0);
        As[ak + 0][ar] = av.x;
        As[ak + 1][ar] = av.y;
        As[ak + 2][ar] = av.z;
        As[ak + 3][ar] = av.w;
        float4 bv = *(const float4*)(Bptr + (size_t)k0 * N);
        *(float4*)&Bs[bk][bc] = bv;
        __syncthreads();
#pragma unroll
        for (int kk = 0; kk < 8; kk++) {
            float4 a0 = *(const float4*)&As[kk][ty * 8];
            float4 a1 = *(const float4*)&As[kk][ty * 8 + 4];
            float4 b0 = *(const float4*)&Bs[kk][tx * 8];
            float4 b1 = *(const float4*)&Bs[kk][tx * 8 + 4];
            float a[8] = {a0.x, a0.y, a0.z, a0.w, a1.x, a1.y, a1.z, a1.w};
            float b[8] = {b0.x, b0.y, b0.z, b0.w, b1.x, b1.y, b1.z, b1.w};
#pragma unroll
            for (int i = 0; i < 8; i++)
#pragma unroll
                for (int j = 0; j < 8; j++)
                    acc[i][j] += a[i] * b[j];
        }
        __syncthreads();
    }

#pragma unroll
    for (int i = 0; i < 8; i++) {
        int row = rowBase + ty * 8 + i;
        float* Crow = C + (size_t)row * N + colBase + tx * 8;
#pragma unroll
        for (int j = 0; j < 8; j++) {
            float v = acc[i][j];
            if (hasBias) v += bias[colBase + tx * 8 + j];
            Crow[j] = v;
        }
    }
}

// ---------------------------------------------------------------------------
// Conv-as-GEMM with split-K. Output rows = (b, patch), K = (r1, r2, cin).
// SAME padding with k=s=8 on 64x64 => zero padding; pure patch GEMM.
// grid (4, 4, SPLITK). Writes partials to g_part.
// ---------------------------------------------------------------------------
__global__ __launch_bounds__(256) void conv_gemm(
    const float* __restrict__ x, const float* __restrict__ W)
{
    __shared__ float As[8][132];
    __shared__ float Bs[8][128];

    int tid = threadIdx.x;
    int tx = tid & 15;
    int ty = tid >> 4;
    int rowBase = blockIdx.y * 128;
    int colBase = blockIdx.x * 128;
    int kbase = blockIdx.z * KCHUNK;

    int ar = tid >> 1;
    int ak = (tid & 1) * 4;
    int bk = tid >> 5;
    int bc = (tid & 31) * 4;

    int row = rowBase + ar;               // 0..511
    int b   = row >> 6;
    int p   = row & 63;
    int py  = p >> 3;
    int px  = p & 7;
    int pixbase = b * 4096 + py * 512 + px * 8;   // + r1*64 + r2 gives pixel

    float acc[8][8];
#pragma unroll
    for (int i = 0; i < 8; i++)
#pragma unroll
        for (int j = 0; j < 8; j++) acc[i][j] = 0.f;

    for (int k0 = kbase; k0 < kbase + KCHUNK; k0 += 8) {
        int pix = k0 >> 9;                    // constant across 8-wide slab
        int r1 = pix >> 3, r2 = pix & 7;
        int cin = (k0 & 511) + ak;
        float4 av = *(const float4*)(x + (size_t)(pixbase + r1 * 64 + r2) * 512 + cin);
        As[ak + 0][ar] = av.x;
        As[ak + 1][ar] = av.y;
        As[ak + 2][ar] = av.z;
        As[ak + 3][ar] = av.w;
        float4 bv = *(const float4*)(W + (size_t)(k0 + bk) * 512 + colBase + bc);
        *(float4*)&Bs[bk][bc] = bv;
        __syncthreads();
#pragma unroll
        for (int kk = 0; kk < 8; kk++) {
            float4 a0 = *(const float4*)&As[kk][ty * 8];
            float4 a1 = *(const float4*)&As[kk][ty * 8 + 4];
            float4 b0 = *(const float4*)&Bs[kk][tx * 8];
            float4 b1 = *(const float4*)&Bs[kk][tx * 8 + 4];
            float a[8] = {a0.x, a0.y, a0.z, a0.w, a1.x, a1.y, a1.z, a1.w};
            float bb[8] = {b0.x, b0.y, b0.z, b0.w, b1.x, b1.y, b1.z, b1.w};
#pragma unroll
            for (int i = 0; i < 8; i++)
#pragma unroll
                for (int j = 0; j < 8; j++)
                    acc[i][j] += a[i] * bb[j];
        }
        __syncthreads();
    }

    size_t base = (size_t)blockIdx.z * (MROWS * C_);
#pragma unroll
    for (int i = 0; i < 8; i++) {
        size_t roff = base + (size_t)(rowBase + ty * 8 + i) * C_ + colBase + tx * 8;
#pragma unroll
        for (int j = 0; j < 8; j++)
            g_part[roff + j] = acc[i][j];
    }
}

// ---------------------------------------------------------------------------
// Split-K reduce + LayerNorm (eps=1e-3, population var). One block per row.
// ---------------------------------------------------------------------------
__inline__ __device__ float warpsum(float v) {
#pragma unroll
    for (int o = 16; o > 0; o >>= 1) v += __shfl_down_sync(0xffffffffu, v, o);
    return v;
}

__global__ __launch_bounds__(256) void reduce_ln(
    const float* __restrict__ gamma, const float* __restrict__ beta)
{
    int row = blockIdx.x;      // 0..511
    int tid = threadIdx.x;     // 256
    int c0 = tid, c1 = tid + 256;

    float v0 = 0.f, v1 = 0.f;
    for (int pz = 0; pz < SPLITK; pz++) {
        size_t base = (size_t)pz * MROWS * C_ + (size_t)row * C_;
        v0 += g_part[base + c0];
        v1 += g_part[base + c1];
    }
    float sum = v0 + v1;
    float sq  = v0 * v0 + v1 * v1;

    __shared__ float ssum[8], ssq[8];
    __shared__ float s_mean, s_inv;
    float ws = warpsum(sum);
    float wq = warpsum(sq);
    int lane = tid & 31, wid = tid >> 5;
    if (lane == 0) { ssum[wid] = ws; ssq[wid] = wq; }
    __syncthreads();
    if (tid == 0) {
        float S = 0.f, Q = 0.f;
#pragma unroll
        for (int i = 0; i < 8; i++) { S += ssum[i]; Q += ssq[i]; }
        float mean = S * (1.0f / C_);
        float var = Q * (1.0f / C_) - mean * mean;
        s_mean = mean;
        s_inv = rsqrtf(var + EPS);
    }
    __syncthreads();
    float mean = s_mean, inv = s_inv;
    g_F[(size_t)row * C_ + c0] = (v0 - mean) * inv * gamma[c0] + beta[c0];
    g_F[(size_t)row * C_ + c1] = (v1 - mean) * inv * gamma[c1] + beta[c1];
}

// ---------------------------------------------------------------------------
// Attention: per (b, nh), 64 keys/values in smem, one query row per thread.
// Q head layout: channel = hd*8 + nh (strided). Out layout: nh*64 + hd.
// grid (B*NH, N/256), 256 threads.
// ---------------------------------------------------------------------------
__global__ __launch_bounds__(256) void attn_kernel()
{
    int bh = blockIdx.x;
    int b  = bh >> 3;
    int nh = bh & 7;
    __shared__ float Kh[64][64];
    __shared__ float Vh[64][64];

    int tid = threadIdx.x;
    for (int i = tid; i < 64 * 64; i += 256) {
        int m = i >> 6, hd = i & 63;
        size_t base = ((size_t)(b * 64 + m)) * 1024 + nh * 64 + hd;
        Kh[m][hd] = g_KV[base];
        Vh[m][hd] = g_KV[base + 512];
    }
    __syncthreads();

    int n = blockIdx.y * 256 + tid;
    const float* qrow = g_Q + ((size_t)b * N_ + n) * C_ + nh;

    float q[64];
#pragma unroll
    for (int hd = 0; hd < 64; hd++) q[hd] = qrow[hd * 8];

    float s[64];
    float mx = -1e30f;
#pragma unroll
    for (int m = 0; m < 64; m++) {
        float d = 0.f;
#pragma unroll
        for (int hd = 0; hd < 64; hd++) d += q[hd] * Kh[m][hd];
        d *= 0.125f;   // 1/sqrt(64)
        s[m] = d;
        mx = fmaxf(mx, d);
    }
    float ssum = 0.f;
#pragma unroll
    for (int m = 0; m < 64; m++) {
        s[m] = __expf(s[m] - mx);
        ssum += s[m];
    }
    float inv = 1.f / ssum;

    float* orow = g_AO + ((size_t)b * N_ + n) * C_ + nh * 64;
#pragma unroll
    for (int hd = 0; hd < 64; hd++) {
        float a = 0.f;
#pragma unroll
        for (int m = 0; m < 64; m++) a += s[m] * Vh[m][hd];
        orow[hd] = a * inv;
    }
}

// ---------------------------------------------------------------------------
// Host launcher — launches only, no runtime API calls, no state.
// ---------------------------------------------------------------------------
extern "C" void kernel_launch(void* const* d_in, const int* in_sizes, int n_in,
                              void* d_out, int out_size)
{
    const float* x     = (const float*)d_in[0];
    const float* Wq    = (const float*)d_in[1];
    const float* Wkv   = (const float*)d_in[2];
    const float* convw = (const float*)d_in[3];
    const float* gamma = (const float*)d_in[4];
    const float* beta  = (const float*)d_in[5];
    const float* Wp    = (const float*)d_in[6];
    const float* bp    = (const float*)d_in[7];
    float* out = (float*)d_out;

    dim3 blk(256);

    // 1. Q = x @ Wq   [32768,512]
    gemm128<<<dim3(4, 256), blk>>>(x, SEL_EXT, Wq, nullptr,
                                   nullptr, SEL_Q, B_ * N_, C_, C_, 0);
    // 2. Conv as split-K GEMM -> g_part
    conv_gemm<<<dim3(4, 4, SPLITK), blk>>>(x, convw);
    // 3. Reduce partials + LayerNorm -> g_F
    reduce_ln<<<MROWS, 256>>>(gamma, beta);
    // 4. KV = F @ Wkv  [512,1024]
    gemm128<<<dim3(8, 4), blk>>>(nullptr, SEL_F, Wkv, nullptr,
                                 nullptr, SEL_KV, MROWS, 2 * C_, C_, 0);
    // 5. Attention -> g_AO
    attn_kernel<<<dim3(B_ * NH_, N_ / 256), blk>>>();
    // 6. out = AO @ Wp + bp
    gemm128<<<dim3(4, 256), blk>>>(nullptr, SEL_AO, Wp, bp,
                                   out, SEL_EXT, B_ * N_, C_, C_, 1);
}

// round 4
// speedup vs baseline: 1.6607x; 1.6607x over previous
#include <cuda_runtime.h>
#include <cuda_bf16.h>
#include <math.h>
#include <cstdint>

// Problem constants
#define B_   8
#define N_   4096
#define C_   512
#define NH_  8
#define HD_  64
#define MROWS 512            // B_*64 reduced tokens
#define KCONV 32768          // 8*8*512
#define SPLITK 32
#define KCHUNK (KCONV/SPLITK)  // 1024
#define EPS 1e-3f

// ---------------------------------------------------------------------------
// Device global scratch
// ---------------------------------------------------------------------------
__device__ float g_Q[B_*N_*C_];                 // 64MB fp32 Q
__device__ float g_part[SPLITK*MROWS*C_];       // 32MB conv split-K partials
__device__ float g_KV[MROWS*2*C_];              // 2MB
__device__ __nv_bfloat16 g_xh[B_*N_*C_], g_xl[B_*N_*C_];        // x hi/lo
__device__ __nv_bfloat16 g_Fh[MROWS*C_], g_Fl[MROWS*C_];        // LN out hi/lo
__device__ __nv_bfloat16 g_AOh[B_*N_*C_], g_AOl[B_*N_*C_];      // attn out hi/lo
__device__ __nv_bfloat16 g_Wqt_h[C_*C_],  g_Wqt_l[C_*C_];       // Wq^T [N][K]
__device__ __nv_bfloat16 g_Wkvt_h[2*C_*C_], g_Wkvt_l[2*C_*C_];  // Wkv^T
__device__ __nv_bfloat16 g_Wct_h[KCONV*C_], g_Wct_l[KCONV*C_];  // convW^T [512][32768]
__device__ __nv_bfloat16 g_Wpt_h[C_*C_],  g_Wpt_l[C_*C_];       // Wp^T

// selectors
#define ASEL_X  0
#define ASEL_F  1
#define ASEL_AO 2
#define BSEL_WQT  0
#define BSEL_WKVT 1
#define BSEL_WCT  2
#define BSEL_WPT  3
#define DSEL_Q    0
#define DSEL_PART 1
#define DSEL_KV   2
#define DSEL_EXT  3
#define TSEL_WQT  0
#define TSEL_WKVT 1
#define TSEL_WCT  2
#define TSEL_WPT  3

// ---------------------------------------------------------------------------
// MMA helpers (sm_80-baseline PTX: valid on compute_103 virtual arch)
// ---------------------------------------------------------------------------
__device__ __forceinline__ uint32_t smem_u32(const void* p) {
    uint32_t a;
    asm("{ .reg .u64 t; cvta.to.shared.u64 t, %1; cvt.u32.u64 %0, t; }"
        : "=r"(a) : "l"(p));
    return a;
}
__device__ __forceinline__ void ldm_x4(uint32_t* r, uint32_t addr) {
    asm volatile("ldmatrix.sync.aligned.m8n8.x4.shared.b16 {%0,%1,%2,%3}, [%4];"
        : "=r"(r[0]), "=r"(r[1]), "=r"(r[2]), "=r"(r[3]) : "r"(addr));
}
__device__ __forceinline__ void mma16816(float* c, const uint32_t* a,
                                         const uint32_t* b) {
    asm volatile("mma.sync.aligned.m16n8k16.row.col.f32.bf16.bf16.f32 "
        "{%0,%1,%2,%3},{%4,%5,%6,%7},{%8,%9},{%0,%1,%2,%3};"
        : "+f"(c[0]), "+f"(c[1]), "+f"(c[2]), "+f"(c[3])
        : "r"(a[0]), "r"(a[1]), "r"(a[2]), "r"(a[3]), "r"(b[0]), "r"(b[1]));
}

// Smem layout: rows padded to 40 bf16 (80B = 5 x 16B slots; slot = (5r+s)%8
// is a permutation => conflict-free ldmatrix). Per stage:
//   Ah 128x40 (10240B) | Al | Bh | Bl     stage = 40960B, double buffered.
#define ROWB 80
#define OFF_AH 0
#define OFF_AL 10240
#define OFF_BH 20480
#define OFF_BL 30720
#define STG    40960
#define SMEM_TOTAL (2*STG)

// ---------------------------------------------------------------------------
// 3-term split-bf16 tensor-core GEMM. C[M,N] += A @ Bt^T, Bt is [N][K].
// Tile 128x128, BK=32, 256 threads (8 warps, warp tile 64x32).
// ---------------------------------------------------------------------------
__global__ __launch_bounds__(256, 1) void mgemm(
    int aSel, int bSel, int dSel,
    int Kfull, int kcount, int ldC,
    float* __restrict__ extC, const float* __restrict__ bias,
    int hasBias, int aGather)
{
    extern __shared__ char smem[];
    uint32_t sb = smem_u32(smem);
    int tid = threadIdx.x, lane = tid & 31, wid = tid >> 5;
    int rowBase = blockIdx.y * 128, colBase = blockIdx.x * 128;
    int kbase = blockIdx.z * kcount;

    const __nv_bfloat16 *Ah, *Al, *Bh, *Bl;
    switch (aSel) {
        case ASEL_X: Ah = g_xh;  Al = g_xl;  break;
        case ASEL_F: Ah = g_Fh;  Al = g_Fl;  break;
        default:     Ah = g_AOh; Al = g_AOl; break;
    }
    switch (bSel) {
        case BSEL_WQT:  Bh = g_Wqt_h;  Bl = g_Wqt_l;  break;
        case BSEL_WKVT: Bh = g_Wkvt_h; Bl = g_Wkvt_l; break;
        case BSEL_WCT:  Bh = g_Wct_h;  Bl = g_Wct_l;  break;
        default:        Bh = g_Wpt_h;  Bl = g_Wpt_l;  break;
    }
    float* Cd;
    switch (dSel) {
        case DSEL_Q:    Cd = g_Q; break;
        case DSEL_PART: Cd = g_part + (size_t)blockIdx.z * (MROWS * C_); break;
        case DSEL_KV:   Cd = g_KV; break;
        default:        Cd = extC; break;
    }

    int m0 = (wid >> 2) * 64;      // warp row origin in tile
    int n0 = (wid & 3) * 32;       // warp col origin in tile

    float acc[4][4][4];
#pragma unroll
    for (int a = 0; a < 4; a++)
#pragma unroll
        for (int b = 0; b < 4; b++)
#pragma unroll
            for (int c = 0; c < 4; c++) acc[a][b][c] = 0.f;

    int iters = kcount >> 5;

    // ---- global load of one BK=32 tile into regs (2 chunks of 16B per array)
    uint4 rah[2], ral[2], rbh[2], rbl[2];
    auto gload = [&](int i) {
        int k0 = kbase + i * 32;
#pragma unroll
        for (int j = 0; j < 2; j++) {
            int c = tid + j * 256;
            int r = c >> 2, s = c & 3;
            size_t offA;
            if (aGather) {
                int rg = rowBase + r;
                int bb = rg >> 6;
                int p = rg & 63;
                int pix = k0 >> 9;     // constant across the 32-wide slab
                int pixel = bb * 4096 + (p >> 3) * 512 + (p & 7) * 8
                          + (pix >> 3) * 64 + (pix & 7);
                offA = (size_t)pixel * 512 + (k0 & 511) + s * 8;
            } else {
                offA = (size_t)(rowBase + r) * Kfull + k0 + s * 8;
            }
            rah[j] = *(const uint4*)(Ah + offA);
            ral[j] = *(const uint4*)(Al + offA);
            size_t offB = (size_t)(colBase + r) * Kfull + k0 + s * 8;
            rbh[j] = *(const uint4*)(Bh + offB);
            rbl[j] = *(const uint4*)(Bl + offB);
        }
    };
    auto sstore = [&](int buf) {
#pragma unroll
        for (int j = 0; j < 2; j++) {
            int c = tid + j * 256;
            int r = c >> 2, s = c & 3;
            uint32_t o = buf * STG + r * ROWB + s * 16;
            *(uint4*)(smem + o + OFF_AH) = rah[j];
            *(uint4*)(smem + o + OFF_AL) = ral[j];
            *(uint4*)(smem + o + OFF_BH) = rbh[j];
            *(uint4*)(smem + o + OFF_BL) = rbl[j];
        }
    };

    gload(0);
    sstore(0);
    __syncthreads();

    int mat = lane >> 3;
    int arow_off = ((mat & 1) << 3) + (lane & 7);
    int nrow_off = ((mat >> 1) << 3) + (lane & 7);

    for (int i = 0; i < iters; i++) {
        if (i + 1 < iters) gload(i + 1);

        uint32_t base = sb + (uint32_t)(i & 1) * STG;
#pragma unroll
        for (int kk = 0; kk < 2; kk++) {
            int akcol = kk * 16 + ((mat >> 1) << 3);
            int bkcol = kk * 16 + ((mat & 1) << 3);
            uint32_t a_h[4][4], a_l[4][4], b_h[2][4], b_l[2][4];
#pragma unroll
            for (int mt = 0; mt < 4; mt++) {
                uint32_t ad = base + OFF_AH
                            + (uint32_t)(m0 + mt * 16 + arow_off) * ROWB
                            + akcol * 2;
                ldm_x4(a_h[mt], ad);
                ldm_x4(a_l[mt], ad + (OFF_AL - OFF_AH));
            }
#pragma unroll
            for (int np = 0; np < 2; np++) {
                uint32_t bd = base + OFF_BH
                            + (uint32_t)(n0 + np * 16 + nrow_off) * ROWB
                            + bkcol * 2;
                ldm_x4(b_h[np], bd);
                ldm_x4(b_l[np], bd + (OFF_BL - OFF_BH));
            }
#pragma unroll
            for (int mt = 0; mt < 4; mt++)
#pragma unroll
                for (int nt = 0; nt < 4; nt++) {
                    const uint32_t* bhf = &b_h[nt >> 1][(nt & 1) * 2];
                    const uint32_t* blf = &b_l[nt >> 1][(nt & 1) * 2];
                    mma16816(acc[mt][nt], a_h[mt], bhf);
                    mma16816(acc[mt][nt], a_l[mt], bhf);
                    mma16816(acc[mt][nt], a_h[mt], blf);
                }
        }
        if (i + 1 < iters) {
            sstore((i + 1) & 1);
            __syncthreads();
        }
    }

    // epilogue: c-frag (m16n8): c0,c1 row=l/4 col=2(l%4)+{0,1}; c2,c3 row+8
    int m0g = rowBase + m0, n0g = colBase + n0;
#pragma unroll
    for (int mt = 0; mt < 4; mt++) {
        int r0 = m0g + mt * 16 + (lane >> 2);
#pragma unroll
        for (int nt = 0; nt < 4; nt++) {
            int col = n0g + nt * 8 + (lane & 3) * 2;
            float b0 = 0.f, b1 = 0.f;
            if (hasBias) { b0 = bias[col]; b1 = bias[col + 1]; }
            float* p = Cd + (size_t)r0 * ldC + col;
            p[0] = acc[mt][nt][0] + b0;
            p[1] = acc[mt][nt][1] + b1;
            float* q = p + 8 * ldC;
            q[0] = acc[mt][nt][2] + b0;
            q[1] = acc[mt][nt][3] + b1;
        }
    }
}

// ---------------------------------------------------------------------------
// Conversion kernels
// ---------------------------------------------------------------------------
__global__ void split_x_kernel(const float* __restrict__ x) {
    const int total = B_*N_*C_;
    for (int i = blockIdx.x * blockDim.x + threadIdx.x; i < total;
         i += gridDim.x * blockDim.x) {
        float v = x[i];
        __nv_bfloat16 h = __float2bfloat16(v);
        g_xh[i] = h;
        g_xl[i] = __float2bfloat16(v - __bfloat162float(h));
    }
}

// Transpose + hi/lo split: W[K][N] -> Wt[n][k]
__global__ void trans_split_kernel(const float* __restrict__ W, int K, int N, int tSel) {
    __shared__ float t[32][33];
    int n0 = blockIdx.x * 32, k0 = blockIdx.y * 32;
    int tx = threadIdx.x, ty = threadIdx.y;
#pragma unroll
    for (int i = 0; i < 4; i++)
        t[ty + 8 * i][tx] = W[(size_t)(k0 + ty + 8 * i) * N + n0 + tx];
    __syncthreads();
    __nv_bfloat16 *Th, *Tl;
    switch (tSel) {
        case TSEL_WQT:  Th = g_Wqt_h;  Tl = g_Wqt_l;  break;
        case TSEL_WKVT: Th = g_Wkvt_h; Tl = g_Wkvt_l; break;
        case TSEL_WCT:  Th = g_Wct_h;  Tl = g_Wct_l;  break;
        default:        Th = g_Wpt_h;  Tl = g_Wpt_l;  break;
    }
#pragma unroll
    for (int i = 0; i < 4; i++) {
        float v = t[tx][ty + 8 * i];
        __nv_bfloat16 h = __float2bfloat16(v);
        size_t o = (size_t)(n0 + ty + 8 * i) * K + k0 + tx;
        Th[o] = h;
        Tl[o] = __float2bfloat16(v - __bfloat162float(h));
    }
}

// ---------------------------------------------------------------------------
// Split-K reduce + LayerNorm -> bf16 hi/lo F
// ---------------------------------------------------------------------------
__inline__ __device__ float warpsum(float v) {
#pragma unroll
    for (int o = 16; o > 0; o >>= 1) v += __shfl_down_sync(0xffffffffu, v, o);
    return v;
}

__global__ __launch_bounds__(256) void reduce_ln(
    const float* __restrict__ gamma, const float* __restrict__ beta)
{
    int row = blockIdx.x;
    int tid = threadIdx.x;
    int c0 = tid, c1 = tid + 256;

    float v0 = 0.f, v1 = 0.f;
    for (int pz = 0; pz < SPLITK; pz++) {
        size_t base = (size_t)pz * MROWS * C_ + (size_t)row * C_;
        v0 += g_part[base + c0];
        v1 += g_part[base + c1];
    }
    float sum = v0 + v1;
    float sq = v0 * v0 + v1 * v1;

    __shared__ float ssum[8], ssq[8];
    __shared__ float s_mean, s_inv;
    float ws = warpsum(sum);
    float wq = warpsum(sq);
    int lane = tid & 31, wid = tid >> 5;
    if (lane == 0) { ssum[wid] = ws; ssq[wid] = wq; }
    __syncthreads();
    if (tid == 0) {
        float S = 0.f, Q = 0.f;
#pragma unroll
        for (int i = 0; i < 8; i++) { S += ssum[i]; Q += ssq[i]; }
        float mean = S * (1.0f / C_);
        float var = Q * (1.0f / C_) - mean * mean;
        s_mean = mean;
        s_inv = rsqrtf(var + EPS);
    }
    __syncthreads();
    float mean = s_mean, inv = s_inv;
    float y0 = (v0 - mean) * inv * gamma[c0] + beta[c0];
    float y1 = (v1 - mean) * inv * gamma[c1] + beta[c1];
    size_t o0 = (size_t)row * C_ + c0, o1 = (size_t)row * C_ + c1;
    __nv_bfloat16 h0 = __float2bfloat16(y0);
    __nv_bfloat16 h1 = __float2bfloat16(y1);
    g_Fh[o0] = h0; g_Fl[o0] = __float2bfloat16(y0 - __bfloat162float(h0));
    g_Fh[o1] = h1; g_Fl[o1] = __float2bfloat16(y1 - __bfloat162float(h1));
}

// ---------------------------------------------------------------------------
// Attention (fp32), writes AO as bf16 hi/lo
// ---------------------------------------------------------------------------
__global__ __launch_bounds__(256) void attn_kernel()
{
    int bh = blockIdx.x;
    int b = bh >> 3;
    int nh = bh & 7;
    __shared__ float Kh[64][64];
    __shared__ float Vh[64][64];

    int tid = threadIdx.x;
    for (int i = tid; i < 64 * 64; i += 256) {
        int m = i >> 6, hd = i & 63;
        size_t base = ((size_t)(b * 64 + m)) * 1024 + nh * 64 + hd;
        Kh[m][hd] = g_KV[base];
        Vh[m][hd] = g_KV[base + 512];
    }
    __syncthreads();

    int n = blockIdx.y * 256 + tid;
    const float* qrow = g_Q + ((size_t)b * N_ + n) * C_ + nh;

    float q[64];
#pragma unroll
    for (int hd = 0; hd < 64; hd++) q[hd] = qrow[hd * 8];

    float s[64];
    float mx = -1e30f;
#pragma unroll
    for (int m = 0; m < 64; m++) {
        float d = 0.f;
#pragma unroll
        for (int hd = 0; hd < 64; hd++) d += q[hd] * Kh[m][hd];
        d *= 0.125f;
        s[m] = d;
        mx = fmaxf(mx, d);
    }
    float ssum = 0.f;
#pragma unroll
    for (int m = 0; m < 64; m++) {
        s[m] = __expf(s[m] - mx);
        ssum += s[m];
    }
    float inv = 1.f / ssum;

    size_t obase = ((size_t)b * N_ + n) * C_ + nh * 64;
#pragma unroll
    for (int hd = 0; hd < 64; hd++) {
        float a = 0.f;
#pragma unroll
        for (int m = 0; m < 64; m++) a += s[m] * Vh[m][hd];
        float v = a * inv;
        __nv_bfloat16 h = __float2bfloat16(v);
        g_AOh[obase + hd] = h;
        g_AOl[obase + hd] = __float2bfloat16(v - __bfloat162float(h));
    }
}

// ---------------------------------------------------------------------------
// Host launcher
// ---------------------------------------------------------------------------
extern "C" void kernel_launch(void* const* d_in, const int* in_sizes, int n_in,
                              void* d_out, int out_size)
{
    const float* x     = (const float*)d_in[0];
    const float* Wq    = (const float*)d_in[1];
    const float* Wkv   = (const float*)d_in[2];
    const float* convw = (const float*)d_in[3];
    const float* gamma = (const float*)d_in[4];
    const float* beta  = (const float*)d_in[5];
    const float* Wp    = (const float*)d_in[6];
    const float* bp    = (const float*)d_in[7];
    float* out = (float*)d_out;

    cudaFuncSetAttribute(mgemm, cudaFuncAttributeMaxDynamicSharedMemorySize,
                         SMEM_TOTAL);

    // conversions
    split_x_kernel<<<8192, 256>>>(x);
    dim3 tb(32, 8);
    trans_split_kernel<<<dim3(16, 16), tb>>>(Wq, 512, 512, TSEL_WQT);
    trans_split_kernel<<<dim3(32, 16), tb>>>(Wkv, 512, 1024, TSEL_WKVT);
    trans_split_kernel<<<dim3(16, 1024), tb>>>(convw, KCONV, 512, TSEL_WCT);
    trans_split_kernel<<<dim3(16, 16), tb>>>(Wp, 512, 512, TSEL_WPT);

    // Q = x @ Wq   grid (N/128, M/128)
    mgemm<<<dim3(4, 256, 1), 256, SMEM_TOTAL>>>(
        ASEL_X, BSEL_WQT, DSEL_Q, 512, 512, 512, nullptr, nullptr, 0, 0);
    // conv as gathered GEMM, split-K=32 -> g_part
    mgemm<<<dim3(4, 4, SPLITK), 256, SMEM_TOTAL>>>(
        ASEL_X, BSEL_WCT, DSEL_PART, KCONV, KCHUNK, 512, nullptr, nullptr, 0, 1);
    // reduce + LN -> Fh/Fl
    reduce_ln<<<MROWS, 256>>>(gamma, beta);
    // KV = F @ Wkv
    mgemm<<<dim3(8, 4, 1), 256, SMEM_TOTAL>>>(
        ASEL_F, BSEL_WKVT, DSEL_KV, 512, 512, 1024, nullptr, nullptr, 0, 0);
    // attention -> AOh/AOl
    attn_kernel<<<dim3(B_ * NH_, N_ / 256), 256>>>();
    // out = AO @ Wp + bp
    mgemm<<<dim3(4, 256, 1), 256, SMEM_TOTAL>>>(
        ASEL_AO, BSEL_WPT, DSEL_EXT, 512, 512, 512, out, bp, 1, 0);
}

// round 5
// speedup vs baseline: 2.7738x; 1.6702x over previous
#include <cuda_runtime.h>
#include <cuda_fp16.h>
#include <math.h>
#include <cstdint>

// Problem constants
#define B_   8
#define N_   4096
#define C_   512
#define NH_  8
#define HD_  64
#define MROWS 512            // B_*64 reduced tokens
#define KCONV 32768          // 8*8*512
#define SPLITK 32
#define KCHUNK (KCONV/SPLITK)  // 1024
#define EPS 1e-3f

// ---------------------------------------------------------------------------
// Device global scratch
// ---------------------------------------------------------------------------
__device__ float g_Q[B_*N_*C_];                 // fp32 Q (GEMM layout)
__device__ __half g_Qp[B_*N_*C_];               // head-major fp16 Q
__device__ float g_part[SPLITK*MROWS*C_];       // conv split-K partials
__device__ float g_KV[MROWS*2*C_];              // K|V fp32
__device__ __half g_xf[B_*N_*C_];               // x fp16
__device__ __half g_Ff[MROWS*C_];               // LN out fp16
__device__ __half g_AOf[B_*N_*C_];              // attention out fp16
__device__ __half g_Wqt[C_*C_];                 // Wq^T  [N][K]
__device__ __half g_Wkvt[2*C_*C_];              // Wkv^T
__device__ __half g_Wct[KCONV*C_];              // convW^T [512][32768]
__device__ __half g_Wpt[C_*C_];                 // Wp^T

// selectors
#define ASEL_X  0
#define ASEL_F  1
#define ASEL_AO 2
#define BSEL_WQT  0
#define BSEL_WKVT 1
#define BSEL_WCT  2
#define BSEL_WPT  3
#define DSEL_Q    0
#define DSEL_PART 1
#define DSEL_KV   2
#define DSEL_EXT  3
#define TSEL_WQT  0
#define TSEL_WKVT 1
#define TSEL_WCT  2
#define TSEL_WPT  3

// ---------------------------------------------------------------------------
// PTX helpers (all sm_80-baseline; valid on compute_103 virtual arch)
// ---------------------------------------------------------------------------
__device__ __forceinline__ uint32_t smem_u32(const void* p) {
    uint32_t a;
    asm("{ .reg .u64 t; cvta.to.shared.u64 t, %1; cvt.u32.u64 %0, t; }"
        : "=r"(a) : "l"(p));
    return a;
}
__device__ __forceinline__ void ldm_x4(uint32_t* r, uint32_t addr) {
    asm volatile("ldmatrix.sync.aligned.m8n8.x4.shared.b16 {%0,%1,%2,%3}, [%4];"
        : "=r"(r[0]), "=r"(r[1]), "=r"(r[2]), "=r"(r[3]) : "r"(addr));
}
__device__ __forceinline__ void mma16816(float* c, const uint32_t* a,
                                         const uint32_t* b) {
    asm volatile("mma.sync.aligned.m16n8k16.row.col.f32.f16.f16.f32 "
        "{%0,%1,%2,%3},{%4,%5,%6,%7},{%8,%9},{%0,%1,%2,%3};"
        : "+f"(c[0]), "+f"(c[1]), "+f"(c[2]), "+f"(c[3])
        : "r"(a[0]), "r"(a[1]), "r"(a[2]), "r"(a[3]), "r"(b[0]), "r"(b[1]));
}
__device__ __forceinline__ void cpa16(uint32_t d, const void* s) {
    asm volatile("cp.async.cg.shared.global [%0], [%1], 16;"
                 :: "r"(d), "l"(s));
}
#define CPA_COMMIT() asm volatile("cp.async.commit_group;" ::: "memory")

// Smem per stage: A 128x40 halves (10240B) | B 128x40 halves (10240B)
// 80B rows -> 5x16B slots; slot=(5r+s)%8 is a permutation => conflict-free ldm.
#define ROWB 80
#define OFF_B 10240
#define STG   20480

// ---------------------------------------------------------------------------
// Single-term fp16 tensor-core GEMM. C[M,N] = A @ Bt^T, Bt is [N][K].
// Tile 128x128, BK=32, 256 threads (8 warps, warp tile 64x32), cp.async x2.
// ---------------------------------------------------------------------------
__global__ __launch_bounds__(256, 2) void mgemm(
    int aSel, int bSel, int dSel,
    int Kfull, int kcount, int ldC,
    float* __restrict__ extC, const float* __restrict__ bias,
    int hasBias, int aGather)
{
    __shared__ __align__(16) char smem[2 * STG];
    uint32_t sb = smem_u32(smem);
    int tid = threadIdx.x, lane = tid & 31, wid = tid >> 5;
    int rowBase = blockIdx.y * 128, colBase = blockIdx.x * 128;
    int kbase = blockIdx.z * kcount;

    const __half *A, *B;
    switch (aSel) {
        case ASEL_X: A = g_xf;  break;
        case ASEL_F: A = g_Ff;  break;
        default:     A = g_AOf; break;
    }
    switch (bSel) {
        case BSEL_WQT:  B = g_Wqt;  break;
        case BSEL_WKVT: B = g_Wkvt; break;
        case BSEL_WCT:  B = g_Wct;  break;
        default:        B = g_Wpt;  break;
    }
    float* Cd;
    switch (dSel) {
        case DSEL_Q:    Cd = g_Q; break;
        case DSEL_PART: Cd = g_part + (size_t)blockIdx.z * (MROWS * C_); break;
        case DSEL_KV:   Cd = g_KV; break;
        default:        Cd = extC; break;
    }

    int m0 = (wid >> 2) * 64;
    int n0 = (wid & 3) * 32;

    float acc[4][4][4];
#pragma unroll
    for (int a = 0; a < 4; a++)
#pragma unroll
        for (int b = 0; b < 4; b++)
#pragma unroll
            for (int c = 0; c < 4; c++) acc[a][b][c] = 0.f;

    int iters = kcount >> 5;

    auto issue = [&](int i) {
        int k0 = kbase + i * 32;
        uint32_t so = sb + (uint32_t)(i & 1) * STG;
        // A: 512 chunks of 16B
#pragma unroll
        for (int j = 0; j < 2; j++) {
            int c = tid + j * 256;
            int r = c >> 2, s = c & 3;
            size_t off;
            if (aGather) {
                int rg = rowBase + r;
                int bb = rg >> 6;
                int p = rg & 63;
                int pix = k0 >> 9;     // constant across the 32-wide slab
                int pixel = bb * 4096 + (p >> 3) * 512 + (p & 7) * 8
                          + (pix >> 3) * 64 + (pix & 7);
                off = (size_t)pixel * 512 + (k0 & 511) + s * 8;
            } else {
                off = (size_t)(rowBase + r) * Kfull + k0 + s * 8;
            }
            cpa16(so + r * ROWB + s * 16, A + off);
        }
        // B: 512 chunks of 16B
#pragma unroll
        for (int j = 0; j < 2; j++) {
            int c = tid + j * 256;
            int r = c >> 2, s = c & 3;
            cpa16(so + OFF_B + r * ROWB + s * 16,
                  B + (size_t)(colBase + r) * Kfull + k0 + s * 8);
        }
        CPA_COMMIT();
    };

    int mat = lane >> 3;
    int arow_off = ((mat & 1) << 3) + (lane & 7);
    int nrow_off = ((mat >> 1) << 3) + (lane & 7);

    issue(0);
    for (int i = 0; i < iters; i++) {
        if (i + 1 < iters) {
            issue(i + 1);
            asm volatile("cp.async.wait_group 1;" ::: "memory");
        } else {
            asm volatile("cp.async.wait_group 0;" ::: "memory");
        }
        __syncthreads();

        uint32_t base = sb + (uint32_t)(i & 1) * STG;
#pragma unroll
        for (int kk = 0; kk < 2; kk++) {
            int akcol = kk * 16 + ((mat >> 1) << 3);
            int bkcol = kk * 16 + ((mat & 1) << 3);
            uint32_t a_f[4][4], b_f[2][4];
#pragma unroll
            for (int mt = 0; mt < 4; mt++) {
                uint32_t ad = base
                            + (uint32_t)(m0 + mt * 16 + arow_off) * ROWB
                            + akcol * 2;
                ldm_x4(a_f[mt], ad);
            }
#pragma unroll
            for (int np = 0; np < 2; np++) {
                uint32_t bd = base + OFF_B
                            + (uint32_t)(n0 + np * 16 + nrow_off) * ROWB
                            + bkcol * 2;
                ldm_x4(b_f[np], bd);
            }
#pragma unroll
            for (int mt = 0; mt < 4; mt++)
#pragma unroll
                for (int nt = 0; nt < 4; nt++)
                    mma16816(acc[mt][nt], a_f[mt],
                             &b_f[nt >> 1][(nt & 1) * 2]);
        }
        __syncthreads();
    }

    // epilogue
    int m0g = rowBase + m0, n0g = colBase + n0;
#pragma unroll
    for (int mt = 0; mt < 4; mt++) {
        int r0 = m0g + mt * 16 + (lane >> 2);
#pragma unroll
        for (int nt = 0; nt < 4; nt++) {
            int col = n0g + nt * 8 + (lane & 3) * 2;
            float b0 = 0.f, b1 = 0.f;
            if (hasBias) { b0 = bias[col]; b1 = bias[col + 1]; }
            float* p = Cd + (size_t)r0 * ldC + col;
            p[0] = acc[mt][nt][0] + b0;
            p[1] = acc[mt][nt][1] + b1;
            float* q = p + 8 * ldC;
            q[0] = acc[mt][nt][2] + b0;
            q[1] = acc[mt][nt][3] + b1;
        }
    }
}

// ---------------------------------------------------------------------------
// Conversion kernels
// ---------------------------------------------------------------------------
__global__ void split_x_kernel(const float* __restrict__ x) {
    const int total = B_*N_*C_;
    for (int i = blockIdx.x * blockDim.x + threadIdx.x; i < total;
         i += gridDim.x * blockDim.x)
        g_xf[i] = __float2half(x[i]);
}

// Transpose: W[K][N] -> Wt[n][k] fp16
__global__ void trans_split_kernel(const float* __restrict__ W, int K, int N, int tSel) {
    __shared__ float t[32][33];
    int n0 = blockIdx.x * 32, k0 = blockIdx.y * 32;
    int tx = threadIdx.x, ty = threadIdx.y;
#pragma unroll
    for (int i = 0; i < 4; i++)
        t[ty + 8 * i][tx] = W[(size_t)(k0 + ty + 8 * i) * N + n0 + tx];
    __syncthreads();
    __half* Th;
    switch (tSel) {
        case TSEL_WQT:  Th = g_Wqt;  break;
        case TSEL_WKVT: Th = g_Wkvt; break;
        case TSEL_WCT:  Th = g_Wct;  break;
        default:        Th = g_Wpt;  break;
    }
#pragma unroll
    for (int i = 0; i < 4; i++)
        Th[(size_t)(n0 + ty + 8 * i) * K + k0 + tx] =
            __float2half(t[tx][ty + 8 * i]);
}

// ---------------------------------------------------------------------------
// Q permute: g_Q [b*4096+n][c] fp32 -> g_Qp head-major fp16
//            [(b*8+nh)*4096+n][hd],  c = hd*8+nh.
// ---------------------------------------------------------------------------
__global__ __launch_bounds__(256) void qperm_kernel() {
    __shared__ __half s[256][72];          // row = nh*32+i, col = hd
    int blk = blockIdx.x;                  // 1024
    int b = blk >> 7, tile = blk & 127;
    int n0 = tile * 32;
    int tid = threadIdx.x;

    for (int idx = tid; idx < 32 * 512; idx += 256) {
        int i = idx >> 9, c = idx & 511;
        float v = g_Q[((size_t)(b * 4096 + n0 + i)) * 512 + c];
        s[(c & 7) * 32 + i][c >> 3] = __float2half(v);
    }
    __syncthreads();

    int w = tid >> 5, lane = tid & 31;
    for (int it = 0; it < 32; it++) {
        int orow = w * 32 + it;
        int nh = orow >> 5, i = orow & 31;
        size_t grow = (size_t)(b * 8 + nh) * 4096 + n0 + i;
        uint32_t* dst = (uint32_t*)(g_Qp + grow * 64);
        dst[lane] = *(uint32_t*)&s[orow][2 * lane];
    }
}

// ---------------------------------------------------------------------------
// Split-K reduce + LayerNorm -> fp16 F
// ---------------------------------------------------------------------------
__inline__ __device__ float warpsum(float v) {
#pragma unroll
    for (int o = 16; o > 0; o >>= 1) v += __shfl_down_sync(0xffffffffu, v, o);
    return v;
}

__global__ __launch_bounds__(256) void reduce_ln(
    const float* __restrict__ gamma, const float* __restrict__ beta)
{
    int row = blockIdx.x;
    int tid = threadIdx.x;
    int c0 = tid, c1 = tid + 256;

    float v0 = 0.f, v1 = 0.f;
    for (int pz = 0; pz < SPLITK; pz++) {
        size_t base = (size_t)pz * MROWS * C_ + (size_t)row * C_;
        v0 += g_part[base + c0];
        v1 += g_part[base + c1];
    }
    float sum = v0 + v1;
    float sq = v0 * v0 + v1 * v1;

    __shared__ float ssum[8], ssq[8];
    __shared__ float s_mean, s_inv;
    float ws = warpsum(sum);
    float wq = warpsum(sq);
    int lane = tid & 31, wid = tid >> 5;
    if (lane == 0) { ssum[wid] = ws; ssq[wid] = wq; }
    __syncthreads();
    if (tid == 0) {
        float S = 0.f, Q = 0.f;
#pragma unroll
        for (int i = 0; i < 8; i++) { S += ssum[i]; Q += ssq[i]; }
        float mean = S * (1.0f / C_);
        float var = Q * (1.0f / C_) - mean * mean;
        s_mean = mean;
        s_inv = rsqrtf(var + EPS);
    }
    __syncthreads();
    float mean = s_mean, inv = s_inv;
    float y0 = (v0 - mean) * inv * gamma[c0] + beta[c0];
    float y1 = (v1 - mean) * inv * gamma[c1] + beta[c1];
    g_Ff[(size_t)row * C_ + c0] = __float2half(y0);
    g_Ff[(size_t)row * C_ + c1] = __float2half(y1);
}

// ---------------------------------------------------------------------------
// Attention: per (b, nh), K/V in smem (fp32), Q from head-major fp16,
// one query row per thread. Writes AO fp16.
// ---------------------------------------------------------------------------
__global__ __launch_bounds__(256) void attn_kernel()
{
    int bh = blockIdx.x;
    int b = bh >> 3;
    int nh = bh & 7;
    __shared__ float Kh[64][64];
    __shared__ float Vh[64][64];

    int tid = threadIdx.x;
    for (int i = tid; i < 64 * 64; i += 256) {
        int m = i >> 6, hd = i & 63;
        size_t base = ((size_t)(b * 64 + m)) * 1024 + nh * 64 + hd;
        Kh[m][hd] = g_KV[base];
        Vh[m][hd] = g_KV[base + 512];
    }
    __syncthreads();

    int n = blockIdx.y * 256 + tid;
    const __half* qrow = g_Qp + ((size_t)(b * 8 + nh) * 4096 + n) * 64;

    float q[64];
#pragma unroll
    for (int j = 0; j < 8; j++) {
        uint4 u = *(const uint4*)(qrow + j * 8);
        __half2* hp = (__half2*)&u;
#pragma unroll
        for (int t = 0; t < 4; t++) {
            float2 f = __half22float2(hp[t]);
            q[j * 8 + 2 * t] = f.x;
            q[j * 8 + 2 * t + 1] = f.y;
        }
    }

    float s[64];
    float mx = -1e30f;
#pragma unroll
    for (int m = 0; m < 64; m++) {
        float d = 0.f;
#pragma unroll
        for (int hd = 0; hd < 64; hd++) d += q[hd] * Kh[m][hd];
        d *= 0.125f;
        s[m] = d;
        mx = fmaxf(mx, d);
    }
    float ssum = 0.f;
#pragma unroll
    for (int m = 0; m < 64; m++) {
        s[m] = __expf(s[m] - mx);
        ssum += s[m];
    }
    float inv = 1.f / ssum;

    size_t obase = ((size_t)b * N_ + n) * C_ + nh * 64;
#pragma unroll
    for (int hd = 0; hd < 64; hd++) {
        float a = 0.f;
#pragma unroll
        for (int m = 0; m < 64; m++) a += s[m] * Vh[m][hd];
        g_AOf[obase + hd] = __float2half(a * inv);
    }
}

// ---------------------------------------------------------------------------
// Host launcher
// ---------------------------------------------------------------------------
extern "C" void kernel_launch(void* const* d_in, const int* in_sizes, int n_in,
                              void* d_out, int out_size)
{
    const float* x     = (const float*)d_in[0];
    const float* Wq    = (const float*)d_in[1];
    const float* Wkv   = (const float*)d_in[2];
    const float* convw = (const float*)d_in[3];
    const float* gamma = (const float*)d_in[4];
    const float* beta  = (const float*)d_in[5];
    const float* Wp    = (const float*)d_in[6];
    const float* bp    = (const float*)d_in[7];
    float* out = (float*)d_out;

    // conversions
    split_x_kernel<<<8192, 256>>>(x);
    dim3 tb(32, 8);
    trans_split_kernel<<<dim3(16, 16), tb>>>(Wq, 512, 512, TSEL_WQT);
    trans_split_kernel<<<dim3(32, 16), tb>>>(Wkv, 512, 1024, TSEL_WKVT);
    trans_split_kernel<<<dim3(16, 1024), tb>>>(convw, KCONV, 512, TSEL_WCT);
    trans_split_kernel<<<dim3(16, 16), tb>>>(Wp, 512, 512, TSEL_WPT);

    // Q = x @ Wq
    mgemm<<<dim3(4, 256, 1), 256>>>(
        ASEL_X, BSEL_WQT, DSEL_Q, 512, 512, 512, nullptr, nullptr, 0, 0);
    // Q -> head-major fp16
    qperm_kernel<<<1024, 256>>>();
    // conv as gathered GEMM, split-K=32 -> g_part
    mgemm<<<dim3(4, 4, SPLITK), 256>>>(
        ASEL_X, BSEL_WCT, DSEL_PART, KCONV, KCHUNK, 512, nullptr, nullptr, 0, 1);
    // reduce + LN -> Ff
    reduce_ln<<<MROWS, 256>>>(gamma, beta);
    // KV = F @ Wkv
    mgemm<<<dim3(8, 4, 1), 256>>>(
        ASEL_F, BSEL_WKVT, DSEL_KV, 512, 512, 1024, nullptr, nullptr, 0, 0);
    // attention -> AOf
    attn_kernel<<<dim3(B_ * NH_, N_ / 256), 256>>>();
    // out = AO @ Wp + bp
    mgemm<<<dim3(4, 256, 1), 256>>>(
        ASEL_AO, BSEL_WPT, DSEL_EXT, 512, 512, 512, out, bp, 1, 0);
}

// round 6
// speedup vs baseline: 5.3131x; 1.9155x over previous
#include <cuda_runtime.h>
#include <cuda_fp16.h>
#include <math.h>
#include <cstdint>

// Problem constants
#define B_   8
#define N_   4096
#define C_   512
#define NH_  8
#define HD_  64
#define MROWS 512
#define KCONV 32768
#define SPLITK 16
#define KCHUNK (KCONV/SPLITK)  // 2048
#define EPS 1e-3f

// ---------------------------------------------------------------------------
// Device global scratch
// ---------------------------------------------------------------------------
__device__ __half g_Qh[B_*N_*C_];               // head-major fp16 Q: col = nh*64+hd
__device__ float g_part[SPLITK*MROWS*C_];       // conv split-K partials (16MB)
__device__ float g_KV[MROWS*2*C_];              // K|V fp32
__device__ __half g_xf[B_*N_*C_];               // x fp16
__device__ __half g_Ff[MROWS*C_];               // LN out fp16
__device__ __half g_AOf[B_*N_*C_];              // attention out fp16
__device__ __half g_Wqt[C_*C_];                 // Wq^T, rows permuted head-major
__device__ __half g_Wkvt[2*C_*C_];              // Wkv^T
__device__ __half g_Wct[KCONV*C_];              // convW^T [512][32768]
__device__ __half g_Wpt[C_*C_];                 // Wp^T

// selectors
#define ASEL_X  0
#define ASEL_F  1
#define ASEL_AO 2
#define BSEL_WQT  0
#define BSEL_WKVT 1
#define BSEL_WCT  2
#define BSEL_WPT  3
#define DSEL_QH   0
#define DSEL_PART 1
#define DSEL_KV   2
#define DSEL_EXT  3
#define TSEL_WQT  0
#define TSEL_WKVT 1
#define TSEL_WCT  2
#define TSEL_WPT  3

// ---------------------------------------------------------------------------
// PTX helpers (sm_80-baseline; valid on compute_103 virtual arch)
// ---------------------------------------------------------------------------
__device__ __forceinline__ uint32_t smem_u32(const void* p) {
    uint32_t a;
    asm("{ .reg .u64 t; cvta.to.shared.u64 t, %1; cvt.u32.u64 %0, t; }"
        : "=r"(a) : "l"(p));
    return a;
}
__device__ __forceinline__ void ldm_x4(uint32_t* r, uint32_t addr) {
    asm volatile("ldmatrix.sync.aligned.m8n8.x4.shared.b16 {%0,%1,%2,%3}, [%4];"
        : "=r"(r[0]), "=r"(r[1]), "=r"(r[2]), "=r"(r[3]) : "r"(addr));
}
__device__ __forceinline__ void ldm_x4t(uint32_t* r, uint32_t addr) {
    asm volatile("ldmatrix.sync.aligned.m8n8.x4.trans.shared.b16 {%0,%1,%2,%3}, [%4];"
        : "=r"(r[0]), "=r"(r[1]), "=r"(r[2]), "=r"(r[3]) : "r"(addr));
}
__device__ __forceinline__ void mma16816(float* c, const uint32_t* a,
                                         const uint32_t* b) {
    asm volatile("mma.sync.aligned.m16n8k16.row.col.f32.f16.f16.f32 "
        "{%0,%1,%2,%3},{%4,%5,%6,%7},{%8,%9},{%0,%1,%2,%3};"
        : "+f"(c[0]), "+f"(c[1]), "+f"(c[2]), "+f"(c[3])
        : "r"(a[0]), "r"(a[1]), "r"(a[2]), "r"(a[3]), "r"(b[0]), "r"(b[1]));
}
__device__ __forceinline__ void cpa16(uint32_t d, const void* s) {
    asm volatile("cp.async.cg.shared.global [%0], [%1], 16;" :: "r"(d), "l"(s));
}
#define CPA_COMMIT() asm volatile("cp.async.commit_group;" ::: "memory")
#define CPA_WAIT2()  asm volatile("cp.async.wait_group 2;" ::: "memory")

__device__ __forceinline__ uint32_t pack_h2(float a, float b) {
    __half2 h = __halves2half2(__float2half(a), __float2half(b));
    return *(uint32_t*)&h;
}

// mgemm smem: per stage A 128x40 halves | B 128x40 halves, 80B rows
// (5x16B slots; slot=(5r+s)%8 is a permutation => conflict-free ldmatrix)
#define ROWB 80
#define OFF_B 10240
#define STG   20480
#define NSTAGE 4
#define MG_SMEM (NSTAGE*STG)   // 81920 (dynamic)

// ---------------------------------------------------------------------------
// fp16 tensor-core GEMM. C[M,N] = A @ Bt^T (Bt stored [N][K]).
// Tile 128x128, BK=32, 256 threads, 4-stage cp.async, 1 sync/iter.
// ---------------------------------------------------------------------------
__global__ __launch_bounds__(256, 2) void mgemm(
    int aSel, int bSel, int dSel,
    int Kfull, int kcount, int ldC,
    float* __restrict__ extC, const float* __restrict__ bias,
    int hasBias, int aGather)
{
    extern __shared__ __align__(16) char smem[];
    uint32_t sb = smem_u32(smem);
    int tid = threadIdx.x, lane = tid & 31, wid = tid >> 5;
    int rowBase = blockIdx.y * 128, colBase = blockIdx.x * 128;
    int kbase = blockIdx.z * kcount;

    const __half *A, *B;
    switch (aSel) {
        case ASEL_X: A = g_xf;  break;
        case ASEL_F: A = g_Ff;  break;
        default:     A = g_AOf; break;
    }
    switch (bSel) {
        case BSEL_WQT:  B = g_Wqt;  break;
        case BSEL_WKVT: B = g_Wkvt; break;
        case BSEL_WCT:  B = g_Wct;  break;
        default:        B = g_Wpt;  break;
    }
    float* Cd;
    switch (dSel) {
        case DSEL_PART: Cd = g_part + (size_t)blockIdx.z * (MROWS * C_); break;
        case DSEL_KV:   Cd = g_KV; break;
        default:        Cd = extC; break;
    }

    int m0 = (wid >> 2) * 64;
    int n0 = (wid & 3) * 32;

    float acc[4][4][4];
#pragma unroll
    for (int a = 0; a < 4; a++)
#pragma unroll
        for (int b = 0; b < 4; b++)
#pragma unroll
            for (int c = 0; c < 4; c++) acc[a][b][c] = 0.f;

    int iters = kcount >> 5;

    auto issue = [&](int i) {
        int k0 = kbase + i * 32;
        uint32_t so = sb + (uint32_t)(i & (NSTAGE - 1)) * STG;
#pragma unroll
        for (int j = 0; j < 2; j++) {
            int c = tid + j * 256;
            int r = c >> 2, s = c & 3;
            size_t off;
            if (aGather) {
                int rg = rowBase + r;
                int bb = rg >> 6;
                int p = rg & 63;
                int pix = k0 >> 9;     // constant across the 32-wide slab
                int pixel = bb * 4096 + (p >> 3) * 512 + (p & 7) * 8
                          + (pix >> 3) * 64 + (pix & 7);
                off = (size_t)pixel * 512 + (k0 & 511) + s * 8;
            } else {
                off = (size_t)(rowBase + r) * Kfull + k0 + s * 8;
            }
            cpa16(so + r * ROWB + s * 16, A + off);
        }
#pragma unroll
        for (int j = 0; j < 2; j++) {
            int c = tid + j * 256;
            int r = c >> 2, s = c & 3;
            cpa16(so + OFF_B + r * ROWB + s * 16,
                  B + (size_t)(colBase + r) * Kfull + k0 + s * 8);
        }
        CPA_COMMIT();
    };

    int mat = lane >> 3;
    int arow_off = ((mat & 1) << 3) + (lane & 7);
    int nrow_off = ((mat >> 1) << 3) + (lane & 7);

    issue(0); issue(1); issue(2);   // iters >= 16 always

    for (int i = 0; i < iters; i++) {
        CPA_WAIT2();                // group i retired (empty-commit keeps count)
        __syncthreads();
        if (i + 3 < iters) issue(i + 3);
        else CPA_COMMIT();          // empty group keeps wait_group arithmetic exact

        uint32_t base = sb + (uint32_t)(i & (NSTAGE - 1)) * STG;
#pragma unroll
        for (int kk = 0; kk < 2; kk++) {
            int akcol = kk * 16 + ((mat >> 1) << 3);
            int bkcol = kk * 16 + ((mat & 1) << 3);
            uint32_t a_f[4][4], b_f[2][4];
#pragma unroll
            for (int mt = 0; mt < 4; mt++)
                ldm_x4(a_f[mt], base + (uint32_t)(m0 + mt * 16 + arow_off) * ROWB
                                 + akcol * 2);
#pragma unroll
            for (int np = 0; np < 2; np++)
                ldm_x4(b_f[np], base + OFF_B
                                 + (uint32_t)(n0 + np * 16 + nrow_off) * ROWB
                                 + bkcol * 2);
#pragma unroll
            for (int mt = 0; mt < 4; mt++)
#pragma unroll
                for (int nt = 0; nt < 4; nt++)
                    mma16816(acc[mt][nt], a_f[mt], &b_f[nt >> 1][(nt & 1) * 2]);
        }
    }

    // epilogue
    int m0g = rowBase + m0, n0g = colBase + n0;
#pragma unroll
    for (int mt = 0; mt < 4; mt++) {
        int r0 = m0g + mt * 16 + (lane >> 2);
#pragma unroll
        for (int nt = 0; nt < 4; nt++) {
            int col = n0g + nt * 8 + (lane & 3) * 2;
            if (dSel == DSEL_QH) {
                __half2 v0 = __halves2half2(__float2half(acc[mt][nt][0]),
                                            __float2half(acc[mt][nt][1]));
                __half2 v1 = __halves2half2(__float2half(acc[mt][nt][2]),
                                            __float2half(acc[mt][nt][3]));
                *(__half2*)(g_Qh + (size_t)r0 * ldC + col) = v0;
                *(__half2*)(g_Qh + (size_t)(r0 + 8) * ldC + col) = v1;
            } else {
                float b0 = 0.f, b1 = 0.f;
                if (hasBias) { b0 = bias[col]; b1 = bias[col + 1]; }
                float* p = Cd + (size_t)r0 * ldC + col;
                p[0] = acc[mt][nt][0] + b0;
                p[1] = acc[mt][nt][1] + b1;
                float* q = p + 8 * ldC;
                q[0] = acc[mt][nt][2] + b0;
                q[1] = acc[mt][nt][3] + b1;
            }
        }
    }
}

// ---------------------------------------------------------------------------
// Conversion kernels
// ---------------------------------------------------------------------------
__global__ void split_x_kernel(const float* __restrict__ x) {
    const int total = B_*N_*C_;
    for (int i = blockIdx.x * blockDim.x + threadIdx.x; i < total;
         i += gridDim.x * blockDim.x)
        g_xf[i] = __float2half(x[i]);
}

// Transpose: W[K][N] -> Wt[n][k] fp16. perm: output row n -> (n%8)*64 + n/8
__global__ void trans_split_kernel(const float* __restrict__ W, int K, int N,
                                   int tSel, int perm) {
    __shared__ float t[32][33];
    int n0 = blockIdx.x * 32, k0 = blockIdx.y * 32;
    int tx = threadIdx.x, ty = threadIdx.y;
#pragma unroll
    for (int i = 0; i < 4; i++)
        t[ty + 8 * i][tx] = W[(size_t)(k0 + ty + 8 * i) * N + n0 + tx];
    __syncthreads();
    __half* Th;
    switch (tSel) {
        case TSEL_WQT:  Th = g_Wqt;  break;
        case TSEL_WKVT: Th = g_Wkvt; break;
        case TSEL_WCT:  Th = g_Wct;  break;
        default:        Th = g_Wpt;  break;
    }
#pragma unroll
    for (int i = 0; i < 4; i++) {
        int n = n0 + ty + 8 * i;
        int np = perm ? ((n & 7) * 64 + (n >> 3)) : n;
        Th[(size_t)np * K + k0 + tx] = __float2half(t[tx][ty + 8 * i]);
    }
}

// ---------------------------------------------------------------------------
// Split-K reduce + LayerNorm -> fp16 F
// ---------------------------------------------------------------------------
__inline__ __device__ float warpsum(float v) {
#pragma unroll
    for (int o = 16; o > 0; o >>= 1) v += __shfl_down_sync(0xffffffffu, v, o);
    return v;
}

__global__ __launch_bounds__(256) void reduce_ln(
    const float* __restrict__ gamma, const float* __restrict__ beta)
{
    int row = blockIdx.x;
    int tid = threadIdx.x;
    int c0 = tid, c1 = tid + 256;

    float v0 = 0.f, v1 = 0.f;
    for (int pz = 0; pz < SPLITK; pz++) {
        size_t base = (size_t)pz * MROWS * C_ + (size_t)row * C_;
        v0 += g_part[base + c0];
        v1 += g_part[base + c1];
    }
    float sum = v0 + v1;
    float sq = v0 * v0 + v1 * v1;

    __shared__ float ssum[8], ssq[8];
    __shared__ float s_mean, s_inv;
    float ws = warpsum(sum);
    float wq = warpsum(sq);
    int lane = tid & 31, wid = tid >> 5;
    if (lane == 0) { ssum[wid] = ws; ssq[wid] = wq; }
    __syncthreads();
    if (tid == 0) {
        float S = 0.f, Q = 0.f;
#pragma unroll
        for (int i = 0; i < 8; i++) { S += ssum[i]; Q += ssq[i]; }
        float mean = S * (1.0f / C_);
        float var = Q * (1.0f / C_) - mean * mean;
        s_mean = mean;
        s_inv = rsqrtf(var + EPS);
    }
    __syncthreads();
    float mean = s_mean, inv = s_inv;
    g_Ff[(size_t)row * C_ + c0] =
        __float2half((v0 - mean) * inv * gamma[c0] + beta[c0]);
    g_Ff[(size_t)row * C_ + c1] =
        __float2half((v1 - mean) * inv * gamma[c1] + beta[c1]);
}

// ---------------------------------------------------------------------------
// MMA attention. Block = (b*8+nh, qtile of 64). 128 threads / 4 warps.
// S = Q@(Kh+Kl)^T ; softmax ; O = (Ph+Pl)@(Vh+Vl) (drop Pl@Vl).
// Smem rows padded to 144B (stride 9 slots -> conflict-free ldmatrix).
// ---------------------------------------------------------------------------
#define AROWB 144
#define AQ  0
#define AKH 9216
#define AKL 18432
#define AVH 27648
#define AVL 36864

__global__ __launch_bounds__(128) void attn_mma()
{
    __shared__ __align__(16) char asm_[46080];
    uint32_t sb = smem_u32(asm_);
    int tid = threadIdx.x, lane = tid & 31, wid = tid >> 5;
    int b = blockIdx.x >> 3, nh = blockIdx.x & 7;
    int n0 = blockIdx.y * 64;

    // load Q (64 rows x 64 halves)
    for (int idx = tid; idx < 512; idx += 128) {
        int r = idx >> 3, s = idx & 7;
        const uint4* src = (const uint4*)(g_Qh
            + ((size_t)(b * 4096 + n0 + r)) * 512 + nh * 64 + s * 8);
        *(uint4*)(asm_ + AQ + r * AROWB + s * 16) = *src;
    }
    // load K, V with hi/lo split (fp32 source)
    for (int idx = tid; idx < 1024; idx += 128) {
        int r = idx >> 4, c4 = idx & 15;
        size_t base = ((size_t)(b * 64 + r)) * 1024 + nh * 64 + c4 * 4;
        float4 kf = *(const float4*)(g_KV + base);
        float4 vf = *(const float4*)(g_KV + base + 512);
        __half kh0 = __float2half(kf.x), kh1 = __float2half(kf.y);
        __half kh2 = __float2half(kf.z), kh3 = __float2half(kf.w);
        __half vh0 = __float2half(vf.x), vh1 = __float2half(vf.y);
        __half vh2 = __float2half(vf.z), vh3 = __float2half(vf.w);
        uint32_t o = r * AROWB + c4 * 8;
        ((__half2*)(asm_ + AKH + o))[0] = __halves2half2(kh0, kh1);
        ((__half2*)(asm_ + AKH + o))[1] = __halves2half2(kh2, kh3);
        ((__half2*)(asm_ + AKL + o))[0] = __halves2half2(
            __float2half(kf.x - __half2float(kh0)),
            __float2half(kf.y - __half2float(kh1)));
        ((__half2*)(asm_ + AKL + o))[1] = __halves2half2(
            __float2half(kf.z - __half2float(kh2)),
            __float2half(kf.w - __half2float(kh3)));
        ((__half2*)(asm_ + AVH + o))[0] = __halves2half2(vh0, vh1);
        ((__half2*)(asm_ + AVH + o))[1] = __halves2half2(vh2, vh3);
        ((__half2*)(asm_ + AVL + o))[0] = __halves2half2(
            __float2half(vf.x - __half2float(vh0)),
            __float2half(vf.y - __half2float(vh1)));
        ((__half2*)(asm_ + AVL + o))[1] = __halves2half2(
            __float2half(vf.z - __half2float(vh2)),
            __float2half(vf.w - __half2float(vh3)));
    }
    __syncthreads();

    int mat = lane >> 3;
    int arow = ((mat & 1) << 3) + (lane & 7);
    int brow = ((mat >> 1) << 3) + (lane & 7);

    // ---- S = Q @ (Kh+Kl)^T  (m16 per warp, n64, k64)
    float sacc[8][4];
#pragma unroll
    for (int i = 0; i < 8; i++)
#pragma unroll
        for (int j = 0; j < 4; j++) sacc[i][j] = 0.f;

#pragma unroll
    for (int kk = 0; kk < 4; kk++) {
        int akcol = kk * 16 + ((mat >> 1) << 3);
        int bkcol = kk * 16 + ((mat & 1) << 3);
        uint32_t a[4];
        ldm_x4(a, sb + AQ + (uint32_t)(wid * 16 + arow) * AROWB + akcol * 2);
#pragma unroll
        for (int ng = 0; ng < 4; ng++) {
            uint32_t bh[4], bl[4];
            uint32_t ba = sb + (uint32_t)(ng * 16 + brow) * AROWB + bkcol * 2;
            ldm_x4(bh, ba + AKH);
            ldm_x4(bl, ba + AKL);
            mma16816(sacc[2 * ng],     a, bh);
            mma16816(sacc[2 * ng + 1], a, bh + 2);
            mma16816(sacc[2 * ng],     a, bl);
            mma16816(sacc[2 * ng + 1], a, bl + 2);
        }
    }

    // ---- softmax (rows r0=lane>>2 and r0+8 of the warp's m16)
    float mx0 = -1e30f, mx1 = -1e30f;
#pragma unroll
    for (int nt = 0; nt < 8; nt++) {
#pragma unroll
        for (int j = 0; j < 4; j++) sacc[nt][j] *= 0.125f;
        mx0 = fmaxf(mx0, fmaxf(sacc[nt][0], sacc[nt][1]));
        mx1 = fmaxf(mx1, fmaxf(sacc[nt][2], sacc[nt][3]));
    }
    mx0 = fmaxf(mx0, __shfl_xor_sync(0xffffffffu, mx0, 1));
    mx0 = fmaxf(mx0, __shfl_xor_sync(0xffffffffu, mx0, 2));
    mx1 = fmaxf(mx1, __shfl_xor_sync(0xffffffffu, mx1, 1));
    mx1 = fmaxf(mx1, __shfl_xor_sync(0xffffffffu, mx1, 2));
    float sum0 = 0.f, sum1 = 0.f;
#pragma unroll
    for (int nt = 0; nt < 8; nt++) {
        sacc[nt][0] = __expf(sacc[nt][0] - mx0);
        sacc[nt][1] = __expf(sacc[nt][1] - mx0);
        sacc[nt][2] = __expf(sacc[nt][2] - mx1);
        sacc[nt][3] = __expf(sacc[nt][3] - mx1);
        sum0 += sacc[nt][0] + sacc[nt][1];
        sum1 += sacc[nt][2] + sacc[nt][3];
    }
    sum0 += __shfl_xor_sync(0xffffffffu, sum0, 1);
    sum0 += __shfl_xor_sync(0xffffffffu, sum0, 2);
    sum1 += __shfl_xor_sync(0xffffffffu, sum1, 1);
    sum1 += __shfl_xor_sync(0xffffffffu, sum1, 2);
    float inv0 = 1.f / sum0, inv1 = 1.f / sum1;

    // ---- O = (Ph+Pl) @ (Vh+Vl), drop Pl@Vl
    float oacc[8][4];
#pragma unroll
    for (int i = 0; i < 8; i++)
#pragma unroll
        for (int j = 0; j < 4; j++) oacc[i][j] = 0.f;

#pragma unroll
    for (int kt = 0; kt < 4; kt++) {
        // A-fragments from the P tiles 2kt, 2kt+1 (hi + residual)
        uint32_t ah[4], al[4];
#pragma unroll
        for (int f = 0; f < 4; f++) {
            int ti = 2 * kt + (f >> 1);
            int j0 = (f & 1) * 2;
            float p0 = sacc[ti][j0], p1 = sacc[ti][j0 + 1];
            __half h0 = __float2half(p0), h1 = __float2half(p1);
            __half2 hh = __halves2half2(h0, h1);
            ah[f] = *(uint32_t*)&hh;
            __half2 ll = __halves2half2(
                __float2half(p0 - __half2float(h0)),
                __float2half(p1 - __half2float(h1)));
            al[f] = *(uint32_t*)&ll;
        }
        // reorder: a-frag = {tile2kt[c0c1], tile2kt[c2c3], tile2kt+1[c0c1], tile2kt+1[c2c3]}
        // f mapping above: f0=t0 j0, f1=t0 j2, f2=t1 j0, f3=t1 j2  -> already correct.
        int vrow = kt * 16 + ((lane >> 3) & 1) * 8 + (lane & 7);
        int vcol = (lane >> 4) * 8;
#pragma unroll
        for (int ng = 0; ng < 4; ng++) {
            uint32_t bh[4], bl[4];
            uint32_t ba = sb + (uint32_t)vrow * AROWB + (ng * 16 + vcol) * 2;
            ldm_x4t(bh, ba + AVH);
            ldm_x4t(bl, ba + AVL);
            mma16816(oacc[2 * ng],     ah, bh);
            mma16816(oacc[2 * ng + 1], ah, bh + 2);
            mma16816(oacc[2 * ng],     ah, bl);
            mma16816(oacc[2 * ng + 1], ah, bl + 2);
            mma16816(oacc[2 * ng],     al, bh);
            mma16816(oacc[2 * ng + 1], al, bh + 2);
        }
    }

    // ---- write O (fp16, channel = nh*64+hd)
    int r0 = n0 + wid * 16 + (lane >> 2);
#pragma unroll
    for (int nt = 0; nt < 8; nt++) {
        int col = nh * 64 + nt * 8 + (lane & 3) * 2;
        __half2 v0 = __halves2half2(__float2half(oacc[nt][0] * inv0),
                                    __float2half(oacc[nt][1] * inv0));
        __half2 v1 = __halves2half2(__float2half(oacc[nt][2] * inv1),
                                    __float2half(oacc[nt][3] * inv1));
        *(__half2*)(g_AOf + ((size_t)(b * 4096 + r0)) * 512 + col) = v0;
        *(__half2*)(g_AOf + ((size_t)(b * 4096 + r0 + 8)) * 512 + col) = v1;
    }
}

// ---------------------------------------------------------------------------
// Host launcher
// ---------------------------------------------------------------------------
extern "C" void kernel_launch(void* const* d_in, const int* in_sizes, int n_in,
                              void* d_out, int out_size)
{
    const float* x     = (const float*)d_in[0];
    const float* Wq    = (const float*)d_in[1];
    const float* Wkv   = (const float*)d_in[2];
    const float* convw = (const float*)d_in[3];
    const float* gamma = (const float*)d_in[4];
    const float* beta  = (const float*)d_in[5];
    const float* Wp    = (const float*)d_in[6];
    const float* bp    = (const float*)d_in[7];
    float* out = (float*)d_out;

    cudaFuncSetAttribute(mgemm, cudaFuncAttributeMaxDynamicSharedMemorySize,
                         MG_SMEM);

    // conversions
    split_x_kernel<<<8192, 256>>>(x);
    dim3 tb(32, 8);
    trans_split_kernel<<<dim3(16, 16), tb>>>(Wq, 512, 512, TSEL_WQT, 1);
    trans_split_kernel<<<dim3(32, 16), tb>>>(Wkv, 512, 1024, TSEL_WKVT, 0);
    trans_split_kernel<<<dim3(16, 1024), tb>>>(convw, KCONV, 512, TSEL_WCT, 0);
    trans_split_kernel<<<dim3(16, 16), tb>>>(Wp, 512, 512, TSEL_WPT, 0);

    // Q = x @ Wq  -> head-major fp16 g_Qh
    mgemm<<<dim3(4, 256, 1), 256, MG_SMEM>>>(
        ASEL_X, BSEL_WQT, DSEL_QH, 512, 512, 512, nullptr, nullptr, 0, 0);
    // conv as gathered GEMM, split-K=16 -> g_part
    mgemm<<<dim3(4, 4, SPLITK), 256, MG_SMEM>>>(
        ASEL_X, BSEL_WCT, DSEL_PART, KCONV, KCHUNK, 512, nullptr, nullptr, 0, 1);
    // reduce + LN -> Ff
    reduce_ln<<<MROWS, 256>>>(gamma, beta);
    // KV = F @ Wkv (fp32 out)
    mgemm<<<dim3(8, 4, 1), 256, MG_SMEM>>>(
        ASEL_F, BSEL_WKVT, DSEL_KV, 512, 512, 1024, nullptr, nullptr, 0, 0);
    // attention (MMA) -> AOf
    attn_mma<<<dim3(64, 64), 128>>>();
    // out = AO @ Wp + bp
    mgemm<<<dim3(4, 256, 1), 256, MG_SMEM>>>(
        ASEL_AO, BSEL_WPT, DSEL_EXT, 512, 512, 512, out, bp, 1, 0);
}

// round 7
// speedup vs baseline: 5.6344x; 1.0605x over previous
#include <cuda_runtime.h>
#include <cuda_fp16.h>
#include <math.h>
#include <cstdint>

// Problem constants
#define B_   8
#define N_   4096
#define C_   512
#define NH_  8
#define HD_  64
#define MROWS 512
#define KCONV 32768
#define SPLITK 16
#define KCHUNK (KCONV/SPLITK)  // 2048
#define EPS 1e-3f

// ---------------------------------------------------------------------------
// Device global scratch
// ---------------------------------------------------------------------------
__device__ __half g_Qh[B_*N_*C_];               // head-major fp16 Q: col = nh*64+hd
__device__ float g_part[SPLITK*MROWS*C_];       // conv split-K partials (16MB)
__device__ __half g_Kf[MROWS*C_];               // K fp16 (head-major cols)
__device__ __half g_Vh[MROWS*C_];               // V hi fp16
__device__ __half g_Vl[MROWS*C_];               // V lo fp16 (residual)
__device__ __half g_xf[B_*N_*C_];               // x fp16
__device__ __half g_Ff[MROWS*C_];               // LN out fp16
__device__ __half g_AOf[B_*N_*C_];              // attention out fp16
__device__ __half g_Wqt[C_*C_];                 // Wq^T, rows permuted head-major
__device__ __half g_Wkvt[2*C_*C_];              // Wkv^T
__device__ __half g_Wct[KCONV*C_];              // convW^T [512][32768]
__device__ __half g_Wpt[C_*C_];                 // Wp^T

// selectors
#define ASEL_X  0
#define ASEL_F  1
#define ASEL_AO 2
#define BSEL_WQT  0
#define BSEL_WKVT 1
#define BSEL_WCT  2
#define BSEL_WPT  3
#define DSEL_QH   0
#define DSEL_PART 1
#define DSEL_KV   2
#define DSEL_EXT  3
#define TSEL_WQT  0
#define TSEL_WKVT 1
#define TSEL_WCT  2
#define TSEL_WPT  3

// ---------------------------------------------------------------------------
// PTX helpers (sm_80-baseline; valid on compute_103 virtual arch)
// ---------------------------------------------------------------------------
__device__ __forceinline__ uint32_t smem_u32(const void* p) {
    uint32_t a;
    asm("{ .reg .u64 t; cvta.to.shared.u64 t, %1; cvt.u32.u64 %0, t; }"
        : "=r"(a) : "l"(p));
    return a;
}
__device__ __forceinline__ void ldm_x4(uint32_t* r, uint32_t addr) {
    asm volatile("ldmatrix.sync.aligned.m8n8.x4.shared.b16 {%0,%1,%2,%3}, [%4];"
        : "=r"(r[0]), "=r"(r[1]), "=r"(r[2]), "=r"(r[3]) : "r"(addr));
}
__device__ __forceinline__ void ldm_x4t(uint32_t* r, uint32_t addr) {
    asm volatile("ldmatrix.sync.aligned.m8n8.x4.trans.shared.b16 {%0,%1,%2,%3}, [%4];"
        : "=r"(r[0]), "=r"(r[1]), "=r"(r[2]), "=r"(r[3]) : "r"(addr));
}
__device__ __forceinline__ void mma16816(float* c, const uint32_t* a,
                                         const uint32_t* b) {
    asm volatile("mma.sync.aligned.m16n8k16.row.col.f32.f16.f16.f32 "
        "{%0,%1,%2,%3},{%4,%5,%6,%7},{%8,%9},{%0,%1,%2,%3};"
        : "+f"(c[0]), "+f"(c[1]), "+f"(c[2]), "+f"(c[3])
        : "r"(a[0]), "r"(a[1]), "r"(a[2]), "r"(a[3]), "r"(b[0]), "r"(b[1]));
}
__device__ __forceinline__ void cpa16(uint32_t d, const void* s) {
    asm volatile("cp.async.cg.shared.global [%0], [%1], 16;" :: "r"(d), "l"(s));
}
#define CPA_COMMIT() asm volatile("cp.async.commit_group;" ::: "memory")
#define CPA_WAIT2()  asm volatile("cp.async.wait_group 2;" ::: "memory")

// mgemm smem: per stage A 128x40 halves | B 128x40 halves, 80B rows
// (5x16B slots; slot=(5r+s)%8 is a permutation => conflict-free ldmatrix)
#define ROWB 80
#define OFF_B 10240
#define STG   20480
#define NSTAGE 4
#define MG_SMEM (NSTAGE*STG)   // 81920 (dynamic)

// ---------------------------------------------------------------------------
// fp16 tensor-core GEMM. C[M,N] = A @ Bt^T (Bt stored [N][K]).
// Tile 128x128, BK=32, 256 threads, 4-stage cp.async, 1 sync/iter.
// ---------------------------------------------------------------------------
__global__ __launch_bounds__(256, 2) void mgemm(
    int aSel, int bSel, int dSel,
    int Kfull, int kcount, int ldC,
    float* __restrict__ extC, const float* __restrict__ bias,
    int hasBias, int aGather)
{
    extern __shared__ __align__(16) char smem[];
    uint32_t sb = smem_u32(smem);
    int tid = threadIdx.x, lane = tid & 31, wid = tid >> 5;
    int rowBase = blockIdx.y * 128, colBase = blockIdx.x * 128;
    int kbase = blockIdx.z * kcount;

    const __half *A, *B;
    switch (aSel) {
        case ASEL_X: A = g_xf;  break;
        case ASEL_F: A = g_Ff;  break;
        default:     A = g_AOf; break;
    }
    switch (bSel) {
        case BSEL_WQT:  B = g_Wqt;  break;
        case BSEL_WKVT: B = g_Wkvt; break;
        case BSEL_WCT:  B = g_Wct;  break;
        default:        B = g_Wpt;  break;
    }
    float* Cd;
    switch (dSel) {
        case DSEL_PART: Cd = g_part + (size_t)blockIdx.z * (MROWS * C_); break;
        default:        Cd = extC; break;
    }

    int m0 = (wid >> 2) * 64;
    int n0 = (wid & 3) * 32;

    float acc[4][4][4];
#pragma unroll
    for (int a = 0; a < 4; a++)
#pragma unroll
        for (int b = 0; b < 4; b++)
#pragma unroll
            for (int c = 0; c < 4; c++) acc[a][b][c] = 0.f;

    int iters = kcount >> 5;

    auto issue = [&](int i) {
        int k0 = kbase + i * 32;
        uint32_t so = sb + (uint32_t)(i & (NSTAGE - 1)) * STG;
#pragma unroll
        for (int j = 0; j < 2; j++) {
            int c = tid + j * 256;
            int r = c >> 2, s = c & 3;
            size_t off;
            if (aGather) {
                int rg = rowBase + r;
                int bb = rg >> 6;
                int p = rg & 63;
                int pix = k0 >> 9;     // constant across the 32-wide slab
                int pixel = bb * 4096 + (p >> 3) * 512 + (p & 7) * 8
                          + (pix >> 3) * 64 + (pix & 7);
                off = (size_t)pixel * 512 + (k0 & 511) + s * 8;
            } else {
                off = (size_t)(rowBase + r) * Kfull + k0 + s * 8;
            }
            cpa16(so + r * ROWB + s * 16, A + off);
        }
#pragma unroll
        for (int j = 0; j < 2; j++) {
            int c = tid + j * 256;
            int r = c >> 2, s = c & 3;
            cpa16(so + OFF_B + r * ROWB + s * 16,
                  B + (size_t)(colBase + r) * Kfull + k0 + s * 8);
        }
        CPA_COMMIT();
    };

    int mat = lane >> 3;
    int arow_off = ((mat & 1) << 3) + (lane & 7);
    int nrow_off = ((mat >> 1) << 3) + (lane & 7);

    issue(0); issue(1); issue(2);   // iters >= 16 always

    for (int i = 0; i < iters; i++) {
        CPA_WAIT2();
        __syncthreads();
        if (i + 3 < iters) issue(i + 3);
        else CPA_COMMIT();          // empty group keeps wait_group arithmetic exact

        uint32_t base = sb + (uint32_t)(i & (NSTAGE - 1)) * STG;
#pragma unroll
        for (int kk = 0; kk < 2; kk++) {
            int akcol = kk * 16 + ((mat >> 1) << 3);
            int bkcol = kk * 16 + ((mat & 1) << 3);
            uint32_t a_f[4][4], b_f[2][4];
#pragma unroll
            for (int mt = 0; mt < 4; mt++)
                ldm_x4(a_f[mt], base + (uint32_t)(m0 + mt * 16 + arow_off) * ROWB
                                 + akcol * 2);
#pragma unroll
            for (int np = 0; np < 2; np++)
                ldm_x4(b_f[np], base + OFF_B
                                 + (uint32_t)(n0 + np * 16 + nrow_off) * ROWB
                                 + bkcol * 2);
#pragma unroll
            for (int mt = 0; mt < 4; mt++)
#pragma unroll
                for (int nt = 0; nt < 4; nt++)
                    mma16816(acc[mt][nt], a_f[mt], &b_f[nt >> 1][(nt & 1) * 2]);
        }
    }

    // epilogue
    int m0g = rowBase + m0, n0g = colBase + n0;
#pragma unroll
    for (int mt = 0; mt < 4; mt++) {
        int r0 = m0g + mt * 16 + (lane >> 2);
#pragma unroll
        for (int nt = 0; nt < 4; nt++) {
            int col = n0g + nt * 8 + (lane & 3) * 2;
            if (dSel == DSEL_QH) {
                __half2 v0 = __halves2half2(__float2half(acc[mt][nt][0]),
                                            __float2half(acc[mt][nt][1]));
                __half2 v1 = __halves2half2(__float2half(acc[mt][nt][2]),
                                            __float2half(acc[mt][nt][3]));
                *(__half2*)(g_Qh + (size_t)r0 * ldC + col) = v0;
                *(__half2*)(g_Qh + (size_t)(r0 + 8) * ldC + col) = v1;
            } else if (dSel == DSEL_KV) {
                // cols [0,512): K -> g_Kf ; cols [512,1024): V -> g_Vh + g_Vl
#pragma unroll
                for (int half = 0; half < 2; half++) {
                    int rr = r0 + half * 8;
                    float f0 = acc[mt][nt][2 * half];
                    float f1 = acc[mt][nt][2 * half + 1];
                    if (col < 512) {
                        *(__half2*)(g_Kf + (size_t)rr * 512 + col) =
                            __halves2half2(__float2half(f0), __float2half(f1));
                    } else {
                        __half h0 = __float2half(f0), h1 = __float2half(f1);
                        *(__half2*)(g_Vh + (size_t)rr * 512 + col - 512) =
                            __halves2half2(h0, h1);
                        *(__half2*)(g_Vl + (size_t)rr * 512 + col - 512) =
                            __halves2half2(
                                __float2half(f0 - __half2float(h0)),
                                __float2half(f1 - __half2float(h1)));
                    }
                }
            } else {
                float b0 = 0.f, b1 = 0.f;
                if (hasBias) { b0 = bias[col]; b1 = bias[col + 1]; }
                float* p = Cd + (size_t)r0 * ldC + col;
                p[0] = acc[mt][nt][0] + b0;
                p[1] = acc[mt][nt][1] + b1;
                float* q = p + 8 * ldC;
                q[0] = acc[mt][nt][2] + b0;
                q[1] = acc[mt][nt][3] + b1;
            }
        }
    }
}

// ---------------------------------------------------------------------------
// Conversion kernels
// ---------------------------------------------------------------------------
__global__ void split_x_kernel(const float* __restrict__ x) {
    const int total = B_*N_*C_;
    for (int i = blockIdx.x * blockDim.x + threadIdx.x; i < total;
         i += gridDim.x * blockDim.x)
        g_xf[i] = __float2half(x[i]);
}

// Transpose: W[K][N] -> Wt[n][k] fp16. perm: output row n -> (n%8)*64 + n/8
__global__ void trans_split_kernel(const float* __restrict__ W, int K, int N,
                                   int tSel, int perm) {
    __shared__ float t[32][33];
    int n0 = blockIdx.x * 32, k0 = blockIdx.y * 32;
    int tx = threadIdx.x, ty = threadIdx.y;
#pragma unroll
    for (int i = 0; i < 4; i++)
        t[ty + 8 * i][tx] = W[(size_t)(k0 + ty + 8 * i) * N + n0 + tx];
    __syncthreads();
    __half* Th;
    switch (tSel) {
        case TSEL_WQT:  Th = g_Wqt;  break;
        case TSEL_WKVT: Th = g_Wkvt; break;
        case TSEL_WCT:  Th = g_Wct;  break;
        default:        Th = g_Wpt;  break;
    }
#pragma unroll
    for (int i = 0; i < 4; i++) {
        int n = n0 + ty + 8 * i;
        int np = perm ? ((n & 7) * 64 + (n >> 3)) : n;
        Th[(size_t)np * K + k0 + tx] = __float2half(t[tx][ty + 8 * i]);
    }
}

// ---------------------------------------------------------------------------
// Split-K reduce + LayerNorm -> fp16 F
// ---------------------------------------------------------------------------
__inline__ __device__ float warpsum(float v) {
#pragma unroll
    for (int o = 16; o > 0; o >>= 1) v += __shfl_down_sync(0xffffffffu, v, o);
    return v;
}

__global__ __launch_bounds__(256) void reduce_ln(
    const float* __restrict__ gamma, const float* __restrict__ beta)
{
    int row = blockIdx.x;
    int tid = threadIdx.x;
    int c0 = tid, c1 = tid + 256;

    float v0 = 0.f, v1 = 0.f;
    for (int pz = 0; pz < SPLITK; pz++) {
        size_t base = (size_t)pz * MROWS * C_ + (size_t)row * C_;
        v0 += g_part[base + c0];
        v1 += g_part[base + c1];
    }
    float sum = v0 + v1;
    float sq = v0 * v0 + v1 * v1;

    __shared__ float ssum[8], ssq[8];
    __shared__ float s_mean, s_inv;
    float ws = warpsum(sum);
    float wq = warpsum(sq);
    int lane = tid & 31, wid = tid >> 5;
    if (lane == 0) { ssum[wid] = ws; ssq[wid] = wq; }
    __syncthreads();
    if (tid == 0) {
        float S = 0.f, Q = 0.f;
#pragma unroll
        for (int i = 0; i < 8; i++) { S += ssum[i]; Q += ssq[i]; }
        float mean = S * (1.0f / C_);
        float var = Q * (1.0f / C_) - mean * mean;
        s_mean = mean;
        s_inv = rsqrtf(var + EPS);
    }
    __syncthreads();
    float mean = s_mean, inv = s_inv;
    g_Ff[(size_t)row * C_ + c0] =
        __float2half((v0 - mean) * inv * gamma[c0] + beta[c0]);
    g_Ff[(size_t)row * C_ + c1] =
        __float2half((v1 - mean) * inv * gamma[c1] + beta[c1]);
}

// ---------------------------------------------------------------------------
// MMA attention. Block = (b*8+nh, qtile of 128). 256 threads / 8 warps.
// S = Q@Kh^T (single term) ; softmax ; O = Ph@(Vh+Vl).
// Smem rows padded to 144B (stride 9 slots -> conflict-free ldmatrix).
// ---------------------------------------------------------------------------
#define AROWB 144
#define AQ  0
#define AKH 18432
#define AVH 27648
#define AVL 36864

__global__ __launch_bounds__(256) void attn_mma()
{
    __shared__ __align__(16) char asm_[46080];
    uint32_t sb = smem_u32(asm_);
    int tid = threadIdx.x, lane = tid & 31, wid = tid >> 5;
    int b = blockIdx.x >> 3, nh = blockIdx.x & 7;
    int n0 = blockIdx.y * 128;

    // load Q (128 rows x 64 halves)
    for (int idx = tid; idx < 1024; idx += 256) {
        int r = idx >> 3, s = idx & 7;
        *(uint4*)(asm_ + AQ + r * AROWB + s * 16) =
            *(const uint4*)(g_Qh + ((size_t)(b * 4096 + n0 + r)) * 512
                            + nh * 64 + s * 8);
    }
    // load Kh, Vh, Vl (64 rows x 64 halves each)
    for (int idx = tid; idx < 512; idx += 256) {
        int r = idx >> 3, s = idx & 7;
        size_t off = ((size_t)(b * 64 + r)) * 512 + nh * 64 + s * 8;
        uint32_t so = r * AROWB + s * 16;
        *(uint4*)(asm_ + AKH + so) = *(const uint4*)(g_Kf + off);
        *(uint4*)(asm_ + AVH + so) = *(const uint4*)(g_Vh + off);
        *(uint4*)(asm_ + AVL + so) = *(const uint4*)(g_Vl + off);
    }
    __syncthreads();

    int mat = lane >> 3;
    int arow = ((mat & 1) << 3) + (lane & 7);
    int brow = ((mat >> 1) << 3) + (lane & 7);

    // ---- S = Q @ Kh^T  (m16 per warp, n64, k64)
    float sacc[8][4];
#pragma unroll
    for (int i = 0; i < 8; i++)
#pragma unroll
        for (int j = 0; j < 4; j++) sacc[i][j] = 0.f;

#pragma unroll
    for (int kk = 0; kk < 4; kk++) {
        int akcol = kk * 16 + ((mat >> 1) << 3);
        int bkcol = kk * 16 + ((mat & 1) << 3);
        uint32_t a[4];
        ldm_x4(a, sb + AQ + (uint32_t)(wid * 16 + arow) * AROWB + akcol * 2);
#pragma unroll
        for (int ng = 0; ng < 4; ng++) {
            uint32_t bh[4];
            ldm_x4(bh, sb + AKH + (uint32_t)(ng * 16 + brow) * AROWB + bkcol * 2);
            mma16816(sacc[2 * ng],     a, bh);
            mma16816(sacc[2 * ng + 1], a, bh + 2);
        }
    }

    // ---- softmax (rows r0=lane>>2 and r0+8 of the warp's m16)
    float mx0 = -1e30f, mx1 = -1e30f;
#pragma unroll
    for (int nt = 0; nt < 8; nt++) {
#pragma unroll
        for (int j = 0; j < 4; j++) sacc[nt][j] *= 0.125f;
        mx0 = fmaxf(mx0, fmaxf(sacc[nt][0], sacc[nt][1]));
        mx1 = fmaxf(mx1, fmaxf(sacc[nt][2], sacc[nt][3]));
    }
    mx0 = fmaxf(mx0, __shfl_xor_sync(0xffffffffu, mx0, 1));
    mx0 = fmaxf(mx0, __shfl_xor_sync(0xffffffffu, mx0, 2));
    mx1 = fmaxf(mx1, __shfl_xor_sync(0xffffffffu, mx1, 1));
    mx1 = fmaxf(mx1, __shfl_xor_sync(0xffffffffu, mx1, 2));
    float sum0 = 0.f, sum1 = 0.f;
#pragma unroll
    for (int nt = 0; nt < 8; nt++) {
        sacc[nt][0] = __expf(sacc[nt][0] - mx0);
        sacc[nt][1] = __expf(sacc[nt][1] - mx0);
        sacc[nt][2] = __expf(sacc[nt][2] - mx1);
        sacc[nt][3] = __expf(sacc[nt][3] - mx1);
        sum0 += sacc[nt][0] + sacc[nt][1];
        sum1 += sacc[nt][2] + sacc[nt][3];
    }
    sum0 += __shfl_xor_sync(0xffffffffu, sum0, 1);
    sum0 += __shfl_xor_sync(0xffffffffu, sum0, 2);
    sum1 += __shfl_xor_sync(0xffffffffu, sum1, 1);
    sum1 += __shfl_xor_sync(0xffffffffu, sum1, 2);
    float inv0 = 1.f / sum0, inv1 = 1.f / sum1;

    // ---- O = Ph @ (Vh + Vl)
    float oacc[8][4];
#pragma unroll
    for (int i = 0; i < 8; i++)
#pragma unroll
        for (int j = 0; j < 4; j++) oacc[i][j] = 0.f;

#pragma unroll
    for (int kt = 0; kt < 4; kt++) {
        uint32_t ah[4];
#pragma unroll
        for (int f = 0; f < 4; f++) {
            int ti = 2 * kt + (f >> 1);
            int j0 = (f & 1) * 2;
            __half2 hh = __halves2half2(__float2half(sacc[ti][j0]),
                                        __float2half(sacc[ti][j0 + 1]));
            ah[f] = *(uint32_t*)&hh;
        }
        int vrow = kt * 16 + ((lane >> 3) & 1) * 8 + (lane & 7);
        int vcol = (lane >> 4) * 8;
#pragma unroll
        for (int ng = 0; ng < 4; ng++) {
            uint32_t bh[4], bl[4];
            uint32_t ba = sb + (uint32_t)vrow * AROWB + (ng * 16 + vcol) * 2;
            ldm_x4t(bh, ba + AVH);
            ldm_x4t(bl, ba + AVL);
            mma16816(oacc[2 * ng],     ah, bh);
            mma16816(oacc[2 * ng + 1], ah, bh + 2);
            mma16816(oacc[2 * ng],     ah, bl);
            mma16816(oacc[2 * ng + 1], ah, bl + 2);
        }
    }

    // ---- write O (fp16, channel = nh*64+hd)
    int r0 = n0 + wid * 16 + (lane >> 2);
#pragma unroll
    for (int nt = 0; nt < 8; nt++) {
        int col = nh * 64 + nt * 8 + (lane & 3) * 2;
        __half2 v0 = __halves2half2(__float2half(oacc[nt][0] * inv0),
                                    __float2half(oacc[nt][1] * inv0));
        __half2 v1 = __halves2half2(__float2half(oacc[nt][2] * inv1),
                                    __float2half(oacc[nt][3] * inv1));
        *(__half2*)(g_AOf + ((size_t)(b * 4096 + r0)) * 512 + col) = v0;
        *(__half2*)(g_AOf + ((size_t)(b * 4096 + r0 + 8)) * 512 + col) = v1;
    }
}

// ---------------------------------------------------------------------------
// Host launcher
// ---------------------------------------------------------------------------
extern "C" void kernel_launch(void* const* d_in, const int* in_sizes, int n_in,
                              void* d_out, int out_size)
{
    const float* x     = (const float*)d_in[0];
    const float* Wq    = (const float*)d_in[1];
    const float* Wkv   = (const float*)d_in[2];
    const float* convw = (const float*)d_in[3];
    const float* gamma = (const float*)d_in[4];
    const float* beta  = (const float*)d_in[5];
    const float* Wp    = (const float*)d_in[6];
    const float* bp    = (const float*)d_in[7];
    float* out = (float*)d_out;

    cudaFuncSetAttribute(mgemm, cudaFuncAttributeMaxDynamicSharedMemorySize,
                         MG_SMEM);

    // conversions
    split_x_kernel<<<8192, 256>>>(x);
    dim3 tb(32, 8);
    trans_split_kernel<<<dim3(16, 16), tb>>>(Wq, 512, 512, TSEL_WQT, 1);
    trans_split_kernel<<<dim3(32, 16), tb>>>(Wkv, 512, 1024, TSEL_WKVT, 0);
    trans_split_kernel<<<dim3(16, 1024), tb>>>(convw, KCONV, 512, TSEL_WCT, 0);
    trans_split_kernel<<<dim3(16, 16), tb>>>(Wp, 512, 512, TSEL_WPT, 0);

    // Q = x @ Wq  -> head-major fp16 g_Qh
    mgemm<<<dim3(4, 256, 1), 256, MG_SMEM>>>(
        ASEL_X, BSEL_WQT, DSEL_QH, 512, 512, 512, nullptr, nullptr, 0, 0);
    // conv as gathered GEMM, split-K=16 -> g_part
    mgemm<<<dim3(4, 4, SPLITK), 256, MG_SMEM>>>(
        ASEL_X, BSEL_WCT, DSEL_PART, KCONV, KCHUNK, 512, nullptr, nullptr, 0, 1);
    // reduce + LN -> Ff
    reduce_ln<<<MROWS, 256>>>(gamma, beta);
    // KV = F @ Wkv -> fp16 Kh / Vh / Vl directly
    mgemm<<<dim3(8, 4, 1), 256, MG_SMEM>>>(
        ASEL_F, BSEL_WKVT, DSEL_KV, 512, 512, 1024, nullptr, nullptr, 0, 0);
    // attention (MMA) -> AOf
    attn_mma<<<dim3(64, 32), 256>>>();
    // out = AO @ Wp + bp
    mgemm<<<dim3(4, 256, 1), 256, MG_SMEM>>>(
        ASEL_AO, BSEL_WPT, DSEL_EXT, 512, 512, 512, out, bp, 1, 0);
}

// round 8
// speedup vs baseline: 6.3286x; 1.1232x over previous
#include <cuda_runtime.h>
#include <cuda_fp16.h>
#include <math.h>
#include <cstdint>

// Problem constants
#define B_   8
#define N_   4096
#define C_   512
#define NH_  8
#define HD_  64
#define MROWS 512
#define KCONV 32768
#define SPLITK 16
#define KCHUNK (KCONV/SPLITK)  // 2048
#define EPS 1e-3f

// ---------------------------------------------------------------------------
// Device global scratch
// ---------------------------------------------------------------------------
__device__ __half g_Qh[B_*N_*C_];               // head-major fp16 Q: col = nh*64+hd
__device__ float g_part[SPLITK*MROWS*C_];       // conv split-K partials (16MB)
__device__ __half g_Kf[MROWS*C_];               // K fp16 (head-major cols)
__device__ __half g_Vh[MROWS*C_];               // V hi fp16
__device__ __half g_Vl[MROWS*C_];               // V lo fp16 (residual)
__device__ __half g_xf[B_*N_*C_];               // x fp16
__device__ __half g_Ff[MROWS*C_];               // LN out fp16
__device__ __half g_AOf[B_*N_*C_];              // attention out fp16
__device__ __half g_Wqt[C_*C_];                 // Wq^T, rows permuted head-major
__device__ __half g_Wkvt[2*C_*C_];              // Wkv^T
__device__ __half g_Wcf[KCONV*C_];              // convW fp16, NATIVE [K][N] layout
__device__ __half g_Wpt[C_*C_];                 // Wp^T

// selectors
#define ASEL_X  0
#define ASEL_F  1
#define ASEL_AO 2
#define BSEL_WQT  0
#define BSEL_WKVT 1
#define BSEL_WCF  2
#define BSEL_WPT  3
#define DSEL_QH   0
#define DSEL_PART 1
#define DSEL_KV   2
#define DSEL_EXT  3

// ---------------------------------------------------------------------------
// PTX helpers (sm_80-baseline; valid on compute_103 virtual arch)
// ---------------------------------------------------------------------------
__device__ __forceinline__ uint32_t smem_u32(const void* p) {
    uint32_t a;
    asm("{ .reg .u64 t; cvta.to.shared.u64 t, %1; cvt.u32.u64 %0, t; }"
        : "=r"(a) : "l"(p));
    return a;
}
__device__ __forceinline__ void ldm_x4(uint32_t* r, uint32_t addr) {
    asm volatile("ldmatrix.sync.aligned.m8n8.x4.shared.b16 {%0,%1,%2,%3}, [%4];"
        : "=r"(r[0]), "=r"(r[1]), "=r"(r[2]), "=r"(r[3]) : "r"(addr));
}
__device__ __forceinline__ void ldm_x4t(uint32_t* r, uint32_t addr) {
    asm volatile("ldmatrix.sync.aligned.m8n8.x4.trans.shared.b16 {%0,%1,%2,%3}, [%4];"
        : "=r"(r[0]), "=r"(r[1]), "=r"(r[2]), "=r"(r[3]) : "r"(addr));
}
__device__ __forceinline__ void mma16816(float* c, const uint32_t* a,
                                         const uint32_t* b) {
    asm volatile("mma.sync.aligned.m16n8k16.row.col.f32.f16.f16.f32 "
        "{%0,%1,%2,%3},{%4,%5,%6,%7},{%8,%9},{%0,%1,%2,%3};"
        : "+f"(c[0]), "+f"(c[1]), "+f"(c[2]), "+f"(c[3])
        : "r"(a[0]), "r"(a[1]), "r"(a[2]), "r"(a[3]), "r"(b[0]), "r"(b[1]));
}
__device__ __forceinline__ void cpa16(uint32_t d, const void* s) {
    asm volatile("cp.async.cg.shared.global [%0], [%1], 16;" :: "r"(d), "l"(s));
}
#define CPA_COMMIT() asm volatile("cp.async.commit_group;" ::: "memory")
#define CPA_WAIT2()  asm volatile("cp.async.wait_group 2;" ::: "memory")

// mgemm smem: per stage A 128x40 halves (80B rows, conflict-free) | B region.
// Non-trans B: 128x40 halves like A. Trans B: 32 rows x 272B (17-slot rows,
// (17r+s)%8 permutation -> conflict-free trans ldmatrix).
#define ROWB  80
#define OFF_B 10240
#define BTROWB 272
#define STG   20480
#define NSTAGE 4
#define MG_SMEM (NSTAGE*STG)   // 81920 (dynamic)

// ---------------------------------------------------------------------------
// fp16 tensor-core GEMM. BT=0: C = A @ Bt^T (Bt stored [N][K]).
//                        BT=1: C = A @ B    (B  stored [K][N], N=512).
// Tile 128x128, BK=32, 256 threads, 4-stage cp.async, 1 sync/iter.
// ---------------------------------------------------------------------------
template<int BT>
__global__ __launch_bounds__(256, 2) void mgemm(
    int aSel, int bSel, int dSel,
    int Kfull, int kcount, int ldC,
    float* __restrict__ extC, const float* __restrict__ bias,
    int hasBias, int aGather)
{
    extern __shared__ __align__(16) char smem[];
    uint32_t sb = smem_u32(smem);
    int tid = threadIdx.x, lane = tid & 31, wid = tid >> 5;
    int rowBase = blockIdx.y * 128, colBase = blockIdx.x * 128;
    int kbase = blockIdx.z * kcount;

    const __half *A, *B;
    switch (aSel) {
        case ASEL_X: A = g_xf;  break;
        case ASEL_F: A = g_Ff;  break;
        default:     A = g_AOf; break;
    }
    switch (bSel) {
        case BSEL_WQT:  B = g_Wqt;  break;
        case BSEL_WKVT: B = g_Wkvt; break;
        case BSEL_WCF:  B = g_Wcf;  break;
        default:        B = g_Wpt;  break;
    }
    float* Cd;
    switch (dSel) {
        case DSEL_PART: Cd = g_part + (size_t)blockIdx.z * (MROWS * C_); break;
        default:        Cd = extC; break;
    }

    int m0 = (wid >> 2) * 64;
    int n0 = (wid & 3) * 32;

    float acc[4][4][4];
#pragma unroll
    for (int a = 0; a < 4; a++)
#pragma unroll
        for (int b = 0; b < 4; b++)
#pragma unroll
            for (int c = 0; c < 4; c++) acc[a][b][c] = 0.f;

    int iters = kcount >> 5;

    auto issue = [&](int i) {
        int k0 = kbase + i * 32;
        uint32_t so = sb + (uint32_t)(i & (NSTAGE - 1)) * STG;
#pragma unroll
        for (int j = 0; j < 2; j++) {
            int c = tid + j * 256;
            int r = c >> 2, s = c & 3;
            size_t off;
            if (aGather) {
                int rg = rowBase + r;
                int bb = rg >> 6;
                int p = rg & 63;
                int pix = k0 >> 9;     // constant across the 32-wide slab
                int pixel = bb * 4096 + (p >> 3) * 512 + (p & 7) * 8
                          + (pix >> 3) * 64 + (pix & 7);
                off = (size_t)pixel * 512 + (k0 & 511) + s * 8;
            } else {
                off = (size_t)(rowBase + r) * Kfull + k0 + s * 8;
            }
            cpa16(so + r * ROWB + s * 16, A + off);
        }
        if (BT) {
            // B [K][N] native: 32 rows x 256B
#pragma unroll
            for (int j = 0; j < 2; j++) {
                int c = tid + j * 256;
                int r = c >> 4, s = c & 15;
                cpa16(so + OFF_B + r * BTROWB + s * 16,
                      B + (size_t)(k0 + r) * 512 + colBase + s * 8);
            }
        } else {
#pragma unroll
            for (int j = 0; j < 2; j++) {
                int c = tid + j * 256;
                int r = c >> 2, s = c & 3;
                cpa16(so + OFF_B + r * ROWB + s * 16,
                      B + (size_t)(colBase + r) * Kfull + k0 + s * 8);
            }
        }
        CPA_COMMIT();
    };

    int mat = lane >> 3;
    int arow_off = ((mat & 1) << 3) + (lane & 7);
    int nrow_off = ((mat >> 1) << 3) + (lane & 7);
    // trans-B fragment addressing (same scheme as attention's V path)
    int btrow_off = ((lane >> 3) & 1) * 8 + (lane & 7);
    int btcol_off = (lane >> 4) * 8;

    issue(0); issue(1); issue(2);   // iters >= 16 always

    for (int i = 0; i < iters; i++) {
        CPA_WAIT2();
        __syncthreads();
        if (i + 3 < iters) issue(i + 3);
        else CPA_COMMIT();          // empty group keeps wait_group arithmetic exact

        uint32_t base = sb + (uint32_t)(i & (NSTAGE - 1)) * STG;
#pragma unroll
        for (int kk = 0; kk < 2; kk++) {
            int akcol = kk * 16 + ((mat >> 1) << 3);
            uint32_t a_f[4][4], b_f[2][4];
#pragma unroll
            for (int mt = 0; mt < 4; mt++)
                ldm_x4(a_f[mt], base + (uint32_t)(m0 + mt * 16 + arow_off) * ROWB
                                 + akcol * 2);
            if (BT) {
                int vrow = kk * 16 + btrow_off;
#pragma unroll
                for (int np = 0; np < 2; np++)
                    ldm_x4t(b_f[np], base + OFF_B + (uint32_t)vrow * BTROWB
                                      + (n0 + np * 16 + btcol_off) * 2);
            } else {
                int bkcol = kk * 16 + ((mat & 1) << 3);
#pragma unroll
                for (int np = 0; np < 2; np++)
                    ldm_x4(b_f[np], base + OFF_B
                                     + (uint32_t)(n0 + np * 16 + nrow_off) * ROWB
                                     + bkcol * 2);
            }
#pragma unroll
            for (int mt = 0; mt < 4; mt++)
#pragma unroll
                for (int nt = 0; nt < 4; nt++)
                    mma16816(acc[mt][nt], a_f[mt], &b_f[nt >> 1][(nt & 1) * 2]);
        }
    }

    // epilogue
    int m0g = rowBase + m0, n0g = colBase + n0;
#pragma unroll
    for (int mt = 0; mt < 4; mt++) {
        int r0 = m0g + mt * 16 + (lane >> 2);
#pragma unroll
        for (int nt = 0; nt < 4; nt++) {
            int col = n0g + nt * 8 + (lane & 3) * 2;
            if (dSel == DSEL_QH) {
                __half2 v0 = __halves2half2(__float2half(acc[mt][nt][0]),
                                            __float2half(acc[mt][nt][1]));
                __half2 v1 = __halves2half2(__float2half(acc[mt][nt][2]),
                                            __float2half(acc[mt][nt][3]));
                *(__half2*)(g_Qh + (size_t)r0 * ldC + col) = v0;
                *(__half2*)(g_Qh + (size_t)(r0 + 8) * ldC + col) = v1;
            } else if (dSel == DSEL_KV) {
#pragma unroll
                for (int half = 0; half < 2; half++) {
                    int rr = r0 + half * 8;
                    float f0 = acc[mt][nt][2 * half];
                    float f1 = acc[mt][nt][2 * half + 1];
                    if (col < 512) {
                        *(__half2*)(g_Kf + (size_t)rr * 512 + col) =
                            __halves2half2(__float2half(f0), __float2half(f1));
                    } else {
                        __half h0 = __float2half(f0), h1 = __float2half(f1);
                        *(__half2*)(g_Vh + (size_t)rr * 512 + col - 512) =
                            __halves2half2(h0, h1);
                        *(__half2*)(g_Vl + (size_t)rr * 512 + col - 512) =
                            __halves2half2(
                                __float2half(f0 - __half2float(h0)),
                                __float2half(f1 - __half2float(h1)));
                    }
                }
            } else {
                float b0 = 0.f, b1 = 0.f;
                if (hasBias) { b0 = bias[col]; b1 = bias[col + 1]; }
                float* p = Cd + (size_t)r0 * ldC + col;
                p[0] = acc[mt][nt][0] + b0;
                p[1] = acc[mt][nt][1] + b1;
                float* q = p + 8 * ldC;
                q[0] = acc[mt][nt][2] + b0;
                q[1] = acc[mt][nt][3] + b1;
            }
        }
    }
}

// ---------------------------------------------------------------------------
// Fused prep: x fp32->fp16 (vectorized), convW fp32->fp16 native layout,
// and the three small weight transposes. One launch.
// blocks [0,8192): x ; [8192,16384): convW ; [16384,16384+1024): transposes.
// ---------------------------------------------------------------------------
__global__ __launch_bounds__(256) void prep_kernel(
    const float* __restrict__ x, const float* __restrict__ convw,
    const float* __restrict__ Wq, const float* __restrict__ Wkv,
    const float* __restrict__ Wp)
{
    int blk = blockIdx.x;
    int tid = threadIdx.x;

    if (blk < 16384) {
        // streaming fp32 -> fp16 convert, 8 elems per thread
        const float* src = (blk < 8192) ? x : convw;
        __half* dst = (blk < 8192) ? g_xf : g_Wcf;
        size_t base = ((size_t)(blk & 8191) * 256 + tid) * 8;
        float4 a = *(const float4*)(src + base);
        float4 b = *(const float4*)(src + base + 4);
        __half2 h[4];
        h[0] = __halves2half2(__float2half(a.x), __float2half(a.y));
        h[1] = __halves2half2(__float2half(a.z), __float2half(a.w));
        h[2] = __halves2half2(__float2half(b.x), __float2half(b.y));
        h[3] = __halves2half2(__float2half(b.z), __float2half(b.w));
        *(uint4*)(dst + base) = *(uint4*)h;
        return;
    }

    // transposes: W[K][N] -> Wt[n][k]
    int t = blk - 16384;
    const float* W;
    __half* Th;
    int K, N, n0, k0, perm;
    if (t < 256) {
        W = Wq; Th = g_Wqt; K = 512; N = 512; perm = 1;
        n0 = (t & 15) * 32; k0 = (t >> 4) * 32;
    } else if (t < 768) {
        int tt = t - 256;
        W = Wkv; Th = g_Wkvt; K = 512; N = 1024; perm = 0;
        n0 = (tt & 31) * 32; k0 = (tt >> 5) * 32;
    } else {
        int tt = t - 768;
        W = Wp; Th = g_Wpt; K = 512; N = 512; perm = 0;
        n0 = (tt & 15) * 32; k0 = (tt >> 4) * 32;
    }
    __shared__ float tbuf[32][33];
    int tx = tid & 31, ty = tid >> 5;
#pragma unroll
    for (int i = 0; i < 4; i++)
        tbuf[ty + 8 * i][tx] = W[(size_t)(k0 + ty + 8 * i) * N + n0 + tx];
    __syncthreads();
#pragma unroll
    for (int i = 0; i < 4; i++) {
        int n = n0 + ty + 8 * i;
        int np = perm ? ((n & 7) * 64 + (n >> 3)) : n;
        Th[(size_t)np * K + k0 + tx] = __float2half(tbuf[tx][ty + 8 * i]);
    }
}

// ---------------------------------------------------------------------------
// Split-K reduce + LayerNorm -> fp16 F
// ---------------------------------------------------------------------------
__inline__ __device__ float warpsum(float v) {
#pragma unroll
    for (int o = 16; o > 0; o >>= 1) v += __shfl_down_sync(0xffffffffu, v, o);
    return v;
}

__global__ __launch_bounds__(256) void reduce_ln(
    const float* __restrict__ gamma, const float* __restrict__ beta)
{
    int row = blockIdx.x;
    int tid = threadIdx.x;
    int c0 = tid, c1 = tid + 256;

    float v0 = 0.f, v1 = 0.f;
    for (int pz = 0; pz < SPLITK; pz++) {
        size_t base = (size_t)pz * MROWS * C_ + (size_t)row * C_;
        v0 += g_part[base + c0];
        v1 += g_part[base + c1];
    }
    float sum = v0 + v1;
    float sq = v0 * v0 + v1 * v1;

    __shared__ float ssum[8], ssq[8];
    __shared__ float s_mean, s_inv;
    float ws = warpsum(sum);
    float wq = warpsum(sq);
    int lane = tid & 31, wid = tid >> 5;
    if (lane == 0) { ssum[wid] = ws; ssq[wid] = wq; }
    __syncthreads();
    if (tid == 0) {
        float S = 0.f, Q = 0.f;
#pragma unroll
        for (int i = 0; i < 8; i++) { S += ssum[i]; Q += ssq[i]; }
        float mean = S * (1.0f / C_);
        float var = Q * (1.0f / C_) - mean * mean;
        s_mean = mean;
        s_inv = rsqrtf(var + EPS);
    }
    __syncthreads();
    float mean = s_mean, inv = s_inv;
    g_Ff[(size_t)row * C_ + c0] =
        __float2half((v0 - mean) * inv * gamma[c0] + beta[c0]);
    g_Ff[(size_t)row * C_ + c1] =
        __float2half((v1 - mean) * inv * gamma[c1] + beta[c1]);
}

// ---------------------------------------------------------------------------
// MMA attention. Block = (b*8+nh, qtile of 128). 256 threads / 8 warps.
// S = Q@Kh^T ; softmax ; O = Ph@(Vh+Vl).
// ---------------------------------------------------------------------------
#define AROWB 144
#define AQ  0
#define AKH 18432
#define AVH 27648
#define AVL 36864

__global__ __launch_bounds__(256) void attn_mma()
{
    __shared__ __align__(16) char asm_[46080];
    uint32_t sb = smem_u32(asm_);
    int tid = threadIdx.x, lane = tid & 31, wid = tid >> 5;
    int b = blockIdx.x >> 3, nh = blockIdx.x & 7;
    int n0 = blockIdx.y * 128;

    for (int idx = tid; idx < 1024; idx += 256) {
        int r = idx >> 3, s = idx & 7;
        *(uint4*)(asm_ + AQ + r * AROWB + s * 16) =
            *(const uint4*)(g_Qh + ((size_t)(b * 4096 + n0 + r)) * 512
                            + nh * 64 + s * 8);
    }
    for (int idx = tid; idx < 512; idx += 256) {
        int r = idx >> 3, s = idx & 7;
        size_t off = ((size_t)(b * 64 + r)) * 512 + nh * 64 + s * 8;
        uint32_t so = r * AROWB + s * 16;
        *(uint4*)(asm_ + AKH + so) = *(const uint4*)(g_Kf + off);
        *(uint4*)(asm_ + AVH + so) = *(const uint4*)(g_Vh + off);
        *(uint4*)(asm_ + AVL + so) = *(const uint4*)(g_Vl + off);
    }
    __syncthreads();

    int mat = lane >> 3;
    int arow = ((mat & 1) << 3) + (lane & 7);
    int brow = ((mat >> 1) << 3) + (lane & 7);

    float sacc[8][4];
#pragma unroll
    for (int i = 0; i < 8; i++)
#pragma unroll
        for (int j = 0; j < 4; j++) sacc[i][j] = 0.f;

#pragma unroll
    for (int kk = 0; kk < 4; kk++) {
        int akcol = kk * 16 + ((mat >> 1) << 3);
        int bkcol = kk * 16 + ((mat & 1) << 3);
        uint32_t a[4];
        ldm_x4(a, sb + AQ + (uint32_t)(wid * 16 + arow) * AROWB + akcol * 2);
#pragma unroll
        for (int ng = 0; ng < 4; ng++) {
            uint32_t bh[4];
            ldm_x4(bh, sb + AKH + (uint32_t)(ng * 16 + brow) * AROWB + bkcol * 2);
            mma16816(sacc[2 * ng],     a, bh);
            mma16816(sacc[2 * ng + 1], a, bh + 2);
        }
    }

    float mx0 = -1e30f, mx1 = -1e30f;
#pragma unroll
    for (int nt = 0; nt < 8; nt++) {
#pragma unroll
        for (int j = 0; j < 4; j++) sacc[nt][j] *= 0.125f;
        mx0 = fmaxf(mx0, fmaxf(sacc[nt][0], sacc[nt][1]));
        mx1 = fmaxf(mx1, fmaxf(sacc[nt][2], sacc[nt][3]));
    }
    mx0 = fmaxf(mx0, __shfl_xor_sync(0xffffffffu, mx0, 1));
    mx0 = fmaxf(mx0, __shfl_xor_sync(0xffffffffu, mx0, 2));
    mx1 = fmaxf(mx1, __shfl_xor_sync(0xffffffffu, mx1, 1));
    mx1 = fmaxf(mx1, __shfl_xor_sync(0xffffffffu, mx1, 2));
    float sum0 = 0.f, sum1 = 0.f;
#pragma unroll
    for (int nt = 0; nt < 8; nt++) {
        sacc[nt][0] = __expf(sacc[nt][0] - mx0);
        sacc[nt][1] = __expf(sacc[nt][1] - mx0);
        sacc[nt][2] = __expf(sacc[nt][2] - mx1);
        sacc[nt][3] = __expf(sacc[nt][3] - mx1);
        sum0 += sacc[nt][0] + sacc[nt][1];
        sum1 += sacc[nt][2] + sacc[nt][3];
    }
    sum0 += __shfl_xor_sync(0xffffffffu, sum0, 1);
    sum0 += __shfl_xor_sync(0xffffffffu, sum0, 2);
    sum1 += __shfl_xor_sync(0xffffffffu, sum1, 1);
    sum1 += __shfl_xor_sync(0xffffffffu, sum1, 2);
    float inv0 = 1.f / sum0, inv1 = 1.f / sum1;

    float oacc[8][4];
#pragma unroll
    for (int i = 0; i < 8; i++)
#pragma unroll
        for (int j = 0; j < 4; j++) oacc[i][j] = 0.f;

#pragma unroll
    for (int kt = 0; kt < 4; kt++) {
        uint32_t ah[4];
#pragma unroll
        for (int f = 0; f < 4; f++) {
            int ti = 2 * kt + (f >> 1);
            int j0 = (f & 1) * 2;
            __half2 hh = __halves2half2(__float2half(sacc[ti][j0]),
                                        __float2half(sacc[ti][j0 + 1]));
            ah[f] = *(uint32_t*)&hh;
        }
        int vrow = kt * 16 + ((lane >> 3) & 1) * 8 + (lane & 7);
        int vcol = (lane >> 4) * 8;
#pragma unroll
        for (int ng = 0; ng < 4; ng++) {
            uint32_t bh[4], bl[4];
            uint32_t ba = sb + (uint32_t)vrow * AROWB + (ng * 16 + vcol) * 2;
            ldm_x4t(bh, ba + AVH);
            ldm_x4t(bl, ba + AVL);
            mma16816(oacc[2 * ng],     ah, bh);
            mma16816(oacc[2 * ng + 1], ah, bh + 2);
            mma16816(oacc[2 * ng],     ah, bl);
            mma16816(oacc[2 * ng + 1], ah, bl + 2);
        }
    }

    int r0 = n0 + wid * 16 + (lane >> 2);
#pragma unroll
    for (int nt = 0; nt < 8; nt++) {
        int col = nh * 64 + nt * 8 + (lane & 3) * 2;
        __half2 v0 = __halves2half2(__float2half(oacc[nt][0] * inv0),
                                    __float2half(oacc[nt][1] * inv0));
        __half2 v1 = __halves2half2(__float2half(oacc[nt][2] * inv1),
                                    __float2half(oacc[nt][3] * inv1));
        *(__half2*)(g_AOf + ((size_t)(b * 4096 + r0)) * 512 + col) = v0;
        *(__half2*)(g_AOf + ((size_t)(b * 4096 + r0 + 8)) * 512 + col) = v1;
    }
}

// ---------------------------------------------------------------------------
// Host launcher
// ---------------------------------------------------------------------------
extern "C" void kernel_launch(void* const* d_in, const int* in_sizes, int n_in,
                              void* d_out, int out_size)
{
    const float* x     = (const float*)d_in[0];
    const float* Wq    = (const float*)d_in[1];
    const float* Wkv   = (const float*)d_in[2];
    const float* convw = (const float*)d_in[3];
    const float* gamma = (const float*)d_in[4];
    const float* beta  = (const float*)d_in[5];
    const float* Wp    = (const float*)d_in[6];
    const float* bp    = (const float*)d_in[7];
    float* out = (float*)d_out;

    cudaFuncSetAttribute(mgemm<0>, cudaFuncAttributeMaxDynamicSharedMemorySize,
                         MG_SMEM);
    cudaFuncSetAttribute(mgemm<1>, cudaFuncAttributeMaxDynamicSharedMemorySize,
                         MG_SMEM);

    // fused conversions + transposes (one launch)
    prep_kernel<<<16384 + 1024, 256>>>(x, convw, Wq, Wkv, Wp);

    // Q = x @ Wq  -> head-major fp16 g_Qh
    mgemm<0><<<dim3(4, 256, 1), 256, MG_SMEM>>>(
        ASEL_X, BSEL_WQT, DSEL_QH, 512, 512, 512, nullptr, nullptr, 0, 0);
    // conv as gathered GEMM (native-layout B), split-K=16 -> g_part
    mgemm<1><<<dim3(4, 4, SPLITK), 256, MG_SMEM>>>(
        ASEL_X, BSEL_WCF, DSEL_PART, KCONV, KCHUNK, 512, nullptr, nullptr, 0, 1);
    // reduce + LN -> Ff
    reduce_ln<<<MROWS, 256>>>(gamma, beta);
    // KV = F @ Wkv -> fp16 Kh / Vh / Vl directly
    mgemm<0><<<dim3(8, 4, 1), 256, MG_SMEM>>>(
        ASEL_F, BSEL_WKVT, DSEL_KV, 512, 512, 1024, nullptr, nullptr, 0, 0);
    // attention (MMA) -> AOf
    attn_mma<<<dim3(64, 32), 256>>>();
    // out = AO @ Wp + bp
    mgemm<0><<<dim3(4, 256, 1), 256, MG_SMEM>>>(
        ASEL_AO, BSEL_WPT, DSEL_EXT, 512, 512, 512, out, bp, 1, 0);
}

// round 9
// speedup vs baseline: 6.5163x; 1.0297x over previous
#include <cuda_runtime.h>
#include <cuda_fp16.h>
#include <math.h>
#include <cstdint>

// Problem constants
#define B_   8
#define N_   4096
#define C_   512
#define NH_  8
#define HD_  64
#define MROWS 512
#define KCONV 32768
#define SPLITK 16
#define KCHUNK (KCONV/SPLITK)  // 2048
#define EPS 1e-3f

// ---------------------------------------------------------------------------
// Device global scratch
// ---------------------------------------------------------------------------
__device__ __half g_Qh[B_*N_*C_];               // head-major fp16 Q: col = nh*64+hd
__device__ float g_part[SPLITK*MROWS*C_];       // conv split-K partials (16MB)
__device__ __half g_Kf[MROWS*C_];               // K fp16 (head-major cols)
__device__ __half g_Vf[MROWS*C_];               // V fp16
__device__ __half g_xf[B_*N_*C_];               // x fp16
__device__ __half g_Ff[MROWS*C_];               // LN out fp16
__device__ __half g_AOf[B_*N_*C_];              // attention out fp16
__device__ __half g_Wqt[C_*C_];                 // Wq^T, rows permuted head-major
__device__ __half g_Wkvt[2*C_*C_];              // Wkv^T
__device__ __half g_Wcf[KCONV*C_];              // convW fp16, NATIVE [K][N] layout
__device__ __half g_Wpt[C_*C_];                 // Wp^T

// selectors
#define ASEL_X  0
#define ASEL_F  1
#define ASEL_AO 2
#define BSEL_WQT  0
#define BSEL_WKVT 1
#define BSEL_WCF  2
#define BSEL_WPT  3
#define DSEL_QH   0
#define DSEL_PART 1
#define DSEL_KV   2
#define DSEL_EXT  3

// ---------------------------------------------------------------------------
// PTX helpers (sm_80-baseline; valid on compute_103 virtual arch)
// ---------------------------------------------------------------------------
__device__ __forceinline__ uint32_t smem_u32(const void* p) {
    uint32_t a;
    asm("{ .reg .u64 t; cvta.to.shared.u64 t, %1; cvt.u32.u64 %0, t; }"
        : "=r"(a) : "l"(p));
    return a;
}
__device__ __forceinline__ void ldm_x4(uint32_t* r, uint32_t addr) {
    asm volatile("ldmatrix.sync.aligned.m8n8.x4.shared.b16 {%0,%1,%2,%3}, [%4];"
        : "=r"(r[0]), "=r"(r[1]), "=r"(r[2]), "=r"(r[3]) : "r"(addr));
}
__device__ __forceinline__ void ldm_x4t(uint32_t* r, uint32_t addr) {
    asm volatile("ldmatrix.sync.aligned.m8n8.x4.trans.shared.b16 {%0,%1,%2,%3}, [%4];"
        : "=r"(r[0]), "=r"(r[1]), "=r"(r[2]), "=r"(r[3]) : "r"(addr));
}
__device__ __forceinline__ void mma16816(float* c, const uint32_t* a,
                                         const uint32_t* b) {
    asm volatile("mma.sync.aligned.m16n8k16.row.col.f32.f16.f16.f32 "
        "{%0,%1,%2,%3},{%4,%5,%6,%7},{%8,%9},{%0,%1,%2,%3};"
        : "+f"(c[0]), "+f"(c[1]), "+f"(c[2]), "+f"(c[3])
        : "r"(a[0]), "r"(a[1]), "r"(a[2]), "r"(a[3]), "r"(b[0]), "r"(b[1]));
}
__device__ __forceinline__ void cpa16(uint32_t d, const void* s) {
    asm volatile("cp.async.cg.shared.global [%0], [%1], 16;" :: "r"(d), "l"(s));
}
#define CPA_COMMIT() asm volatile("cp.async.commit_group;" ::: "memory")
#define CPA_WAIT2()  asm volatile("cp.async.wait_group 2;" ::: "memory")

// mgemm smem: per stage A 128x40 halves (80B rows, conflict-free) | B region.
// Non-trans B: 128x40 halves like A. Trans B: 32 rows x 272B (17-slot rows,
// (17r+s)%8 permutation -> conflict-free trans ldmatrix).
#define ROWB  80
#define OFF_B 10240
#define BTROWB 272
#define STG   20480
#define NSTAGE 4
#define MG_SMEM (NSTAGE*STG)   // 81920 (dynamic)

// ---------------------------------------------------------------------------
// fp16 tensor-core GEMM. BT=0: C = A @ Bt^T (Bt stored [N][K]).
//                        BT=1: C = A @ B    (B  stored [K][N], N=512).
// Tile 128x128, BK=32, 256 threads, 4-stage cp.async, 1 sync/iter.
// ---------------------------------------------------------------------------
template<int BT>
__global__ __launch_bounds__(256, 2) void mgemm(
    int aSel, int bSel, int dSel,
    int Kfull, int kcount, int ldC,
    float* __restrict__ extC, const float* __restrict__ bias,
    int hasBias, int aGather)
{
    extern __shared__ __align__(16) char smem[];
    uint32_t sb = smem_u32(smem);
    int tid = threadIdx.x, lane = tid & 31, wid = tid >> 5;
    int rowBase = blockIdx.y * 128, colBase = blockIdx.x * 128;
    int kbase = blockIdx.z * kcount;

    const __half *A, *B;
    switch (aSel) {
        case ASEL_X: A = g_xf;  break;
        case ASEL_F: A = g_Ff;  break;
        default:     A = g_AOf; break;
    }
    switch (bSel) {
        case BSEL_WQT:  B = g_Wqt;  break;
        case BSEL_WKVT: B = g_Wkvt; break;
        case BSEL_WCF:  B = g_Wcf;  break;
        default:        B = g_Wpt;  break;
    }
    float* Cd;
    switch (dSel) {
        case DSEL_PART: Cd = g_part + (size_t)blockIdx.z * (MROWS * C_); break;
        default:        Cd = extC; break;
    }

    int m0 = (wid >> 2) * 64;
    int n0 = (wid & 3) * 32;

    float acc[4][4][4];
#pragma unroll
    for (int a = 0; a < 4; a++)
#pragma unroll
        for (int b = 0; b < 4; b++)
#pragma unroll
            for (int c = 0; c < 4; c++) acc[a][b][c] = 0.f;

    int iters = kcount >> 5;

    auto issue = [&](int i) {
        int k0 = kbase + i * 32;
        uint32_t so = sb + (uint32_t)(i & (NSTAGE - 1)) * STG;
#pragma unroll
        for (int j = 0; j < 2; j++) {
            int c = tid + j * 256;
            int r = c >> 2, s = c & 3;
            size_t off;
            if (aGather) {
                int rg = rowBase + r;
                int bb = rg >> 6;
                int p = rg & 63;
                int pix = k0 >> 9;     // constant across the 32-wide slab
                int pixel = bb * 4096 + (p >> 3) * 512 + (p & 7) * 8
                          + (pix >> 3) * 64 + (pix & 7);
                off = (size_t)pixel * 512 + (k0 & 511) + s * 8;
            } else {
                off = (size_t)(rowBase + r) * Kfull + k0 + s * 8;
            }
            cpa16(so + r * ROWB + s * 16, A + off);
        }
        if (BT) {
            // B [K][N] native: 32 rows x 256B
#pragma unroll
            for (int j = 0; j < 2; j++) {
                int c = tid + j * 256;
                int r = c >> 4, s = c & 15;
                cpa16(so + OFF_B + r * BTROWB + s * 16,
                      B + (size_t)(k0 + r) * 512 + colBase + s * 8);
            }
        } else {
#pragma unroll
            for (int j = 0; j < 2; j++) {
                int c = tid + j * 256;
                int r = c >> 2, s = c & 3;
                cpa16(so + OFF_B + r * ROWB + s * 16,
                      B + (size_t)(colBase + r) * Kfull + k0 + s * 8);
            }
        }
        CPA_COMMIT();
    };

    int mat = lane >> 3;
    int arow_off = ((mat & 1) << 3) + (lane & 7);
    int nrow_off = ((mat >> 1) << 3) + (lane & 7);
    int btrow_off = ((lane >> 3) & 1) * 8 + (lane & 7);
    int btcol_off = (lane >> 4) * 8;

    issue(0); issue(1); issue(2);   // iters >= 16 always

    for (int i = 0; i < iters; i++) {
        CPA_WAIT2();
        __syncthreads();
        if (i + 3 < iters) issue(i + 3);
        else CPA_COMMIT();          // empty group keeps wait_group arithmetic exact

        uint32_t base = sb + (uint32_t)(i & (NSTAGE - 1)) * STG;
#pragma unroll
        for (int kk = 0; kk < 2; kk++) {
            int akcol = kk * 16 + ((mat >> 1) << 3);
            uint32_t a_f[4][4], b_f[2][4];
#pragma unroll
            for (int mt = 0; mt < 4; mt++)
                ldm_x4(a_f[mt], base + (uint32_t)(m0 + mt * 16 + arow_off) * ROWB
                                 + akcol * 2);
            if (BT) {
                int vrow = kk * 16 + btrow_off;
#pragma unroll
                for (int np = 0; np < 2; np++)
                    ldm_x4t(b_f[np], base + OFF_B + (uint32_t)vrow * BTROWB
                                      + (n0 + np * 16 + btcol_off) * 2);
            } else {
                int bkcol = kk * 16 + ((mat & 1) << 3);
#pragma unroll
                for (int np = 0; np < 2; np++)
                    ldm_x4(b_f[np], base + OFF_B
                                     + (uint32_t)(n0 + np * 16 + nrow_off) * ROWB
                                     + bkcol * 2);
            }
#pragma unroll
            for (int mt = 0; mt < 4; mt++)
#pragma unroll
                for (int nt = 0; nt < 4; nt++)
                    mma16816(acc[mt][nt], a_f[mt], &b_f[nt >> 1][(nt & 1) * 2]);
        }
    }

    // epilogue
    int m0g = rowBase + m0, n0g = colBase + n0;
#pragma unroll
    for (int mt = 0; mt < 4; mt++) {
        int r0 = m0g + mt * 16 + (lane >> 2);
#pragma unroll
        for (int nt = 0; nt < 4; nt++) {
            int col = n0g + nt * 8 + (lane & 3) * 2;
            if (dSel == DSEL_QH) {
                __half2 v0 = __halves2half2(__float2half(acc[mt][nt][0]),
                                            __float2half(acc[mt][nt][1]));
                __half2 v1 = __halves2half2(__float2half(acc[mt][nt][2]),
                                            __float2half(acc[mt][nt][3]));
                *(__half2*)(g_Qh + (size_t)r0 * ldC + col) = v0;
                *(__half2*)(g_Qh + (size_t)(r0 + 8) * ldC + col) = v1;
            } else if (dSel == DSEL_KV) {
#pragma unroll
                for (int half = 0; half < 2; half++) {
                    int rr = r0 + half * 8;
                    float f0 = acc[mt][nt][2 * half];
                    float f1 = acc[mt][nt][2 * half + 1];
                    __half2 hv = __halves2half2(__float2half(f0),
                                                __float2half(f1));
                    if (col < 512)
                        *(__half2*)(g_Kf + (size_t)rr * 512 + col) = hv;
                    else
                        *(__half2*)(g_Vf + (size_t)rr * 512 + col - 512) = hv;
                }
            } else {
                float b0 = 0.f, b1 = 0.f;
                if (hasBias) { b0 = bias[col]; b1 = bias[col + 1]; }
                float* p = Cd + (size_t)r0 * ldC + col;
                p[0] = acc[mt][nt][0] + b0;
                p[1] = acc[mt][nt][1] + b1;
                float* q = p + 8 * ldC;
                q[0] = acc[mt][nt][2] + b0;
                q[1] = acc[mt][nt][3] + b1;
            }
        }
    }
}

// ---------------------------------------------------------------------------
// Fused prep: x fp32->fp16, convW fp32->fp16 native layout (16 elems/thread),
// and the three small weight transposes. One launch.
// blocks [0,4096): x ; [4096,8192): convW ; [8192,8192+1024): transposes.
// ---------------------------------------------------------------------------
__global__ __launch_bounds__(256) void prep_kernel(
    const float* __restrict__ x, const float* __restrict__ convw,
    const float* __restrict__ Wq, const float* __restrict__ Wkv,
    const float* __restrict__ Wp)
{
    int blk = blockIdx.x;
    int tid = threadIdx.x;

    if (blk < 8192) {
        const float* src = (blk < 4096) ? x : convw;
        __half* dst = (blk < 4096) ? g_xf : g_Wcf;
        size_t base0 = (size_t)(blk & 4095) * 4096;
#pragma unroll
        for (int j = 0; j < 2; j++) {
            size_t base = base0 + (size_t)j * 2048 + (size_t)tid * 8;
            float4 a = *(const float4*)(src + base);
            float4 b = *(const float4*)(src + base + 4);
            __half2 h[4];
            h[0] = __halves2half2(__float2half(a.x), __float2half(a.y));
            h[1] = __halves2half2(__float2half(a.z), __float2half(a.w));
            h[2] = __halves2half2(__float2half(b.x), __float2half(b.y));
            h[3] = __halves2half2(__float2half(b.z), __float2half(b.w));
            *(uint4*)(dst + base) = *(uint4*)h;
        }
        return;
    }

    // transposes: W[K][N] -> Wt[n][k]
    int t = blk - 8192;
    const float* W;
    __half* Th;
    int K, N, n0, k0, perm;
    if (t < 256) {
        W = Wq; Th = g_Wqt; K = 512; N = 512; perm = 1;
        n0 = (t & 15) * 32; k0 = (t >> 4) * 32;
    } else if (t < 768) {
        int tt = t - 256;
        W = Wkv; Th = g_Wkvt; K = 512; N = 1024; perm = 0;
        n0 = (tt & 31) * 32; k0 = (tt >> 5) * 32;
    } else {
        int tt = t - 768;
        W = Wp; Th = g_Wpt; K = 512; N = 512; perm = 0;
        n0 = (tt & 15) * 32; k0 = (tt >> 4) * 32;
    }
    __shared__ float tbuf[32][33];
    int tx = tid & 31, ty = tid >> 5;
#pragma unroll
    for (int i = 0; i < 4; i++)
        tbuf[ty + 8 * i][tx] = W[(size_t)(k0 + ty + 8 * i) * N + n0 + tx];
    __syncthreads();
#pragma unroll
    for (int i = 0; i < 4; i++) {
        int n = n0 + ty + 8 * i;
        int np = perm ? ((n & 7) * 64 + (n >> 3)) : n;
        Th[(size_t)np * K + k0 + tx] = __float2half(tbuf[tx][ty + 8 * i]);
    }
}

// ---------------------------------------------------------------------------
// Split-K reduce + LayerNorm -> fp16 F. 512 threads, one column each.
// ---------------------------------------------------------------------------
__global__ __launch_bounds__(512) void reduce_ln(
    const float* __restrict__ gamma, const float* __restrict__ beta)
{
    int row = blockIdx.x;
    int tid = threadIdx.x;   // 0..511 = column

    float v = 0.f;
#pragma unroll
    for (int pz = 0; pz < SPLITK; pz++)
        v += g_part[(size_t)pz * MROWS * C_ + (size_t)row * C_ + tid];

    float sum = v, sq = v * v;
    __shared__ float ssum[16], ssq[16];
    __shared__ float s_mean, s_inv;
#pragma unroll
    for (int o = 16; o > 0; o >>= 1) {
        sum += __shfl_down_sync(0xffffffffu, sum, o);
        sq  += __shfl_down_sync(0xffffffffu, sq, o);
    }
    int lane = tid & 31, wid = tid >> 5;
    if (lane == 0) { ssum[wid] = sum; ssq[wid] = sq; }
    __syncthreads();
    if (tid == 0) {
        float S = 0.f, Q = 0.f;
#pragma unroll
        for (int i = 0; i < 16; i++) { S += ssum[i]; Q += ssq[i]; }
        float mean = S * (1.0f / C_);
        float var = Q * (1.0f / C_) - mean * mean;
        s_mean = mean;
        s_inv = rsqrtf(var + EPS);
    }
    __syncthreads();
    g_Ff[(size_t)row * C_ + tid] =
        __float2half((v - s_mean) * s_inv * gamma[tid] + beta[tid]);
}

// ---------------------------------------------------------------------------
// MMA attention. Block = (b*8+nh, qtile of 128). 256 threads / 8 warps.
// S = Q@Kh^T ; softmax ; O = Ph@Vh (single-term V).
// Smem rows padded to 144B (stride 9 slots -> conflict-free ldmatrix).
// ---------------------------------------------------------------------------
#define AROWB 144
#define AQ  0
#define AKH 18432
#define AVH 27648

__global__ __launch_bounds__(256) void attn_mma()
{
    __shared__ __align__(16) char asm_[36864];
    uint32_t sb = smem_u32(asm_);
    int tid = threadIdx.x, lane = tid & 31, wid = tid >> 5;
    int b = blockIdx.x >> 3, nh = blockIdx.x & 7;
    int n0 = blockIdx.y * 128;

    for (int idx = tid; idx < 1024; idx += 256) {
        int r = idx >> 3, s = idx & 7;
        *(uint4*)(asm_ + AQ + r * AROWB + s * 16) =
            *(const uint4*)(g_Qh + ((size_t)(b * 4096 + n0 + r)) * 512
                            + nh * 64 + s * 8);
    }
    for (int idx = tid; idx < 512; idx += 256) {
        int r = idx >> 3, s = idx & 7;
        size_t off = ((size_t)(b * 64 + r)) * 512 + nh * 64 + s * 8;
        uint32_t so = r * AROWB + s * 16;
        *(uint4*)(asm_ + AKH + so) = *(const uint4*)(g_Kf + off);
        *(uint4*)(asm_ + AVH + so) = *(const uint4*)(g_Vf + off);
    }
    __syncthreads();

    int mat = lane >> 3;
    int arow = ((mat & 1) << 3) + (lane & 7);
    int brow = ((mat >> 1) << 3) + (lane & 7);

    float sacc[8][4];
#pragma unroll
    for (int i = 0; i < 8; i++)
#pragma unroll
        for (int j = 0; j < 4; j++) sacc[i][j] = 0.f;

#pragma unroll
    for (int kk = 0; kk < 4; kk++) {
        int akcol = kk * 16 + ((mat >> 1) << 3);
        int bkcol = kk * 16 + ((mat & 1) << 3);
        uint32_t a[4];
        ldm_x4(a, sb + AQ + (uint32_t)(wid * 16 + arow) * AROWB + akcol * 2);
#pragma unroll
        for (int ng = 0; ng < 4; ng++) {
            uint32_t bh[4];
            ldm_x4(bh, sb + AKH + (uint32_t)(ng * 16 + brow) * AROWB + bkcol * 2);
            mma16816(sacc[2 * ng],     a, bh);
            mma16816(sacc[2 * ng + 1], a, bh + 2);
        }
    }

    float mx0 = -1e30f, mx1 = -1e30f;
#pragma unroll
    for (int nt = 0; nt < 8; nt++) {
#pragma unroll
        for (int j = 0; j < 4; j++) sacc[nt][j] *= 0.125f;
        mx0 = fmaxf(mx0, fmaxf(sacc[nt][0], sacc[nt][1]));
        mx1 = fmaxf(mx1, fmaxf(sacc[nt][2], sacc[nt][3]));
    }
    mx0 = fmaxf(mx0, __shfl_xor_sync(0xffffffffu, mx0, 1));
    mx0 = fmaxf(mx0, __shfl_xor_sync(0xffffffffu, mx0, 2));
    mx1 = fmaxf(mx1, __shfl_xor_sync(0xffffffffu, mx1, 1));
    mx1 = fmaxf(mx1, __shfl_xor_sync(0xffffffffu, mx1, 2));
    float sum0 = 0.f, sum1 = 0.f;
#pragma unroll
    for (int nt = 0; nt < 8; nt++) {
        sacc[nt][0] = __expf(sacc[nt][0] - mx0);
        sacc[nt][1] = __expf(sacc[nt][1] - mx0);
        sacc[nt][2] = __expf(sacc[nt][2] - mx1);
        sacc[nt][3] = __expf(sacc[nt][3] - mx1);
        sum0 += sacc[nt][0] + sacc[nt][1];
        sum1 += sacc[nt][2] + sacc[nt][3];
    }
    sum0 += __shfl_xor_sync(0xffffffffu, sum0, 1);
    sum0 += __shfl_xor_sync(0xffffffffu, sum0, 2);
    sum1 += __shfl_xor_sync(0xffffffffu, sum1, 1);
    sum1 += __shfl_xor_sync(0xffffffffu, sum1, 2);
    float inv0 = 1.f / sum0, inv1 = 1.f / sum1;

    float oacc[8][4];
#pragma unroll
    for (int i = 0; i < 8; i++)
#pragma unroll
        for (int j = 0; j < 4; j++) oacc[i][j] = 0.f;

#pragma unroll
    for (int kt = 0; kt < 4; kt++) {
        uint32_t ah[4];
#pragma unroll
        for (int f = 0; f < 4; f++) {
            int ti = 2 * kt + (f >> 1);
            int j0 = (f & 1) * 2;
            __half2 hh = __halves2half2(__float2half(sacc[ti][j0]),
                                        __float2half(sacc[ti][j0 + 1]));
            ah[f] = *(uint32_t*)&hh;
        }
        int vrow = kt * 16 + ((lane >> 3) & 1) * 8 + (lane & 7);
        int vcol = (lane >> 4) * 8;
#pragma unroll
        for (int ng = 0; ng < 4; ng++) {
            uint32_t bh[4];
            ldm_x4t(bh, sb + AVH + (uint32_t)vrow * AROWB
                         + (ng * 16 + vcol) * 2);
            mma16816(oacc[2 * ng],     ah, bh);
            mma16816(oacc[2 * ng + 1], ah, bh + 2);
        }
    }

    int r0 = n0 + wid * 16 + (lane >> 2);
#pragma unroll
    for (int nt = 0; nt < 8; nt++) {
        int col = nh * 64 + nt * 8 + (lane & 3) * 2;
        __half2 v0 = __halves2half2(__float2half(oacc[nt][0] * inv0),
                                    __float2half(oacc[nt][1] * inv0));
        __half2 v1 = __halves2half2(__float2half(oacc[nt][2] * inv1),
                                    __float2half(oacc[nt][3] * inv1));
        *(__half2*)(g_AOf + ((size_t)(b * 4096 + r0)) * 512 + col) = v0;
        *(__half2*)(g_AOf + ((size_t)(b * 4096 + r0 + 8)) * 512 + col) = v1;
    }
}

// ---------------------------------------------------------------------------
// Host launcher
// ---------------------------------------------------------------------------
extern "C" void kernel_launch(void* const* d_in, const int* in_sizes, int n_in,
                              void* d_out, int out_size)
{
    const float* x     = (const float*)d_in[0];
    const float* Wq    = (const float*)d_in[1];
    const float* Wkv   = (const float*)d_in[2];
    const float* convw = (const float*)d_in[3];
    const float* gamma = (const float*)d_in[4];
    const float* beta  = (const float*)d_in[5];
    const float* Wp    = (const float*)d_in[6];
    const float* bp    = (const float*)d_in[7];
    float* out = (float*)d_out;

    cudaFuncSetAttribute(mgemm<0>, cudaFuncAttributeMaxDynamicSharedMemorySize,
                         MG_SMEM);
    cudaFuncSetAttribute(mgemm<1>, cudaFuncAttributeMaxDynamicSharedMemorySize,
                         MG_SMEM);

    // fused conversions + transposes (one launch)
    prep_kernel<<<8192 + 1024, 256>>>(x, convw, Wq, Wkv, Wp);

    // Q = x @ Wq  -> head-major fp16 g_Qh
    mgemm<0><<<dim3(4, 256, 1), 256, MG_SMEM>>>(
        ASEL_X, BSEL_WQT, DSEL_QH, 512, 512, 512, nullptr, nullptr, 0, 0);
    // conv as gathered GEMM (native-layout B), split-K=16 -> g_part
    mgemm<1><<<dim3(4, 4, SPLITK), 256, MG_SMEM>>>(
        ASEL_X, BSEL_WCF, DSEL_PART, KCONV, KCHUNK, 512, nullptr, nullptr, 0, 1);
    // reduce + LN -> Ff
    reduce_ln<<<MROWS, 512>>>(gamma, beta);
    // KV = F @ Wkv -> fp16 Kf / Vf directly
    mgemm<0><<<dim3(8, 4, 1), 256, MG_SMEM>>>(
        ASEL_F, BSEL_WKVT, DSEL_KV, 512, 512, 1024, nullptr, nullptr, 0, 0);
    // attention (MMA) -> AOf
    attn_mma<<<dim3(64, 32), 256>>>();
    // out = AO @ Wp + bp
    mgemm<0><<<dim3(4, 256, 1), 256, MG_SMEM>>>(
        ASEL_AO, BSEL_WPT, DSEL_EXT, 512, 512, 512, out, bp, 1, 0);
}

// round 13
// speedup vs baseline: 7.0536x; 1.0825x over previous
#include <cuda_runtime.h>
#include <cuda_fp16.h>
#include <math.h>
#include <cstdint>

// Problem constants
#define B_   8
#define N_   4096
#define C_   512
#define NH_  8
#define HD_  64
#define MROWS 512
#define KCONV 32768
#define SPLITK 16
#define KCHUNK (KCONV/SPLITK)  // 2048
#define EPS 1e-3f

// ---------------------------------------------------------------------------
// Device global scratch (referenced ONLY from device code)
// ---------------------------------------------------------------------------
__device__ __half g_Qh[B_*N_*C_];               // head-major fp16 Q: col = nh*64+hd
__device__ float g_part[SPLITK*MROWS*C_];       // conv split-K partials (16MB)
__device__ __half g_Kf[MROWS*C_];               // K fp16 (head-major cols)
__device__ __half g_Vf[MROWS*C_];               // V fp16
__device__ __half g_xf[B_*N_*C_];               // x fp16
__device__ __half g_Ff[MROWS*C_];               // LN out fp16
__device__ __half g_AOf[B_*N_*C_];              // attention out fp16
__device__ __half g_Wqt[C_*C_];                 // Wq^T, rows permuted head-major
__device__ __half g_Wkvt[2*C_*C_];              // Wkv^T
__device__ __half g_Wcf[KCONV*C_];              // convW fp16, NATIVE [K][N] layout
__device__ __half g_Wpt[C_*C_];                 // Wp^T

// selectors (resolved in device code only)
#define ASEL_F  1
#define ASEL_AO 2
#define BSEL_WKVT 1
#define BSEL_WPT  3
#define DSEL_QH   0
#define DSEL_KV   2
#define DSEL_EXT  3

// ---------------------------------------------------------------------------
// PTX helpers (sm_80-baseline; valid on compute_103 virtual arch)
// ---------------------------------------------------------------------------
__device__ __forceinline__ uint32_t smem_u32(const void* p) {
    uint32_t a;
    asm("{ .reg .u64 t; cvta.to.shared.u64 t, %1; cvt.u32.u64 %0, t; }"
        : "=r"(a) : "l"(p));
    return a;
}
__device__ __forceinline__ void ldm_x4(uint32_t* r, uint32_t addr) {
    asm volatile("ldmatrix.sync.aligned.m8n8.x4.shared.b16 {%0,%1,%2,%3}, [%4];"
        : "=r"(r[0]), "=r"(r[1]), "=r"(r[2]), "=r"(r[3]) : "r"(addr));
}
__device__ __forceinline__ void ldm_x4t(uint32_t* r, uint32_t addr) {
    asm volatile("ldmatrix.sync.aligned.m8n8.x4.trans.shared.b16 {%0,%1,%2,%3}, [%4];"
        : "=r"(r[0]), "=r"(r[1]), "=r"(r[2]), "=r"(r[3]) : "r"(addr));
}
__device__ __forceinline__ void mma16816(float* c, const uint32_t* a,
                                         const uint32_t* b) {
    asm volatile("mma.sync.aligned.m16n8k16.row.col.f32.f16.f16.f32 "
        "{%0,%1,%2,%3},{%4,%5,%6,%7},{%8,%9},{%0,%1,%2,%3};"
        : "+f"(c[0]), "+f"(c[1]), "+f"(c[2]), "+f"(c[3])
        : "r"(a[0]), "r"(a[1]), "r"(a[2]), "r"(a[3]), "r"(b[0]), "r"(b[1]));
}
__device__ __forceinline__ void cpa16(uint32_t d, const void* s) {
    asm volatile("cp.async.cg.shared.global [%0], [%1], 16;" :: "r"(d), "l"(s));
}
#define CPA_COMMIT() asm volatile("cp.async.commit_group;" ::: "memory")
#define CPA_WAIT2()  asm volatile("cp.async.wait_group 2;" ::: "memory")

// mgemm smem layout
#define ROWB  80
#define OFF_B 10240
#define BTROWB 272
#define STG   20480
#define NSTAGE 4
#define MG_SMEM (NSTAGE*STG)   // 81920 (dynamic)

// ---------------------------------------------------------------------------
// GEMM body. BT=0: C = A @ Bt^T (Bt [N][K]).  BT=1: C = A @ B (B [K][N], N=512).
// Tile 128x128, BK=32, 256 threads, 4-stage cp.async, 1 sync/iter.
// ---------------------------------------------------------------------------
template<int BT>
__device__ __forceinline__ void mgemm_body(
    const __half* __restrict__ A, const __half* __restrict__ B,
    int dSel, int Kfull, int iters, int kbase, int ldC,
    int rowBase, int colBase,
    float* __restrict__ Cd, const float* __restrict__ bias,
    int hasBias, int aGather, char* smem)
{
    uint32_t sb = smem_u32(smem);
    int tid = threadIdx.x, lane = tid & 31, wid = tid >> 5;

    int m0 = (wid >> 2) * 64;
    int n0 = (wid & 3) * 32;

    float acc[4][4][4];
#pragma unroll
    for (int a = 0; a < 4; a++)
#pragma unroll
        for (int b = 0; b < 4; b++)
#pragma unroll
            for (int c = 0; c < 4; c++) acc[a][b][c] = 0.f;

    auto issue = [&](int i) {
        int k0 = kbase + i * 32;
        uint32_t so = sb + (uint32_t)(i & (NSTAGE - 1)) * STG;
#pragma unroll
        for (int j = 0; j < 2; j++) {
            int c = tid + j * 256;
            int r = c >> 2, s = c & 3;
            size_t off;
            if (aGather) {
                int rg = rowBase + r;
                int bb = rg >> 6;
                int p = rg & 63;
                int pix = k0 >> 9;     // constant across the 32-wide slab
                int pixel = bb * 4096 + (p >> 3) * 512 + (p & 7) * 8
                          + (pix >> 3) * 64 + (pix & 7);
                off = (size_t)pixel * 512 + (k0 & 511) + s * 8;
            } else {
                off = (size_t)(rowBase + r) * Kfull + k0 + s * 8;
            }
            cpa16(so + r * ROWB + s * 16, A + off);
        }
        if (BT) {
#pragma unroll
            for (int j = 0; j < 2; j++) {
                int c = tid + j * 256;
                int r = c >> 4, s = c & 15;
                cpa16(so + OFF_B + r * BTROWB + s * 16,
                      B + (size_t)(k0 + r) * 512 + colBase + s * 8);
            }
        } else {
#pragma unroll
            for (int j = 0; j < 2; j++) {
                int c = tid + j * 256;
                int r = c >> 2, s = c & 3;
                cpa16(so + OFF_B + r * ROWB + s * 16,
                      B + (size_t)(colBase + r) * Kfull + k0 + s * 8);
            }
        }
        CPA_COMMIT();
    };

    int mat = lane >> 3;
    int arow_off = ((mat & 1) << 3) + (lane & 7);
    int nrow_off = ((mat >> 1) << 3) + (lane & 7);
    int btrow_off = ((lane >> 3) & 1) * 8 + (lane & 7);
    int btcol_off = (lane >> 4) * 8;

    issue(0); issue(1); issue(2);

    for (int i = 0; i < iters; i++) {
        CPA_WAIT2();
        __syncthreads();
        if (i + 3 < iters) issue(i + 3);
        else CPA_COMMIT();          // empty group keeps wait_group count exact

        uint32_t base = sb + (uint32_t)(i & (NSTAGE - 1)) * STG;
#pragma unroll
        for (int kk = 0; kk < 2; kk++) {
            int akcol = kk * 16 + ((mat >> 1) << 3);
            uint32_t a_f[4][4], b_f[2][4];
#pragma unroll
            for (int mt = 0; mt < 4; mt++)
                ldm_x4(a_f[mt], base + (uint32_t)(m0 + mt * 16 + arow_off) * ROWB
                                 + akcol * 2);
            if (BT) {
                int vrow = kk * 16 + btrow_off;
#pragma unroll
                for (int np = 0; np < 2; np++)
                    ldm_x4t(b_f[np], base + OFF_B + (uint32_t)vrow * BTROWB
                                      + (n0 + np * 16 + btcol_off) * 2);
            } else {
                int bkcol = kk * 16 + ((mat & 1) << 3);
#pragma unroll
                for (int np = 0; np < 2; np++)
                    ldm_x4(b_f[np], base + OFF_B
                                     + (uint32_t)(n0 + np * 16 + nrow_off) * ROWB
                                     + bkcol * 2);
            }
#pragma unroll
            for (int mt = 0; mt < 4; mt++)
#pragma unroll
                for (int nt = 0; nt < 4; nt++)
                    mma16816(acc[mt][nt], a_f[mt], &b_f[nt >> 1][(nt & 1) * 2]);
        }
    }

    // epilogue
    int m0g = rowBase + m0, n0g = colBase + n0;
#pragma unroll
    for (int mt = 0; mt < 4; mt++) {
        int r0 = m0g + mt * 16 + (lane >> 2);
#pragma unroll
        for (int nt = 0; nt < 4; nt++) {
            int col = n0g + nt * 8 + (lane & 3) * 2;
            if (dSel == DSEL_QH) {
                __half2 v0 = __halves2half2(__float2half(acc[mt][nt][0]),
                                            __float2half(acc[mt][nt][1]));
                __half2 v1 = __halves2half2(__float2half(acc[mt][nt][2]),
                                            __float2half(acc[mt][nt][3]));
                *(__half2*)(g_Qh + (size_t)r0 * ldC + col) = v0;
                *(__half2*)(g_Qh + (size_t)(r0 + 8) * ldC + col) = v1;
            } else if (dSel == DSEL_KV) {
#pragma unroll
                for (int half = 0; half < 2; half++) {
                    int rr = r0 + half * 8;
                    __half2 hv = __halves2half2(
                        __float2half(acc[mt][nt][2 * half]),
                        __float2half(acc[mt][nt][2 * half + 1]));
                    if (col < 512)
                        *(__half2*)(g_Kf + (size_t)rr * 512 + col) = hv;
                    else
                        *(__half2*)(g_Vf + (size_t)rr * 512 + col - 512) = hv;
                }
            } else {
                float b0 = 0.f, b1 = 0.f;
                if (hasBias) { b0 = bias[col]; b1 = bias[col + 1]; }
                float* p = Cd + (size_t)r0 * ldC + col;
                p[0] = acc[mt][nt][0] + b0;
                p[1] = acc[mt][nt][1] + b1;
                float* q = p + 8 * ldC;
                q[0] = acc[mt][nt][2] + b0;
                q[1] = acc[mt][nt][3] + b1;
            }
        }
    }
}

// Fused Q-projection + conv GEMM (independent; conv's long CTAs first).
__global__ __launch_bounds__(256, 2) void mgemm_qc()
{
    extern __shared__ __align__(16) char smem[];
    int bid = blockIdx.x;
    if (bid < 256) {
        int z = bid & 15, xy = bid >> 4;
        mgemm_body<1>(g_xf, g_Wcf, /*dSel=*/99, KCONV, KCHUNK / 32,
                      z * KCHUNK, 512, (xy >> 2) * 128, (xy & 3) * 128,
                      g_part + (size_t)z * (MROWS * C_), nullptr, 0, 1, smem);
    } else {
        int t = bid - 256;
        mgemm_body<0>(g_xf, g_Wqt, DSEL_QH, 512, 16, 0, 512,
                      (t >> 2) * 128, (t & 3) * 128,
                      nullptr, nullptr, 0, 0, smem);
    }
}

// Generic BT=0 GEMM (KV projection, out projection) — buffers resolved
// IN DEVICE CODE via selectors (never pass __device__ symbols from host!).
__global__ __launch_bounds__(256, 2) void mgemm_g(
    int aSel, int bSel, int dSel, int Kfull, int ldC,
    float* __restrict__ extC, const float* __restrict__ bias, int hasBias)
{
    extern __shared__ __align__(16) char smem[];
    const __half* A = (aSel == ASEL_F) ? g_Ff : g_AOf;
    const __half* B = (bSel == BSEL_WKVT) ? g_Wkvt : g_Wpt;
    mgemm_body<0>(A, B, dSel, Kfull, Kfull / 32, 0, ldC,
                  blockIdx.y * 128, blockIdx.x * 128,
                  extC, bias, hasBias, 0, smem);
}

// ---------------------------------------------------------------------------
// Fused prep: x fp32->fp16, convW fp32->fp16 native layout (16 elems/thread),
// and the three small weight transposes. One launch.
// ---------------------------------------------------------------------------
__global__ __launch_bounds__(256) void prep_kernel(
    const float* __restrict__ x, const float* __restrict__ convw,
    const float* __restrict__ Wq, const float* __restrict__ Wkv,
    const float* __restrict__ Wp)
{
    int blk = blockIdx.x;
    int tid = threadIdx.x;

    if (blk < 8192) {
        const float* src = (blk < 4096) ? x : convw;
        __half* dst = (blk < 4096) ? g_xf : g_Wcf;
        size_t base0 = (size_t)(blk & 4095) * 4096;
#pragma unroll
        for (int j = 0; j < 2; j++) {
            size_t base = base0 + (size_t)j * 2048 + (size_t)tid * 8;
            float4 a = *(const float4*)(src + base);
            float4 b = *(const float4*)(src + base + 4);
            __half2 h[4];
            h[0] = __halves2half2(__float2half(a.x), __float2half(a.y));
            h[1] = __halves2half2(__float2half(a.z), __float2half(a.w));
            h[2] = __halves2half2(__float2half(b.x), __float2half(b.y));
            h[3] = __halves2half2(__float2half(b.z), __float2half(b.w));
            *(uint4*)(dst + base) = *(uint4*)h;
        }
        return;
    }

    int t = blk - 8192;
    const float* W;
    __half* Th;
    int K, N, n0, k0, perm;
    if (t < 256) {
        W = Wq; Th = g_Wqt; K = 512; N = 512; perm = 1;
        n0 = (t & 15) * 32; k0 = (t >> 4) * 32;
    } else if (t < 768) {
        int tt = t - 256;
        W = Wkv; Th = g_Wkvt; K = 512; N = 1024; perm = 0;
        n0 = (tt & 31) * 32; k0 = (tt >> 5) * 32;
    } else {
        int tt = t - 768;
        W = Wp; Th = g_Wpt; K = 512; N = 512; perm = 0;
        n0 = (tt & 15) * 32; k0 = (tt >> 4) * 32;
    }
    __shared__ float tbuf[32][33];
    int tx = tid & 31, ty = tid >> 5;
#pragma unroll
    for (int i = 0; i < 4; i++)
        tbuf[ty + 8 * i][tx] = W[(size_t)(k0 + ty + 8 * i) * N + n0 + tx];
    __syncthreads();
#pragma unroll
    for (int i = 0; i < 4; i++) {
        int n = n0 + ty + 8 * i;
        int np = perm ? ((n & 7) * 64 + (n >> 3)) : n;
        Th[(size_t)np * K + k0 + tx] = __float2half(tbuf[tx][ty + 8 * i]);
    }
}

// ---------------------------------------------------------------------------
// Split-K reduce + LayerNorm -> fp16 F. 512 threads, one column each.
// ---------------------------------------------------------------------------
__global__ __launch_bounds__(512) void reduce_ln(
    const float* __restrict__ gamma, const float* __restrict__ beta)
{
    int row = blockIdx.x;
    int tid = threadIdx.x;

    float v = 0.f;
#pragma unroll
    for (int pz = 0; pz < SPLITK; pz++)
        v += g_part[(size_t)pz * MROWS * C_ + (size_t)row * C_ + tid];

    float sum = v, sq = v * v;
    __shared__ float ssum[16], ssq[16];
    __shared__ float s_mean, s_inv;
#pragma unroll
    for (int o = 16; o > 0; o >>= 1) {
        sum += __shfl_down_sync(0xffffffffu, sum, o);
        sq  += __shfl_down_sync(0xffffffffu, sq, o);
    }
    int lane = tid & 31, wid = tid >> 5;
    if (lane == 0) { ssum[wid] = sum; ssq[wid] = sq; }
    __syncthreads();
    if (tid == 0) {
        float S = 0.f, Q = 0.f;
#pragma unroll
        for (int i = 0; i < 16; i++) { S += ssum[i]; Q += ssq[i]; }
        float mean = S * (1.0f / C_);
        float var = Q * (1.0f / C_) - mean * mean;
        s_mean = mean;
        s_inv = rsqrtf(var + EPS);
    }
    __syncthreads();
    g_Ff[(size_t)row * C_ + tid] =
        __float2half((v - s_mean) * s_inv * gamma[tid] + beta[tid]);
}

// ---------------------------------------------------------------------------
// MMA attention. Block = (b*8+nh, qtile of 128). 256 threads / 8 warps.
// S = Q@Kh^T ; softmax via ex2.approx.f16x2 (no max-sub: logits bounded,
// max|logit*scale| ~ 1.5 << fp16 exp2 range); O = Ph@Vh.
// ---------------------------------------------------------------------------
#define AROWB 144
#define AQ  0
#define AKH 18432
#define AVH 27648
// 0.125 (1/sqrt(64)) * log2(e)
#define SM_SCALE 0.18033688f

__global__ __launch_bounds__(256) void attn_mma()
{
    __shared__ __align__(16) char asm_[36864];
    uint32_t sb = smem_u32(asm_);
    int tid = threadIdx.x, lane = tid & 31, wid = tid >> 5;
    int b = blockIdx.x >> 3, nh = blockIdx.x & 7;
    int n0 = blockIdx.y * 128;

    for (int idx = tid; idx < 1024; idx += 256) {
        int r = idx >> 3, s = idx & 7;
        *(uint4*)(asm_ + AQ + r * AROWB + s * 16) =
            *(const uint4*)(g_Qh + ((size_t)(b * 4096 + n0 + r)) * 512
                            + nh * 64 + s * 8);
    }
    for (int idx = tid; idx < 512; idx += 256) {
        int r = idx >> 3, s = idx & 7;
        size_t off = ((size_t)(b * 64 + r)) * 512 + nh * 64 + s * 8;
        uint32_t so = r * AROWB + s * 16;
        *(uint4*)(asm_ + AKH + so) = *(const uint4*)(g_Kf + off);
        *(uint4*)(asm_ + AVH + so) = *(const uint4*)(g_Vf + off);
    }
    __syncthreads();

    int mat = lane >> 3;
    int arow = ((mat & 1) << 3) + (lane & 7);
    int brow = ((mat >> 1) << 3) + (lane & 7);

    float sacc[8][4];
#pragma unroll
    for (int i = 0; i < 8; i++)
#pragma unroll
        for (int j = 0; j < 4; j++) sacc[i][j] = 0.f;

#pragma unroll
    for (int kk = 0; kk < 4; kk++) {
        int akcol = kk * 16 + ((mat >> 1) << 3);
        int bkcol = kk * 16 + ((mat & 1) << 3);
        uint32_t a[4];
        ldm_x4(a, sb + AQ + (uint32_t)(wid * 16 + arow) * AROWB + akcol * 2);
#pragma unroll
        for (int ng = 0; ng < 4; ng++) {
            uint32_t bh[4];
            ldm_x4(bh, sb + AKH + (uint32_t)(ng * 16 + brow) * AROWB + bkcol * 2);
            mma16816(sacc[2 * ng],     a, bh);
            mma16816(sacc[2 * ng + 1], a, bh + 2);
        }
    }

    // softmax: exp2 of scaled logits directly in fp16x2 (P fragments),
    // fp32 row sums. No max-subtraction (logits bounded by construction).
    uint32_t ph[8][2];
    float sum0 = 0.f, sum1 = 0.f;
#pragma unroll
    for (int nt = 0; nt < 8; nt++) {
        __half2 h01 = __floats2half2_rn(sacc[nt][0] * SM_SCALE,
                                        sacc[nt][1] * SM_SCALE);
        __half2 h23 = __floats2half2_rn(sacc[nt][2] * SM_SCALE,
                                        sacc[nt][3] * SM_SCALE);
        h01 = h2exp2(h01);
        h23 = h2exp2(h23);
        ph[nt][0] = *(uint32_t*)&h01;
        ph[nt][1] = *(uint32_t*)&h23;
        float2 f0 = __half22float2(h01);
        float2 f1 = __half22float2(h23);
        sum0 += f0.x + f0.y;
        sum1 += f1.x + f1.y;
    }
    sum0 += __shfl_xor_sync(0xffffffffu, sum0, 1);
    sum0 += __shfl_xor_sync(0xffffffffu, sum0, 2);
    sum1 += __shfl_xor_sync(0xffffffffu, sum1, 1);
    sum1 += __shfl_xor_sync(0xffffffffu, sum1, 2);
    float inv0 = 1.f / sum0, inv1 = 1.f / sum1;

    float oacc[8][4];
#pragma unroll
    for (int i = 0; i < 8; i++)
#pragma unroll
        for (int j = 0; j < 4; j++) oacc[i][j] = 0.f;

#pragma unroll
    for (int kt = 0; kt < 4; kt++) {
        uint32_t ah[4] = { ph[2 * kt][0], ph[2 * kt][1],
                           ph[2 * kt + 1][0], ph[2 * kt + 1][1] };
        int vrow = kt * 16 + ((lane >> 3) & 1) * 8 + (lane & 7);
        int vcol = (lane >> 4) * 8;
#pragma unroll
        for (int ng = 0; ng < 4; ng++) {
            uint32_t bh[4];
            ldm_x4t(bh, sb + AVH + (uint32_t)vrow * AROWB
                         + (ng * 16 + vcol) * 2);
            mma16816(oacc[2 * ng],     ah, bh);
            mma16816(oacc[2 * ng + 1], ah, bh + 2);
        }
    }

    int r0 = n0 + wid * 16 + (lane >> 2);
#pragma unroll
    for (int nt = 0; nt < 8; nt++) {
        int col = nh * 64 + nt * 8 + (lane & 3) * 2;
        __half2 v0 = __halves2half2(__float2half(oacc[nt][0] * inv0),
                                    __float2half(oacc[nt][1] * inv0));
        __half2 v1 = __halves2half2(__float2half(oacc[nt][2] * inv1),
                                    __float2half(oacc[nt][3] * inv1));
        *(__half2*)(g_AOf + ((size_t)(b * 4096 + r0)) * 512 + col) = v0;
        *(__half2*)(g_AOf + ((size_t)(b * 4096 + r0 + 8)) * 512 + col) = v1;
    }
}

// ---------------------------------------------------------------------------
// Host launcher
// ---------------------------------------------------------------------------
extern "C" void kernel_launch(void* const* d_in, const int* in_sizes, int n_in,
                              void* d_out, int out_size)
{
    const float* x     = (const float*)d_in[0];
    const float* Wq    = (const float*)d_in[1];
    const float* Wkv   = (const float*)d_in[2];
    const float* convw = (const float*)d_in[3];
    const float* gamma = (const float*)d_in[4];
    const float* beta  = (const float*)d_in[5];
    const float* Wp    = (const float*)d_in[6];
    const float* bp    = (const float*)d_in[7];
    float* out = (float*)d_out;

    cudaFuncSetAttribute(mgemm_qc, cudaFuncAttributeMaxDynamicSharedMemorySize,
                         MG_SMEM);
    cudaFuncSetAttribute(mgemm_g, cudaFuncAttributeMaxDynamicSharedMemorySize,
                         MG_SMEM);

    // fused conversions + transposes (one launch)
    prep_kernel<<<8192 + 1024, 256>>>(x, convw, Wq, Wkv, Wp);

    // Q-projection + conv GEMM fused (conv's long CTAs first)
    mgemm_qc<<<1280, 256, MG_SMEM>>>();
    // reduce + LN -> Ff
    reduce_ln<<<MROWS, 512>>>(gamma, beta);
    // KV = F @ Wkv -> fp16 Kf / Vf directly
    mgemm_g<<<dim3(8, 4), 256, MG_SMEM>>>(
        ASEL_F, BSEL_WKVT, DSEL_KV, 512, 1024, nullptr, nullptr, 0);
    // attention (MMA) -> AOf
    attn_mma<<<dim3(64, 32), 256>>>();
    // out = AO @ Wp + bp
    mgemm_g<<<dim3(4, 256), 256, MG_SMEM>>>(
        ASEL_AO, BSEL_WPT, DSEL_EXT, 512, 512, out, bp, 1);
}

// round 14
// speedup vs baseline: 7.1140x; 1.0086x over previous
#include <cuda_runtime.h>
#include <cuda_fp16.h>
#include <math.h>
#include <cstdint>

// Problem constants
#define B_   8
#define N_   4096
#define C_   512
#define NH_  8
#define HD_  64
#define MROWS 512
#define KCONV 32768
#define SPLITK 16
#define KCHUNK (KCONV/SPLITK)  // 2048
#define EPS 1e-3f

// ---------------------------------------------------------------------------
// Device global scratch (referenced ONLY from device code)
// ---------------------------------------------------------------------------
__device__ __half g_Qh[B_*N_*C_];               // head-major fp16 Q: col = nh*64+hd
__device__ float g_part[SPLITK*MROWS*C_];       // conv split-K partials (16MB)
__device__ __half g_Kp[2*MROWS*C_];             // K fp16 partials (split-K halves)
__device__ __half g_Vp[2*MROWS*C_];             // V fp16 partials
__device__ __half g_xf[B_*N_*C_];               // x fp16
__device__ __half g_Ff[MROWS*C_];               // LN out fp16
__device__ __half g_AOf[B_*N_*C_];              // attention out fp16
__device__ __half g_Wqt[C_*C_];                 // Wq^T, rows permuted head-major
__device__ __half g_Wkvt[2*C_*C_];              // Wkv^T
__device__ __half g_Wcf[KCONV*C_];              // convW fp16, NATIVE [K][N] layout
__device__ __half g_Wpt[C_*C_];                 // Wp^T

// selectors (resolved in device code only)
#define ASEL_F  1
#define ASEL_AO 2
#define BSEL_WKVT 1
#define BSEL_WPT  3
#define DSEL_QH   0
#define DSEL_KV   2
#define DSEL_EXT  3

// ---------------------------------------------------------------------------
// PTX helpers (sm_80-baseline; valid on compute_103 virtual arch)
// ---------------------------------------------------------------------------
__device__ __forceinline__ uint32_t smem_u32(const void* p) {
    uint32_t a;
    asm("{ .reg .u64 t; cvta.to.shared.u64 t, %1; cvt.u32.u64 %0, t; }"
        : "=r"(a) : "l"(p));
    return a;
}
__device__ __forceinline__ void ldm_x4(uint32_t* r, uint32_t addr) {
    asm volatile("ldmatrix.sync.aligned.m8n8.x4.shared.b16 {%0,%1,%2,%3}, [%4];"
        : "=r"(r[0]), "=r"(r[1]), "=r"(r[2]), "=r"(r[3]) : "r"(addr));
}
__device__ __forceinline__ void ldm_x4t(uint32_t* r, uint32_t addr) {
    asm volatile("ldmatrix.sync.aligned.m8n8.x4.trans.shared.b16 {%0,%1,%2,%3}, [%4];"
        : "=r"(r[0]), "=r"(r[1]), "=r"(r[2]), "=r"(r[3]) : "r"(addr));
}
__device__ __forceinline__ void mma16816(float* c, const uint32_t* a,
                                         const uint32_t* b) {
    asm volatile("mma.sync.aligned.m16n8k16.row.col.f32.f16.f16.f32 "
        "{%0,%1,%2,%3},{%4,%5,%6,%7},{%8,%9},{%0,%1,%2,%3};"
        : "+f"(c[0]), "+f"(c[1]), "+f"(c[2]), "+f"(c[3])
        : "r"(a[0]), "r"(a[1]), "r"(a[2]), "r"(a[3]), "r"(b[0]), "r"(b[1]));
}
__device__ __forceinline__ void cpa16(uint32_t d, const void* s) {
    asm volatile("cp.async.cg.shared.global [%0], [%1], 16;" :: "r"(d), "l"(s));
}
#define CPA_COMMIT() asm volatile("cp.async.commit_group;" ::: "memory")
#define CPA_WAIT2()  asm volatile("cp.async.wait_group 2;" ::: "memory")

// mgemm smem layout
#define ROWB  80
#define OFF_B 10240
#define BTROWB 272
#define STG   20480
#define NSTAGE 4
#define MG_SMEM (NSTAGE*STG)   // 81920 (dynamic)

// ---------------------------------------------------------------------------
// GEMM body. BT=0: C = A @ Bt^T (Bt [N][K]).  BT=1: C = A @ B (B [K][N], N=512).
// Tile 128x128, BK=32, 256 threads, 4-stage cp.async, 1 sync/iter.
// ---------------------------------------------------------------------------
template<int BT>
__device__ __forceinline__ void mgemm_body(
    const __half* __restrict__ A, const __half* __restrict__ B,
    int dSel, int Kfull, int iters, int kbase, int ldC,
    int rowBase, int colBase,
    float* __restrict__ Cd, const float* __restrict__ bias,
    int hasBias, int aGather, int kvoff, char* smem)
{
    uint32_t sb = smem_u32(smem);
    int tid = threadIdx.x, lane = tid & 31, wid = tid >> 5;

    int m0 = (wid >> 2) * 64;
    int n0 = (wid & 3) * 32;

    float acc[4][4][4];
#pragma unroll
    for (int a = 0; a < 4; a++)
#pragma unroll
        for (int b = 0; b < 4; b++)
#pragma unroll
            for (int c = 0; c < 4; c++) acc[a][b][c] = 0.f;

    auto issue = [&](int i) {
        int k0 = kbase + i * 32;
        uint32_t so = sb + (uint32_t)(i & (NSTAGE - 1)) * STG;
#pragma unroll
        for (int j = 0; j < 2; j++) {
            int c = tid + j * 256;
            int r = c >> 2, s = c & 3;
            size_t off;
            if (aGather) {
                int rg = rowBase + r;
                int bb = rg >> 6;
                int p = rg & 63;
                int pix = k0 >> 9;     // constant across the 32-wide slab
                int pixel = bb * 4096 + (p >> 3) * 512 + (p & 7) * 8
                          + (pix >> 3) * 64 + (pix & 7);
                off = (size_t)pixel * 512 + (k0 & 511) + s * 8;
            } else {
                off = (size_t)(rowBase + r) * Kfull + k0 + s * 8;
            }
            cpa16(so + r * ROWB + s * 16, A + off);
        }
        if (BT) {
#pragma unroll
            for (int j = 0; j < 2; j++) {
                int c = tid + j * 256;
                int r = c >> 4, s = c & 15;
                cpa16(so + OFF_B + r * BTROWB + s * 16,
                      B + (size_t)(k0 + r) * 512 + colBase + s * 8);
            }
        } else {
#pragma unroll
            for (int j = 0; j < 2; j++) {
                int c = tid + j * 256;
                int r = c >> 2, s = c & 3;
                cpa16(so + OFF_B + r * ROWB + s * 16,
                      B + (size_t)(colBase + r) * Kfull + k0 + s * 8);
            }
        }
        CPA_COMMIT();
    };

    int mat = lane >> 3;
    int arow_off = ((mat & 1) << 3) + (lane & 7);
    int nrow_off = ((mat >> 1) << 3) + (lane & 7);
    int btrow_off = ((lane >> 3) & 1) * 8 + (lane & 7);
    int btcol_off = (lane >> 4) * 8;

    issue(0); issue(1); issue(2);

    for (int i = 0; i < iters; i++) {
        CPA_WAIT2();
        __syncthreads();
        if (i + 3 < iters) issue(i + 3);
        else CPA_COMMIT();          // empty group keeps wait_group count exact

        uint32_t base = sb + (uint32_t)(i & (NSTAGE - 1)) * STG;
#pragma unroll
        for (int kk = 0; kk < 2; kk++) {
            int akcol = kk * 16 + ((mat >> 1) << 3);
            uint32_t a_f[4][4], b_f[2][4];
#pragma unroll
            for (int mt = 0; mt < 4; mt++)
                ldm_x4(a_f[mt], base + (uint32_t)(m0 + mt * 16 + arow_off) * ROWB
                                 + akcol * 2);
            if (BT) {
                int vrow = kk * 16 + btrow_off;
#pragma unroll
                for (int np = 0; np < 2; np++)
                    ldm_x4t(b_f[np], base + OFF_B + (uint32_t)vrow * BTROWB
                                      + (n0 + np * 16 + btcol_off) * 2);
            } else {
                int bkcol = kk * 16 + ((mat & 1) << 3);
#pragma unroll
                for (int np = 0; np < 2; np++)
                    ldm_x4(b_f[np], base + OFF_B
                                     + (uint32_t)(n0 + np * 16 + nrow_off) * ROWB
                                     + bkcol * 2);
            }
#pragma unroll
            for (int mt = 0; mt < 4; mt++)
#pragma unroll
                for (int nt = 0; nt < 4; nt++)
                    mma16816(acc[mt][nt], a_f[mt], &b_f[nt >> 1][(nt & 1) * 2]);
        }
    }

    // epilogue
    int m0g = rowBase + m0, n0g = colBase + n0;
#pragma unroll
    for (int mt = 0; mt < 4; mt++) {
        int r0 = m0g + mt * 16 + (lane >> 2);
#pragma unroll
        for (int nt = 0; nt < 4; nt++) {
            int col = n0g + nt * 8 + (lane & 3) * 2;
            if (dSel == DSEL_QH) {
                __half2 v0 = __halves2half2(__float2half(acc[mt][nt][0]),
                                            __float2half(acc[mt][nt][1]));
                __half2 v1 = __halves2half2(__float2half(acc[mt][nt][2]),
                                            __float2half(acc[mt][nt][3]));
                *(__half2*)(g_Qh + (size_t)r0 * ldC + col) = v0;
                *(__half2*)(g_Qh + (size_t)(r0 + 8) * ldC + col) = v1;
            } else if (dSel == DSEL_KV) {
#pragma unroll
                for (int half = 0; half < 2; half++) {
                    int rr = r0 + half * 8;
                    __half2 hv = __halves2half2(
                        __float2half(acc[mt][nt][2 * half]),
                        __float2half(acc[mt][nt][2 * half + 1]));
                    if (col < 512)
                        *(__half2*)(g_Kp + kvoff + (size_t)rr * 512 + col) = hv;
                    else
                        *(__half2*)(g_Vp + kvoff + (size_t)rr * 512 + col - 512) = hv;
                }
            } else {
                float b0 = 0.f, b1 = 0.f;
                if (hasBias) { b0 = bias[col]; b1 = bias[col + 1]; }
                float* p = Cd + (size_t)r0 * ldC + col;
                p[0] = acc[mt][nt][0] + b0;
                p[1] = acc[mt][nt][1] + b1;
                float* q = p + 8 * ldC;
                q[0] = acc[mt][nt][2] + b0;
                q[1] = acc[mt][nt][3] + b1;
            }
        }
    }
}

// Fused Q-projection + conv GEMM (independent; conv's long CTAs first).
__global__ __launch_bounds__(256, 2) void mgemm_qc()
{
    extern __shared__ __align__(16) char smem[];
    int bid = blockIdx.x;
    if (bid < 256) {
        int z = bid & 15, xy = bid >> 4;
        mgemm_body<1>(g_xf, g_Wcf, /*dSel=*/99, KCONV, KCHUNK / 32,
                      z * KCHUNK, 512, (xy >> 2) * 128, (xy & 3) * 128,
                      g_part + (size_t)z * (MROWS * C_), nullptr, 0, 1, 0, smem);
    } else {
        int t = bid - 256;
        mgemm_body<0>(g_xf, g_Wqt, DSEL_QH, 512, 16, 0, 512,
                      (t >> 2) * 128, (t & 3) * 128,
                      nullptr, nullptr, 0, 0, 0, smem);
    }
}

// Generic BT=0 GEMM (KV projection w/ split-K via blockIdx.z, out projection)
// — buffers resolved IN DEVICE CODE via selectors.
__global__ __launch_bounds__(256, 2) void mgemm_g(
    int aSel, int bSel, int dSel, int Kfull, int iters, int kchunk, int ldC,
    float* __restrict__ extC, const float* __restrict__ bias, int hasBias)
{
    extern __shared__ __align__(16) char smem[];
    const __half* A = (aSel == ASEL_F) ? g_Ff : g_AOf;
    const __half* B = (bSel == BSEL_WKVT) ? g_Wkvt : g_Wpt;
    int z = blockIdx.z;
    mgemm_body<0>(A, B, dSel, Kfull, iters, z * kchunk, ldC,
                  blockIdx.y * 128, blockIdx.x * 128,
                  extC, bias, hasBias, 0, z * (MROWS * C_), smem);
}

// ---------------------------------------------------------------------------
// Fused prep: x fp32->fp16, convW fp32->fp16 native layout (16 elems/thread),
// and the three small weight transposes. One launch.
// ---------------------------------------------------------------------------
__global__ __launch_bounds__(256) void prep_kernel(
    const float* __restrict__ x, const float* __restrict__ convw,
    const float* __restrict__ Wq, const float* __restrict__ Wkv,
    const float* __restrict__ Wp)
{
    int blk = blockIdx.x;
    int tid = threadIdx.x;

    if (blk < 8192) {
        const float* src = (blk < 4096) ? x : convw;
        __half* dst = (blk < 4096) ? g_xf : g_Wcf;
        size_t base0 = (size_t)(blk & 4095) * 4096;
#pragma unroll
        for (int j = 0; j < 2; j++) {
            size_t base = base0 + (size_t)j * 2048 + (size_t)tid * 8;
            float4 a = *(const float4*)(src + base);
            float4 b = *(const float4*)(src + base + 4);
            __half2 h[4];
            h[0] = __halves2half2(__float2half(a.x), __float2half(a.y));
            h[1] = __halves2half2(__float2half(a.z), __float2half(a.w));
            h[2] = __halves2half2(__float2half(b.x), __float2half(b.y));
            h[3] = __halves2half2(__float2half(b.z), __float2half(b.w));
            *(uint4*)(dst + base) = *(uint4*)h;
        }
        return;
    }

    int t = blk - 8192;
    const float* W;
    __half* Th;
    int K, N, n0, k0, perm;
    if (t < 256) {
        W = Wq; Th = g_Wqt; K = 512; N = 512; perm = 1;
        n0 = (t & 15) * 32; k0 = (t >> 4) * 32;
    } else if (t < 768) {
        int tt = t - 256;
        W = Wkv; Th = g_Wkvt; K = 512; N = 1024; perm = 0;
        n0 = (tt & 31) * 32; k0 = (tt >> 5) * 32;
    } else {
        int tt = t - 768;
        W = Wp; Th = g_Wpt; K = 512; N = 512; perm = 0;
        n0 = (tt & 15) * 32; k0 = (tt >> 4) * 32;
    }
    __shared__ float tbuf[32][33];
    int tx = tid & 31, ty = tid >> 5;
#pragma unroll
    for (int i = 0; i < 4; i++)
        tbuf[ty + 8 * i][tx] = W[(size_t)(k0 + ty + 8 * i) * N + n0 + tx];
    __syncthreads();
#pragma unroll
    for (int i = 0; i < 4; i++) {
        int n = n0 + ty + 8 * i;
        int np = perm ? ((n & 7) * 64 + (n >> 3)) : n;
        Th[(size_t)np * K + k0 + tx] = __float2half(tbuf[tx][ty + 8 * i]);
    }
}

// ---------------------------------------------------------------------------
// Split-K reduce + LayerNorm -> fp16 F. 2 rows per block, 512 threads,
// float2 loads (256 blocks -> better MLP/occupancy on the 16MB read).
// ---------------------------------------------------------------------------
__global__ __launch_bounds__(512) void reduce_ln(
    const float* __restrict__ gamma, const float* __restrict__ beta)
{
    int tid = threadIdx.x;
    int row = blockIdx.x * 2 + (tid >> 8);
    int c = (tid & 255) * 2;

    float2 v = make_float2(0.f, 0.f);
#pragma unroll
    for (int pz = 0; pz < SPLITK; pz++) {
        float2 p = *(const float2*)&g_part[(size_t)pz * MROWS * C_
                                           + (size_t)row * C_ + c];
        v.x += p.x;
        v.y += p.y;
    }
    float sum = v.x + v.y;
    float sq = v.x * v.x + v.y * v.y;

    __shared__ float ssum[16], ssq[16];
    __shared__ float s_mean[2], s_inv[2];
#pragma unroll
    for (int o = 16; o > 0; o >>= 1) {
        sum += __shfl_down_sync(0xffffffffu, sum, o);
        sq  += __shfl_down_sync(0xffffffffu, sq, o);
    }
    int lane = tid & 31, wid = tid >> 5;
    if (lane == 0) { ssum[wid] = sum; ssq[wid] = sq; }
    __syncthreads();
    if ((tid & 255) == 0) {
        int rr = tid >> 8;
        float S = 0.f, Q = 0.f;
#pragma unroll
        for (int i = 0; i < 8; i++) { S += ssum[rr * 8 + i]; Q += ssq[rr * 8 + i]; }
        float mean = S * (1.0f / C_);
        float var = Q * (1.0f / C_) - mean * mean;
        s_mean[rr] = mean;
        s_inv[rr] = rsqrtf(var + EPS);
    }
    __syncthreads();
    int rr = tid >> 8;
    float mean = s_mean[rr], inv = s_inv[rr];
    __half2 outv = __floats2half2_rn(
        (v.x - mean) * inv * gamma[c] + beta[c],
        (v.y - mean) * inv * gamma[c + 1] + beta[c + 1]);
    *(__half2*)&g_Ff[(size_t)row * C_ + c] = outv;
}

// ---------------------------------------------------------------------------
// MMA attention. Block = (b*8+nh, qtile of 128). 256 threads / 8 warps.
// Combines KV split-K halves (__hadd2) during smem load.
// S = Q@K^T ; softmax via ex2.approx.f16x2 ; O = P@V.
// ---------------------------------------------------------------------------
#define AROWB 144
#define AQ  0
#define AKH 18432
#define AVH 27648
// 0.125 (1/sqrt(64)) * log2(e)
#define SM_SCALE 0.18033688f

__global__ __launch_bounds__(256) void attn_mma()
{
    __shared__ __align__(16) char asm_[36864];
    uint32_t sb = smem_u32(asm_);
    int tid = threadIdx.x, lane = tid & 31, wid = tid >> 5;
    int b = blockIdx.x >> 3, nh = blockIdx.x & 7;
    int n0 = blockIdx.y * 128;

    for (int idx = tid; idx < 1024; idx += 256) {
        int r = idx >> 3, s = idx & 7;
        *(uint4*)(asm_ + AQ + r * AROWB + s * 16) =
            *(const uint4*)(g_Qh + ((size_t)(b * 4096 + n0 + r)) * 512
                            + nh * 64 + s * 8);
    }
    for (int idx = tid; idx < 512; idx += 256) {
        int r = idx >> 3, s = idx & 7;
        size_t off = ((size_t)(b * 64 + r)) * 512 + nh * 64 + s * 8;
        uint32_t so = r * AROWB + s * 16;
        uint4 k0 = *(const uint4*)(g_Kp + off);
        uint4 k1 = *(const uint4*)(g_Kp + MROWS * C_ + off);
        uint4 v0 = *(const uint4*)(g_Vp + off);
        uint4 v1 = *(const uint4*)(g_Vp + MROWS * C_ + off);
        __half2* ka = (__half2*)&k0; __half2* kb = (__half2*)&k1;
        __half2* va = (__half2*)&v0; __half2* vb = (__half2*)&v1;
        uint4 kc, vc;
        __half2* kcp = (__half2*)&kc; __half2* vcp = (__half2*)&vc;
#pragma unroll
        for (int j = 0; j < 4; j++) {
            kcp[j] = __hadd2(ka[j], kb[j]);
            vcp[j] = __hadd2(va[j], vb[j]);
        }
        *(uint4*)(asm_ + AKH + so) = kc;
        *(uint4*)(asm_ + AVH + so) = vc;
    }
    __syncthreads();

    int mat = lane >> 3;
    int arow = ((mat & 1) << 3) + (lane & 7);
    int brow = ((mat >> 1) << 3) + (lane & 7);

    float sacc[8][4];
#pragma unroll
    for (int i = 0; i < 8; i++)
#pragma unroll
        for (int j = 0; j < 4; j++) sacc[i][j] = 0.f;

#pragma unroll
    for (int kk = 0; kk < 4; kk++) {
        int akcol = kk * 16 + ((mat >> 1) << 3);
        int bkcol = kk * 16 + ((mat & 1) << 3);
        uint32_t a[4];
        ldm_x4(a, sb + AQ + (uint32_t)(wid * 16 + arow) * AROWB + akcol * 2);
#pragma unroll
        for (int ng = 0; ng < 4; ng++) {
            uint32_t bh[4];
            ldm_x4(bh, sb + AKH + (uint32_t)(ng * 16 + brow) * AROWB + bkcol * 2);
            mma16816(sacc[2 * ng],     a, bh);
            mma16816(sacc[2 * ng + 1], a, bh + 2);
        }
    }

    // softmax: exp2 in fp16x2 (these ARE the P fragments); fp32 row sums.
    uint32_t ph[8][2];
    float sum0 = 0.f, sum1 = 0.f;
#pragma unroll
    for (int nt = 0; nt < 8; nt++) {
        __half2 h01 = __floats2half2_rn(sacc[nt][0] * SM_SCALE,
                                        sacc[nt][1] * SM_SCALE);
        __half2 h23 = __floats2half2_rn(sacc[nt][2] * SM_SCALE,
                                        sacc[nt][3] * SM_SCALE);
        h01 = h2exp2(h01);
        h23 = h2exp2(h23);
        ph[nt][0] = *(uint32_t*)&h01;
        ph[nt][1] = *(uint32_t*)&h23;
        float2 f0 = __half22float2(h01);
        float2 f1 = __half22float2(h23);
        sum0 += f0.x + f0.y;
        sum1 += f1.x + f1.y;
    }
    sum0 += __shfl_xor_sync(0xffffffffu, sum0, 1);
    sum0 += __shfl_xor_sync(0xffffffffu, sum0, 2);
    sum1 += __shfl_xor_sync(0xffffffffu, sum1, 1);
    sum1 += __shfl_xor_sync(0xffffffffu, sum1, 2);
    float inv0 = 1.f / sum0, inv1 = 1.f / sum1;

    float oacc[8][4];
#pragma unroll
    for (int i = 0; i < 8; i++)
#pragma unroll
        for (int j = 0; j < 4; j++) oacc[i][j] = 0.f;

#pragma unroll
    for (int kt = 0; kt < 4; kt++) {
        uint32_t ah[4] = { ph[2 * kt][0], ph[2 * kt][1],
                           ph[2 * kt + 1][0], ph[2 * kt + 1][1] };
        int vrow = kt * 16 + ((lane >> 3) & 1) * 8 + (lane & 7);
        int vcol = (lane >> 4) * 8;
#pragma unroll
        for (int ng = 0; ng < 4; ng++) {
            uint32_t bh[4];
            ldm_x4t(bh, sb + AVH + (uint32_t)vrow * AROWB
                         + (ng * 16 + vcol) * 2);
            mma16816(oacc[2 * ng],     ah, bh);
            mma16816(oacc[2 * ng + 1], ah, bh + 2);
        }
    }

    int r0 = n0 + wid * 16 + (lane >> 2);
#pragma unroll
    for (int nt = 0; nt < 8; nt++) {
        int col = nh * 64 + nt * 8 + (lane & 3) * 2;
        __half2 v0 = __halves2half2(__float2half(oacc[nt][0] * inv0),
                                    __float2half(oacc[nt][1] * inv0));
        __half2 v1 = __halves2half2(__float2half(oacc[nt][2] * inv1),
                                    __float2half(oacc[nt][3] * inv1));
        *(__half2*)(g_AOf + ((size_t)(b * 4096 + r0)) * 512 + col) = v0;
        *(__half2*)(g_AOf + ((size_t)(b * 4096 + r0 + 8)) * 512 + col) = v1;
    }
}

// ---------------------------------------------------------------------------
// Host launcher
// ---------------------------------------------------------------------------
extern "C" void kernel_launch(void* const* d_in, const int* in_sizes, int n_in,
                              void* d_out, int out_size)
{
    const float* x     = (const float*)d_in[0];
    const float* Wq    = (const float*)d_in[1];
    const float* Wkv   = (const float*)d_in[2];
    const float* convw = (const float*)d_in[3];
    const float* gamma = (const float*)d_in[4];
    const float* beta  = (const float*)d_in[5];
    const float* Wp    = (const float*)d_in[6];
    const float* bp    = (const float*)d_in[7];
    float* out = (float*)d_out;

    cudaFuncSetAttribute(mgemm_qc, cudaFuncAttributeMaxDynamicSharedMemorySize,
                         MG_SMEM);
    cudaFuncSetAttribute(mgemm_g, cudaFuncAttributeMaxDynamicSharedMemorySize,
                         MG_SMEM);

    // fused conversions + transposes (one launch)
    prep_kernel<<<8192 + 1024, 256>>>(x, convw, Wq, Wkv, Wp);

    // Q-projection + conv GEMM fused (conv's long CTAs first)
    mgemm_qc<<<1280, 256, MG_SMEM>>>();
    // reduce + LN -> Ff (2 rows/block)
    reduce_ln<<<MROWS / 2, 512>>>(gamma, beta);
    // KV = F @ Wkv, split-K=2 -> fp16 partials g_Kp/g_Vp
    mgemm_g<<<dim3(8, 4, 2), 256, MG_SMEM>>>(
        ASEL_F, BSEL_WKVT, DSEL_KV, 512, 8, 256, 1024, nullptr, nullptr, 0);
    // attention (MMA, combines KV halves) -> AOf
    attn_mma<<<dim3(64, 32), 256>>>();
    // out = AO @ Wp + bp
    mgemm_g<<<dim3(4, 256, 1), 256, MG_SMEM>>>(
        ASEL_AO, BSEL_WPT, DSEL_EXT, 512, 16, 0, 512, out, bp, 1);
}

// round 15
// speedup vs baseline: 7.1582x; 1.0062x over previous
#include <cuda_runtime.h>
#include <cuda_fp16.h>
#include <math.h>
#include <cstdint>

// Problem constants
#define B_   8
#define N_   4096
#define C_   512
#define NH_  8
#define HD_  64
#define MROWS 512
#define KCONV 32768
#define SPLITK 16
#define KCHUNK (KCONV/SPLITK)  // 2048
#define EPS 1e-3f

// ---------------------------------------------------------------------------
// Device global scratch (referenced ONLY from device code)
// ---------------------------------------------------------------------------
__device__ __half g_Qh[B_*N_*C_];               // head-major fp16 Q: col = nh*64+hd
__device__ float g_part[SPLITK*MROWS*C_];       // conv split-K partials (16MB)
__device__ __half g_Kp[2*MROWS*C_];             // K fp16 partials (split-K halves)
__device__ __half g_Vp[2*MROWS*C_];             // V fp16 partials
__device__ __half g_xf[B_*N_*C_];               // x fp16
__device__ __half g_Ff[MROWS*C_];               // LN out fp16
__device__ __half g_AOf[B_*N_*C_];              // attention out fp16
__device__ __half g_Wqt[C_*C_];                 // Wq^T, rows permuted head-major
__device__ __half g_Wkvt[2*C_*C_];              // Wkv^T
__device__ __half g_Wcf[KCONV*C_];              // convW fp16, NATIVE [K][N] layout
__device__ __half g_Wpt[C_*C_];                 // Wp^T
__device__ unsigned g_bar;                      // monotonic ticket barrier

// selectors (resolved in device code only)
#define ASEL_F  1
#define ASEL_AO 2
#define DSEL_QH   0
#define DSEL_KV   2
#define DSEL_EXT  3

// ---------------------------------------------------------------------------
// PTX helpers (sm_80-baseline; valid on compute_103 virtual arch)
// ---------------------------------------------------------------------------
__device__ __forceinline__ uint32_t smem_u32(const void* p) {
    uint32_t a;
    asm("{ .reg .u64 t; cvta.to.shared.u64 t, %1; cvt.u32.u64 %0, t; }"
        : "=r"(a) : "l"(p));
    return a;
}
__device__ __forceinline__ void ldm_x4(uint32_t* r, uint32_t addr) {
    asm volatile("ldmatrix.sync.aligned.m8n8.x4.shared.b16 {%0,%1,%2,%3}, [%4];"
        : "=r"(r[0]), "=r"(r[1]), "=r"(r[2]), "=r"(r[3]) : "r"(addr));
}
__device__ __forceinline__ void ldm_x4t(uint32_t* r, uint32_t addr) {
    asm volatile("ldmatrix.sync.aligned.m8n8.x4.trans.shared.b16 {%0,%1,%2,%3}, [%4];"
        : "=r"(r[0]), "=r"(r[1]), "=r"(r[2]), "=r"(r[3]) : "r"(addr));
}
__device__ __forceinline__ void mma16816(float* c, const uint32_t* a,
                                         const uint32_t* b) {
    asm volatile("mma.sync.aligned.m16n8k16.row.col.f32.f16.f16.f32 "
        "{%0,%1,%2,%3},{%4,%5,%6,%7},{%8,%9},{%0,%1,%2,%3};"
        : "+f"(c[0]), "+f"(c[1]), "+f"(c[2]), "+f"(c[3])
        : "r"(a[0]), "r"(a[1]), "r"(a[2]), "r"(a[3]), "r"(b[0]), "r"(b[1]));
}
__device__ __forceinline__ void cpa16(uint32_t d, const void* s) {
    asm volatile("cp.async.cg.shared.global [%0], [%1], 16;" :: "r"(d), "l"(s));
}
#define CPA_COMMIT() asm volatile("cp.async.commit_group;" ::: "memory")
#define CPA_WAIT2()  asm volatile("cp.async.wait_group 2;" ::: "memory")

// mgemm smem layout
#define ROWB  80
#define OFF_B 10240
#define BTROWB 272
#define STG   20480
#define NSTAGE 4
#define MG_SMEM (NSTAGE*STG)   // 81920 (dynamic)

// ---------------------------------------------------------------------------
// GEMM body. BT=0: C = A @ Bt^T (Bt [N][K]).  BT=1: C = A @ B (B [K][N], N=512).
// Tile 128x128, BK=32, 256 threads, 4-stage cp.async, 1 sync/iter.
// ---------------------------------------------------------------------------
template<int BT>
__device__ __forceinline__ void mgemm_body(
    const __half* __restrict__ A, const __half* __restrict__ B,
    int dSel, int Kfull, int iters, int kbase, int ldC,
    int rowBase, int colBase,
    float* __restrict__ Cd, const float* __restrict__ bias,
    int hasBias, int aGather, int kvoff, char* smem)
{
    uint32_t sb = smem_u32(smem);
    int tid = threadIdx.x, lane = tid & 31, wid = tid >> 5;

    int m0 = (wid >> 2) * 64;
    int n0 = (wid & 3) * 32;

    float acc[4][4][4];
#pragma unroll
    for (int a = 0; a < 4; a++)
#pragma unroll
        for (int b = 0; b < 4; b++)
#pragma unroll
            for (int c = 0; c < 4; c++) acc[a][b][c] = 0.f;

    auto issue = [&](int i) {
        int k0 = kbase + i * 32;
        uint32_t so = sb + (uint32_t)(i & (NSTAGE - 1)) * STG;
#pragma unroll
        for (int j = 0; j < 2; j++) {
            int c = tid + j * 256;
            int r = c >> 2, s = c & 3;
            size_t off;
            if (aGather) {
                int rg = rowBase + r;
                int bb = rg >> 6;
                int p = rg & 63;
                int pix = k0 >> 9;     // constant across the 32-wide slab
                int pixel = bb * 4096 + (p >> 3) * 512 + (p & 7) * 8
                          + (pix >> 3) * 64 + (pix & 7);
                off = (size_t)pixel * 512 + (k0 & 511) + s * 8;
            } else {
                off = (size_t)(rowBase + r) * Kfull + k0 + s * 8;
            }
            cpa16(so + r * ROWB + s * 16, A + off);
        }
        if (BT) {
#pragma unroll
            for (int j = 0; j < 2; j++) {
                int c = tid + j * 256;
                int r = c >> 4, s = c & 15;
                cpa16(so + OFF_B + r * BTROWB + s * 16,
                      B + (size_t)(k0 + r) * 512 + colBase + s * 8);
            }
        } else {
#pragma unroll
            for (int j = 0; j < 2; j++) {
                int c = tid + j * 256;
                int r = c >> 2, s = c & 3;
                cpa16(so + OFF_B + r * ROWB + s * 16,
                      B + (size_t)(colBase + r) * Kfull + k0 + s * 8);
            }
        }
        CPA_COMMIT();
    };

    int mat = lane >> 3;
    int arow_off = ((mat & 1) << 3) + (lane & 7);
    int nrow_off = ((mat >> 1) << 3) + (lane & 7);
    int btrow_off = ((lane >> 3) & 1) * 8 + (lane & 7);
    int btcol_off = (lane >> 4) * 8;

    issue(0); issue(1); issue(2);

    for (int i = 0; i < iters; i++) {
        CPA_WAIT2();
        __syncthreads();
        if (i + 3 < iters) issue(i + 3);
        else CPA_COMMIT();          // empty group keeps wait_group count exact

        uint32_t base = sb + (uint32_t)(i & (NSTAGE - 1)) * STG;
#pragma unroll
        for (int kk = 0; kk < 2; kk++) {
            int akcol = kk * 16 + ((mat >> 1) << 3);
            uint32_t a_f[4][4], b_f[2][4];
#pragma unroll
            for (int mt = 0; mt < 4; mt++)
                ldm_x4(a_f[mt], base + (uint32_t)(m0 + mt * 16 + arow_off) * ROWB
                                 + akcol * 2);
            if (BT) {
                int vrow = kk * 16 + btrow_off;
#pragma unroll
                for (int np = 0; np < 2; np++)
                    ldm_x4t(b_f[np], base + OFF_B + (uint32_t)vrow * BTROWB
                                      + (n0 + np * 16 + btcol_off) * 2);
            } else {
                int bkcol = kk * 16 + ((mat & 1) << 3);
#pragma unroll
                for (int np = 0; np < 2; np++)
                    ldm_x4(b_f[np], base + OFF_B
                                     + (uint32_t)(n0 + np * 16 + nrow_off) * ROWB
                                     + bkcol * 2);
            }
#pragma unroll
            for (int mt = 0; mt < 4; mt++)
#pragma unroll
                for (int nt = 0; nt < 4; nt++)
                    mma16816(acc[mt][nt], a_f[mt], &b_f[nt >> 1][(nt & 1) * 2]);
        }
    }

    // epilogue
    int m0g = rowBase + m0, n0g = colBase + n0;
#pragma unroll
    for (int mt = 0; mt < 4; mt++) {
        int r0 = m0g + mt * 16 + (lane >> 2);
#pragma unroll
        for (int nt = 0; nt < 4; nt++) {
            int col = n0g + nt * 8 + (lane & 3) * 2;
            if (dSel == DSEL_QH) {
                __half2 v0 = __halves2half2(__float2half(acc[mt][nt][0]),
                                            __float2half(acc[mt][nt][1]));
                __half2 v1 = __halves2half2(__float2half(acc[mt][nt][2]),
                                            __float2half(acc[mt][nt][3]));
                *(__half2*)(g_Qh + (size_t)r0 * ldC + col) = v0;
                *(__half2*)(g_Qh + (size_t)(r0 + 8) * ldC + col) = v1;
            } else if (dSel == DSEL_KV) {
#pragma unroll
                for (int half = 0; half < 2; half++) {
                    int rr = r0 + half * 8;
                    __half2 hv = __halves2half2(
                        __float2half(acc[mt][nt][2 * half]),
                        __float2half(acc[mt][nt][2 * half + 1]));
                    if (col < 512)
                        *(__half2*)(g_Kp + kvoff + (size_t)rr * 512 + col) = hv;
                    else
                        *(__half2*)(g_Vp + kvoff + (size_t)rr * 512 + col - 512) = hv;
                }
            } else {
                float b0 = 0.f, b1 = 0.f;
                if (hasBias) { b0 = bias[col]; b1 = bias[col + 1]; }
                float* p = Cd + (size_t)r0 * ldC + col;
                p[0] = acc[mt][nt][0] + b0;
                p[1] = acc[mt][nt][1] + b1;
                float* q = p + 8 * ldC;
                q[0] = acc[mt][nt][2] + b0;
                q[1] = acc[mt][nt][3] + b1;
            }
        }
    }
}

// Fused Q-projection + conv GEMM (independent; conv's long CTAs first).
__global__ __launch_bounds__(256, 2) void mgemm_qc()
{
    extern __shared__ __align__(16) char smem[];
    int bid = blockIdx.x;
    if (bid < 256) {
        int z = bid & 15, xy = bid >> 4;
        mgemm_body<1>(g_xf, g_Wcf, /*dSel=*/99, KCONV, KCHUNK / 32,
                      z * KCHUNK, 512, (xy >> 2) * 128, (xy & 3) * 128,
                      g_part + (size_t)z * (MROWS * C_), nullptr, 0, 1, 0, smem);
    } else {
        int t = bid - 256;
        mgemm_body<0>(g_xf, g_Wqt, DSEL_QH, 512, 16, 0, 512,
                      (t >> 2) * 128, (t & 3) * 128,
                      nullptr, nullptr, 0, 0, 0, smem);
    }
}

// ---------------------------------------------------------------------------
// Fused reduce_ln + KV GEMM. 256 CTAs x 256 threads, MG_SMEM dynamic smem.
// Residency: 128 regs & 80KB smem both give 2 CTAs/SM -> 296 slots >= 256,
// so the monotonic ticket barrier cannot deadlock.
// Phase 1: each CTA reduces+LNs 2 rows of g_part -> g_Ff.
// Barrier (monotonic ticket; replay-safe across graph launches).
// Phase 2: CTAs 0..63 run the KV split-K=2 GEMM.
// ---------------------------------------------------------------------------
__global__ __launch_bounds__(256, 2) void lnkv_kernel(
    const float* __restrict__ gamma, const float* __restrict__ beta)
{
    extern __shared__ __align__(16) char smem[];
    int bid = blockIdx.x;
    int tid = threadIdx.x;

    // ---- phase 1: reduce + LN, 2 rows per CTA ----
    {
        int row = bid * 2 + (tid >> 7);
        int c = (tid & 127) * 4;

        float4 v = make_float4(0.f, 0.f, 0.f, 0.f);
#pragma unroll
        for (int pz = 0; pz < SPLITK; pz++) {
            float4 p = *(const float4*)&g_part[(size_t)pz * MROWS * C_
                                               + (size_t)row * C_ + c];
            v.x += p.x; v.y += p.y; v.z += p.z; v.w += p.w;
        }
        float sum = v.x + v.y + v.z + v.w;
        float sq = v.x * v.x + v.y * v.y + v.z * v.z + v.w * v.w;

        float* ssum = (float*)smem;          // [8]
        float* ssq  = (float*)smem + 8;      // [8]
        float* sst  = (float*)smem + 16;     // mean0, inv0, mean1, inv1
#pragma unroll
        for (int o = 16; o > 0; o >>= 1) {
            sum += __shfl_down_sync(0xffffffffu, sum, o);
            sq  += __shfl_down_sync(0xffffffffu, sq, o);
        }
        int lane = tid & 31, wid = tid >> 5;
        if (lane == 0) { ssum[wid] = sum; ssq[wid] = sq; }
        __syncthreads();
        if ((tid & 127) == 0) {
            int rr = tid >> 7;
            float S = 0.f, Q = 0.f;
#pragma unroll
            for (int i = 0; i < 4; i++) { S += ssum[rr * 4 + i]; Q += ssq[rr * 4 + i]; }
            float mean = S * (1.0f / C_);
            float var = Q * (1.0f / C_) - mean * mean;
            sst[rr * 2] = mean;
            sst[rr * 2 + 1] = rsqrtf(var + EPS);
        }
        __syncthreads();
        int rr = tid >> 7;
        float mean = sst[rr * 2], inv = sst[rr * 2 + 1];
        __half2 o0 = __floats2half2_rn(
            (v.x - mean) * inv * gamma[c] + beta[c],
            (v.y - mean) * inv * gamma[c + 1] + beta[c + 1]);
        __half2 o1 = __floats2half2_rn(
            (v.z - mean) * inv * gamma[c + 2] + beta[c + 2],
            (v.w - mean) * inv * gamma[c + 3] + beta[c + 3]);
        __half2 ov[2] = {o0, o1};
        *(uint2*)&g_Ff[(size_t)row * C_ + c] = *(uint2*)ov;
    }

    // ---- device-wide barrier (monotonic ticket, replay-safe) ----
    __threadfence();
    __syncthreads();
    if (tid == 0) {
        unsigned t = atomicAdd(&g_bar, 1u);
        unsigned target = ((t >> 8) + 1u) << 8;
        while (*(volatile unsigned*)&g_bar < target) { }
    }
    __syncthreads();
    __threadfence();

    // ---- phase 2: KV split-K=2 GEMM on CTAs 0..63 ----
    if (bid < 64) {
        int xq = bid & 7, y = (bid >> 3) & 3, z = bid >> 5;
        mgemm_body<0>(g_Ff, g_Wkvt, DSEL_KV, 512, 8, z * 256, 1024,
                      y * 128, xq * 128,
                      nullptr, nullptr, 0, 0, z * (MROWS * C_), smem);
    }
}

// Generic BT=0 GEMM (out projection) — buffers resolved in device code.
__global__ __launch_bounds__(256, 2) void mgemm_g(
    int dSel, int Kfull, int iters, int ldC,
    float* __restrict__ extC, const float* __restrict__ bias, int hasBias)
{
    extern __shared__ __align__(16) char smem[];
    mgemm_body<0>(g_AOf, g_Wpt, dSel, Kfull, iters, 0, ldC,
                  blockIdx.y * 128, blockIdx.x * 128,
                  extC, bias, hasBias, 0, 0, smem);
}

// ---------------------------------------------------------------------------
// Fused prep: x fp32->fp16, convW fp32->fp16 native layout (16 elems/thread),
// and the three small weight transposes. One launch.
// ---------------------------------------------------------------------------
__global__ __launch_bounds__(256) void prep_kernel(
    const float* __restrict__ x, const float* __restrict__ convw,
    const float* __restrict__ Wq, const float* __restrict__ Wkv,
    const float* __restrict__ Wp)
{
    int blk = blockIdx.x;
    int tid = threadIdx.x;

    if (blk < 8192) {
        const float* src = (blk < 4096) ? x : convw;
        __half* dst = (blk < 4096) ? g_xf : g_Wcf;
        size_t base0 = (size_t)(blk & 4095) * 4096;
#pragma unroll
        for (int j = 0; j < 2; j++) {
            size_t base = base0 + (size_t)j * 2048 + (size_t)tid * 8;
            float4 a = *(const float4*)(src + base);
            float4 b = *(const float4*)(src + base + 4);
            __half2 h[4];
            h[0] = __halves2half2(__float2half(a.x), __float2half(a.y));
            h[1] = __halves2half2(__float2half(a.z), __float2half(a.w));
            h[2] = __halves2half2(__float2half(b.x), __float2half(b.y));
            h[3] = __halves2half2(__float2half(b.z), __float2half(b.w));
            *(uint4*)(dst + base) = *(uint4*)h;
        }
        return;
    }

    int t = blk - 8192;
    const float* W;
    __half* Th;
    int K, N, n0, k0, perm;
    if (t < 256) {
        W = Wq; Th = g_Wqt; K = 512; N = 512; perm = 1;
        n0 = (t & 15) * 32; k0 = (t >> 4) * 32;
    } else if (t < 768) {
        int tt = t - 256;
        W = Wkv; Th = g_Wkvt; K = 512; N = 1024; perm = 0;
        n0 = (tt & 31) * 32; k0 = (tt >> 5) * 32;
    } else {
        int tt = t - 768;
        W = Wp; Th = g_Wpt; K = 512; N = 512; perm = 0;
        n0 = (tt & 15) * 32; k0 = (tt >> 4) * 32;
    }
    __shared__ float tbuf[32][33];
    int tx = tid & 31, ty = tid >> 5;
#pragma unroll
    for (int i = 0; i < 4; i++)
        tbuf[ty + 8 * i][tx] = W[(size_t)(k0 + ty + 8 * i) * N + n0 + tx];
    __syncthreads();
#pragma unroll
    for (int i = 0; i < 4; i++) {
        int n = n0 + ty + 8 * i;
        int np = perm ? ((n & 7) * 64 + (n >> 3)) : n;
        Th[(size_t)np * K + k0 + tx] = __float2half(tbuf[tx][ty + 8 * i]);
    }
}

// ---------------------------------------------------------------------------
// MMA attention. Block = (b*8+nh, qtile of 128). 256 threads / 8 warps.
// Combines KV split-K halves (__hadd2) during smem load.
// S = Q@K^T ; softmax via ex2.approx.f16x2 ; O = P@V.
// ---------------------------------------------------------------------------
#define AROWB 144
#define AQ  0
#define AKH 18432
#define AVH 27648
// 0.125 (1/sqrt(64)) * log2(e)
#define SM_SCALE 0.18033688f

__global__ __launch_bounds__(256) void attn_mma()
{
    __shared__ __align__(16) char asm_[36864];
    uint32_t sb = smem_u32(asm_);
    int tid = threadIdx.x, lane = tid & 31, wid = tid >> 5;
    int b = blockIdx.x >> 3, nh = blockIdx.x & 7;
    int n0 = blockIdx.y * 128;

    for (int idx = tid; idx < 1024; idx += 256) {
        int r = idx >> 3, s = idx & 7;
        *(uint4*)(asm_ + AQ + r * AROWB + s * 16) =
            *(const uint4*)(g_Qh + ((size_t)(b * 4096 + n0 + r)) * 512
                            + nh * 64 + s * 8);
    }
    for (int idx = tid; idx < 512; idx += 256) {
        int r = idx >> 3, s = idx & 7;
        size_t off = ((size_t)(b * 64 + r)) * 512 + nh * 64 + s * 8;
        uint32_t so = r * AROWB + s * 16;
        uint4 k0 = *(const uint4*)(g_Kp + off);
        uint4 k1 = *(const uint4*)(g_Kp + MROWS * C_ + off);
        uint4 v0 = *(const uint4*)(g_Vp + off);
        uint4 v1 = *(const uint4*)(g_Vp + MROWS * C_ + off);
        __half2* ka = (__half2*)&k0; __half2* kb = (__half2*)&k1;
        __half2* va = (__half2*)&v0; __half2* vb = (__half2*)&v1;
        uint4 kc, vc;
        __half2* kcp = (__half2*)&kc; __half2* vcp = (__half2*)&vc;
#pragma unroll
        for (int j = 0; j < 4; j++) {
            kcp[j] = __hadd2(ka[j], kb[j]);
            vcp[j] = __hadd2(va[j], vb[j]);
        }
        *(uint4*)(asm_ + AKH + so) = kc;
        *(uint4*)(asm_ + AVH + so) = vc;
    }
    __syncthreads();

    int mat = lane >> 3;
    int arow = ((mat & 1) << 3) + (lane & 7);
    int brow = ((mat >> 1) << 3) + (lane & 7);

    float sacc[8][4];
#pragma unroll
    for (int i = 0; i < 8; i++)
#pragma unroll
        for (int j = 0; j < 4; j++) sacc[i][j] = 0.f;

#pragma unroll
    for (int kk = 0; kk < 4; kk++) {
        int akcol = kk * 16 + ((mat >> 1) << 3);
        int bkcol = kk * 16 + ((mat & 1) << 3);
        uint32_t a[4];
        ldm_x4(a, sb + AQ + (uint32_t)(wid * 16 + arow) * AROWB + akcol * 2);
#pragma unroll
        for (int ng = 0; ng < 4; ng++) {
            uint32_t bh[4];
            ldm_x4(bh, sb + AKH + (uint32_t)(ng * 16 + brow) * AROWB + bkcol * 2);
            mma16816(sacc[2 * ng],     a, bh);
            mma16816(sacc[2 * ng + 1], a, bh + 2);
        }
    }

    // softmax: exp2 in fp16x2 (these ARE the P fragments); fp32 row sums.
    uint32_t ph[8][2];
    float sum0 = 0.f, sum1 = 0.f;
#pragma unroll
    for (int nt = 0; nt < 8; nt++) {
        __half2 h01 = __floats2half2_rn(sacc[nt][0] * SM_SCALE,
                                        sacc[nt][1] * SM_SCALE);
        __half2 h23 = __floats2half2_rn(sacc[nt][2] * SM_SCALE,
                                        sacc[nt][3] * SM_SCALE);
        h01 = h2exp2(h01);
        h23 = h2exp2(h23);
        ph[nt][0] = *(uint32_t*)&h01;
        ph[nt][1] = *(uint32_t*)&h23;
        float2 f0 = __half22float2(h01);
        float2 f1 = __half22float2(h23);
        sum0 += f0.x + f0.y;
        sum1 += f1.x + f1.y;
    }
    sum0 += __shfl_xor_sync(0xffffffffu, sum0, 1);
    sum0 += __shfl_xor_sync(0xffffffffu, sum0, 2);
    sum1 += __shfl_xor_sync(0xffffffffu, sum1, 1);
    sum1 += __shfl_xor_sync(0xffffffffu, sum1, 2);
    float inv0 = 1.f / sum0, inv1 = 1.f / sum1;

    float oacc[8][4];
#pragma unroll
    for (int i = 0; i < 8; i++)
#pragma unroll
        for (int j = 0; j < 4; j++) oacc[i][j] = 0.f;

#pragma unroll
    for (int kt = 0; kt < 4; kt++) {
        uint32_t ah[4] = { ph[2 * kt][0], ph[2 * kt][1],
                           ph[2 * kt + 1][0], ph[2 * kt + 1][1] };
        int vrow = kt * 16 + ((lane >> 3) & 1) * 8 + (lane & 7);
        int vcol = (lane >> 4) * 8;
#pragma unroll
        for (int ng = 0; ng < 4; ng++) {
            uint32_t bh[4];
            ldm_x4t(bh, sb + AVH + (uint32_t)vrow * AROWB
                         + (ng * 16 + vcol) * 2);
            mma16816(oacc[2 * ng],     ah, bh);
            mma16816(oacc[2 * ng + 1], ah, bh + 2);
        }
    }

    int r0 = n0 + wid * 16 + (lane >> 2);
#pragma unroll
    for (int nt = 0; nt < 8; nt++) {
        int col = nh * 64 + nt * 8 + (lane & 3) * 2;
        __half2 v0 = __halves2half2(__float2half(oacc[nt][0] * inv0),
                                    __float2half(oacc[nt][1] * inv0));
        __half2 v1 = __halves2half2(__float2half(oacc[nt][2] * inv1),
                                    __float2half(oacc[nt][3] * inv1));
        *(__half2*)(g_AOf + ((size_t)(b * 4096 + r0)) * 512 + col) = v0;
        *(__half2*)(g_AOf + ((size_t)(b * 4096 + r0 + 8)) * 512 + col) = v1;
    }
}

// ---------------------------------------------------------------------------
// Host launcher
// ---------------------------------------------------------------------------
extern "C" void kernel_launch(void* const* d_in, const int* in_sizes, int n_in,
                              void* d_out, int out_size)
{
    const float* x     = (const float*)d_in[0];
    const float* Wq    = (const float*)d_in[1];
    const float* Wkv   = (const float*)d_in[2];
    const float* convw = (const float*)d_in[3];
    const float* gamma = (const float*)d_in[4];
    const float* beta  = (const float*)d_in[5];
    const float* Wp    = (const float*)d_in[6];
    const float* bp    = (const float*)d_in[7];
    float* out = (float*)d_out;

    cudaFuncSetAttribute(mgemm_qc, cudaFuncAttributeMaxDynamicSharedMemorySize,
                         MG_SMEM);
    cudaFuncSetAttribute(lnkv_kernel, cudaFuncAttributeMaxDynamicSharedMemorySize,
                         MG_SMEM);
    cudaFuncSetAttribute(mgemm_g, cudaFuncAttributeMaxDynamicSharedMemorySize,
                         MG_SMEM);

    // fused conversions + transposes (one launch)
    prep_kernel<<<8192 + 1024, 256>>>(x, convw, Wq, Wkv, Wp);

    // Q-projection + conv GEMM fused (conv's long CTAs first)
    mgemm_qc<<<1280, 256, MG_SMEM>>>();
    // fused reduce+LN then KV split-K GEMM (device-wide ticket barrier)
    lnkv_kernel<<<256, 256, MG_SMEM>>>(gamma, beta);
    // attention (MMA, combines KV halves) -> AOf
    attn_mma<<<dim3(64, 32), 256>>>();
    // out = AO @ Wp + bp
    mgemm_g<<<dim3(4, 256), 256, MG_SMEM>>>(
        DSEL_EXT, 512, 16, 512, out, bp, 1);
}